// round 8
// baseline (speedup 1.0000x reference)
#include <cuda_runtime.h>
#include <cuda_bf16.h>
#include <cstdint>

#define Bb   256
#define Tt   64
#define OBSn 4096
#define Dd   1024
#define Aa   8
#define Hh   2048
#define ZLn  4
#define ZDn  256
#define BT   (Bb*Tt)          // 16384
#define EPSf 1e-5f
#define JEW_LD (Dd + Aa)      // 1032

typedef __nv_bfloat16 bf16;

// ---------------- scratch (static device globals; no allocation) -------------
__device__ float g_h1[BT * Hh];
__device__ float g_x [BT * Dd];
__device__ float g_gi[BT * 3 * Dd];
__device__ float g_h [Bb * Dd];
__device__ float g_z [Bb * ZLn * ZDn];
__device__ float g_d1[Bb * Hh];
__device__ float g_d2[Bb * OBSn];
__device__ float g_mean[4096];
__device__ float g_var [4096];
__device__ float g_wscan[4 * Dd * Dd];
__device__ float g_M2[3 * Dd * Aa];
__device__ float g_c [3 * Dd];

// int8 split buffers (value = s[row] * (q1*128 + q0))
__device__ int8_t q_obs1[BT * OBSn], q_obs0[BT * OBSn];
__device__ float  s_obs[BT];
__device__ int8_t q_w1a[Hh * OBSn], q_w1b[Hh * OBSn];
__device__ float  s_w1[Hh];
__device__ int8_t q_h1a[BT * Hh], q_h1b[BT * Hh];
__device__ float  s_h1[BT];
__device__ int8_t q_w2a[Dd * Hh], q_w2b[Dd * Hh];
__device__ float  s_w2[Dd];
__device__ int8_t q_xa[BT * Dd], q_xb[BT * Dd];
__device__ float  s_x[BT];
__device__ int8_t q_wiha[3 * Dd * Dd], q_wihb[3 * Dd * Dd];
__device__ float  s_wih[3 * Dd];

// bf16 hi/lo (scan + decoder)
__device__ bf16 g_wsh [4 * Dd * Dd], g_wsl [4 * Dd * Dd];  // PERMUTED rows 4d+comp
__device__ bf16 g_hh  [Bb * Dd],   g_hl  [Bb * Dd];
__device__ bf16 g_zh  [Bb * Dd],   g_zl  [Bb * Dd];
__device__ bf16 g_d1h [Bb * Hh],   g_d1l [Bb * Hh];
__device__ bf16 g_dw1h[Hh * Dd],   g_dw1l[Hh * Dd];
__device__ bf16 g_dw2h[OBSn * Hh], g_dw2l[OBSn * Hh];

// ======================= PTX helpers =========================================
__device__ __forceinline__ uint32_t smem_u32(const void* p) {
    uint32_t a;
    asm("{ .reg .u64 t; cvta.to.shared.u64 t, %1; cvt.u32.u64 %0, t; }"
        : "=r"(a) : "l"(p));
    return a;
}
__device__ __forceinline__ void cp16(uint32_t s, const void* g) {
    asm volatile("cp.async.cg.shared.global [%0], [%1], 16;" :: "r"(s), "l"(g));
}
__device__ __forceinline__ void cp_commit() {
    asm volatile("cp.async.commit_group;" ::: "memory");
}
__device__ __forceinline__ void cp_wait0() {
    asm volatile("cp.async.wait_group 0;" ::: "memory");
}
__device__ __forceinline__ void cp_wait1() {
    asm volatile("cp.async.wait_group 1;" ::: "memory");
}
__device__ __forceinline__ void cp_wait2() {
    asm volatile("cp.async.wait_group 2;" ::: "memory");
}
__device__ __forceinline__ void ldm_x4(uint32_t* r, uint32_t a) {
    asm volatile("ldmatrix.sync.aligned.m8n8.x4.shared.b16 {%0,%1,%2,%3}, [%4];"
                 : "=r"(r[0]), "=r"(r[1]), "=r"(r[2]), "=r"(r[3]) : "r"(a));
}
__device__ __forceinline__ void ldm_x2(uint32_t* r, uint32_t a) {
    asm volatile("ldmatrix.sync.aligned.m8n8.x2.shared.b16 {%0,%1}, [%2];"
                 : "=r"(r[0]), "=r"(r[1]) : "r"(a));
}
__device__ __forceinline__ void mma_bf16(float* c, const uint32_t* a, const uint32_t* b) {
    asm volatile("mma.sync.aligned.m16n8k16.row.col.f32.bf16.bf16.f32 "
                 "{%0,%1,%2,%3}, {%4,%5,%6,%7}, {%8,%9}, {%0,%1,%2,%3};"
                 : "+f"(c[0]), "+f"(c[1]), "+f"(c[2]), "+f"(c[3])
                 : "r"(a[0]), "r"(a[1]), "r"(a[2]), "r"(a[3]),
                   "r"(b[0]), "r"(b[1]));
}
__device__ __forceinline__ void mma_s8(int* c, const uint32_t* a, const uint32_t* b) {
    asm volatile("mma.sync.aligned.m16n8k32.row.col.s32.s8.s8.s32 "
                 "{%0,%1,%2,%3}, {%4,%5,%6,%7}, {%8,%9}, {%0,%1,%2,%3};"
                 : "+r"(c[0]), "+r"(c[1]), "+r"(c[2]), "+r"(c[3])
                 : "r"(a[0]), "r"(a[1]), "r"(a[2]), "r"(a[3]),
                   "r"(b[0]), "r"(b[1]));
}

// =================== int8 split GEMM: C = A @ B^T (+bias) ====================
// Aq1/Aq0: MxK int8 (ld=K) + sa[M]; Bq1/Bq0: NxK int8 + sb[N]; C: MxN fp32.
// M%128==0, N%128==0, K%32==0 (>=96). Grid (N/128, M/128), 256 threads.
#define QLD   48                       // 32 data bytes + 16 pad per row
#define QTILE (128 * QLD)
#define QSTAGE (4 * QTILE)             // Aq1, Aq0, Bq1, Bq0 = 24576 B
#define QSM_BYTES (3 * QSTAGE)         // 73728

__global__ void __launch_bounds__(256)
imma_gemm(const int8_t* __restrict__ Aq1, const int8_t* __restrict__ Aq0,
          const float* __restrict__ sa,
          const int8_t* __restrict__ Bq1, const int8_t* __restrict__ Bq0,
          const float* __restrict__ sb,
          const float* __restrict__ bias, float* __restrict__ C,
          int M, int N, int K)
{
    extern __shared__ char qsm[];

    const int tid = threadIdx.x;
    const int wid = tid >> 5, lane = tid & 31;
    const int wm = wid >> 2, wn = wid & 3;
    const int rowBase = blockIdx.y * 128, colBase = blockIdx.x * 128;
    const int NC = K >> 5;

    int acc1[4][4][4], acc2[4][4][4];
#pragma unroll
    for (int i = 0; i < 4; i++)
#pragma unroll
        for (int j = 0; j < 4; j++)
#pragma unroll
            for (int k = 0; k < 4; k++) { acc1[i][j][k] = 0; acc2[i][j][k] = 0; }

    const int8_t* srcs[4] = { Aq1, Aq0, Bq1, Bq0 };
    const int   rbs [4] = { rowBase, rowBase, colBase, colBase };

    auto load = [&](int c, int st) {
        const int koff = c << 5;
        char* stp = qsm + st * QSTAGE;
        const int row = tid >> 1;
        const int seg = (tid & 1) << 4;
#pragma unroll
        for (int tI = 0; tI < 4; tI++) {
            cp16(smem_u32(stp + tI * QTILE + row * QLD + seg),
                 srcs[tI] + (size_t)(rbs[tI] + row) * K + koff + seg);
        }
        cp_commit();
    };

    load(0, 0);
    load(1, 1);
    for (int c = 0; c < NC; c++) {
        const int st = c % 3;
        if (c + 2 < NC) { load(c + 2, (c + 2) % 3); cp_wait2(); }
        else if (c + 1 < NC) cp_wait1();
        else cp_wait0();
        __syncthreads();

        const char* stp = qsm + st * QSTAGE;
        uint32_t a1f[4][4], a0f[4][4];
        uint32_t b1f[4][2], b0f[4][2];
#pragma unroll
        for (int mt = 0; mt < 4; mt++) {
            int r = wm * 64 + mt * 16 + (lane & 15);
            int off = r * QLD + ((lane >> 4) << 4);
            ldm_x4(a1f[mt], smem_u32(stp + 0 * QTILE + off));
            ldm_x4(a0f[mt], smem_u32(stp + 1 * QTILE + off));
        }
#pragma unroll
        for (int nt = 0; nt < 4; nt++) {
            int r = wn * 32 + nt * 8 + (lane & 7);
            int off = r * QLD + (((lane >> 3) & 1) << 4);
            ldm_x2(b1f[nt], smem_u32(stp + 2 * QTILE + off));
            ldm_x2(b0f[nt], smem_u32(stp + 3 * QTILE + off));
        }
#pragma unroll
        for (int mt = 0; mt < 4; mt++)
#pragma unroll
            for (int nt = 0; nt < 4; nt++) {
                mma_s8(acc1[mt][nt], a1f[mt], b1f[nt]);   // q1*q1
                mma_s8(acc2[mt][nt], a1f[mt], b0f[nt]);   // q1*q0
                mma_s8(acc2[mt][nt], a0f[mt], b1f[nt]);   // q0*q1
            }
        __syncthreads();
    }

    // epilogue: out = sa*sb*(acc1*16384 + acc2*128) + bias
#pragma unroll
    for (int mt = 0; mt < 4; mt++) {
        const int row = rowBase + wm * 64 + mt * 16 + (lane >> 2);
        const float sa0 = sa[row], sa1 = sa[row + 8];
#pragma unroll
        for (int nt = 0; nt < 4; nt++) {
            const int col = colBase + wn * 32 + nt * 8 + (lane & 3) * 2;
            const float sb0 = sb[col], sb1 = sb[col + 1];
            float bi0 = bias ? bias[col] : 0.f;
            float bi1 = bias ? bias[col + 1] : 0.f;
            float v00 = sa0 * sb0 * fmaf((float)acc1[mt][nt][0], 16384.f,
                                         (float)acc2[mt][nt][0] * 128.f) + bi0;
            float v01 = sa0 * sb1 * fmaf((float)acc1[mt][nt][1], 16384.f,
                                         (float)acc2[mt][nt][1] * 128.f) + bi1;
            float v10 = sa1 * sb0 * fmaf((float)acc1[mt][nt][2], 16384.f,
                                         (float)acc2[mt][nt][2] * 128.f) + bi0;
            float v11 = sa1 * sb1 * fmaf((float)acc1[mt][nt][3], 16384.f,
                                         (float)acc2[mt][nt][3] * 128.f) + bi1;
            *(float2*)(C + (size_t)row * N + col) = make_float2(v00, v01);
            *(float2*)(C + (size_t)(row + 8) * N + col) = make_float2(v10, v11);
        }
    }
}

// ============== row quantization: X[M,K] fp32 -> (q1,q0) int8 + s[M] =========
// One CTA (256 thr) per row. K in {1024, 2048, 4096} (K/1024 float4/thread).
__global__ void __launch_bounds__(256)
quant_rows(const float* __restrict__ X, int8_t* __restrict__ q1,
           int8_t* __restrict__ q0, float* __restrict__ s, int K)
{
    const int row = blockIdx.x, tid = threadIdx.x;
    const float4* X4 = (const float4*)(X + (size_t)row * K);
    const int nf4 = K >> 10;

    float buf[16];
    float mx = 0.f;
#pragma unroll
    for (int i = 0; i < 4; i++) {
        if (i < nf4) {
            float4 v = X4[i * 256 + tid];
            buf[i*4+0]=v.x; buf[i*4+1]=v.y; buf[i*4+2]=v.z; buf[i*4+3]=v.w;
            mx = fmaxf(mx, fmaxf(fmaxf(fabsf(v.x), fabsf(v.y)),
                                 fmaxf(fabsf(v.z), fabsf(v.w))));
        }
    }
#pragma unroll
    for (int o = 16; o; o >>= 1)
        mx = fmaxf(mx, __shfl_xor_sync(0xffffffffu, mx, o));
    __shared__ float wmax[8];
    if ((tid & 31) == 0) wmax[tid >> 5] = mx;
    __syncthreads();
    float m = wmax[0];
#pragma unroll
    for (int j = 1; j < 8; j++) m = fmaxf(m, wmax[j]);
    const float sr = fmaxf(m, 1e-30f) * (1.f / 16256.f);
    if (tid == 0) s[row] = sr;
    const float inv = 1.f / sr;

    char4* Q1 = (char4*)(q1 + (size_t)row * K);
    char4* Q0 = (char4*)(q0 + (size_t)row * K);
#pragma unroll
    for (int i = 0; i < 4; i++) {
        if (i < nf4) {
            char c1[4], c0[4];
#pragma unroll
            for (int j = 0; j < 4; j++) {
                float v = buf[i*4+j] * inv;
                float hi = rintf(v * (1.f / 128.f));
                hi = fminf(fmaxf(hi, -127.f), 127.f);
                float lo = rintf(v - 128.f * hi);
                c1[j] = (char)(int)hi;
                c0[j] = (char)(int)lo;
            }
            Q1[i * 256 + tid] = make_char4(c1[0], c1[1], c1[2], c1[3]);
            Q0[i * 256 + tid] = make_char4(c0[0], c0[1], c0[2], c0[3]);
        }
    }
}

// =================== HMMA hi/lo GEMM (decoder), 3-stage ======================
#define LD2   40
#define TILE2 (128 * LD2)
#define STAGE2 (4 * TILE2)
#define SM3_BYTES (3 * STAGE2 * 2)     // 122880

__global__ void __launch_bounds__(256)
mma_gemm(const bf16* __restrict__ Ah, const bf16* __restrict__ Al,
         const bf16* __restrict__ Bh, const bf16* __restrict__ Bl,
         const float* __restrict__ bias, float* __restrict__ C,
         int M, int N, int K)
{
    extern __shared__ bf16 sm2[];

    const int tid = threadIdx.x;
    const int wid = tid >> 5, lane = tid & 31;
    const int wm = wid >> 2, wn = wid & 3;
    const int rowBase = blockIdx.y * 128, colBase = blockIdx.x * 128;
    const int NC = K >> 5;

    float acc[4][4][4];
#pragma unroll
    for (int i = 0; i < 4; i++)
#pragma unroll
        for (int j = 0; j < 4; j++)
#pragma unroll
            for (int k = 0; k < 4; k++) acc[i][j][k] = 0.f;

    const bf16* srcs[4] = { Ah, Al, Bh, Bl };
    const int   rbs [4] = { rowBase, rowBase, colBase, colBase };

    auto load = [&](int c, int st) {
        const int koff = c << 5;
        bf16* stp = sm2 + st * STAGE2;
#pragma unroll
        for (int tI = 0; tI < 4; tI++) {
#pragma unroll
            for (int i = 0; i < 2; i++) {
                int u = tid * 2 + i;
                int row = u >> 2;
                int seg = (u & 3) << 3;
                cp16(smem_u32(stp + tI * TILE2 + row * LD2 + seg),
                     srcs[tI] + (size_t)(rbs[tI] + row) * K + koff + seg);
            }
        }
        cp_commit();
    };

    load(0, 0);
    load(1, 1);
    for (int c = 0; c < NC; c++) {
        const int st = c % 3;
        if (c + 2 < NC) { load(c + 2, (c + 2) % 3); cp_wait2(); }
        else if (c + 1 < NC) cp_wait1();
        else cp_wait0();
        __syncthreads();

        const bf16* stp = sm2 + st * STAGE2;
#pragma unroll
        for (int kh = 0; kh < 2; kh++) {
            const int kcol = kh << 4;
            uint32_t a[2][4][4];
            uint32_t b[2][4][2];
#pragma unroll
            for (int t = 0; t < 2; t++) {
                const bf16* base = stp + t * TILE2;
#pragma unroll
                for (int mt = 0; mt < 4; mt++) {
                    int r = wm * 64 + mt * 16 + (lane & 15);
                    int cc = kcol + ((lane >> 4) << 3);
                    ldm_x4(a[t][mt], smem_u32(base + r * LD2 + cc));
                }
            }
#pragma unroll
            for (int t = 0; t < 2; t++) {
                const bf16* base = stp + (2 + t) * TILE2;
#pragma unroll
                for (int nt = 0; nt < 4; nt++) {
                    int r = wn * 32 + nt * 8 + (lane & 7);
                    int cc = kcol + (((lane >> 3) & 1) << 3);
                    ldm_x2(b[t][nt], smem_u32(base + r * LD2 + cc));
                }
            }
#pragma unroll
            for (int mt = 0; mt < 4; mt++)
#pragma unroll
                for (int nt = 0; nt < 4; nt++) {
                    mma_bf16(acc[mt][nt], a[0][mt], b[0][nt]);
                    mma_bf16(acc[mt][nt], a[0][mt], b[1][nt]);
                    mma_bf16(acc[mt][nt], a[1][mt], b[0][nt]);
                }
        }
        __syncthreads();
    }

#pragma unroll
    for (int mt = 0; mt < 4; mt++) {
        const int row = rowBase + wm * 64 + mt * 16 + (lane >> 2);
#pragma unroll
        for (int nt = 0; nt < 4; nt++) {
            const int col = colBase + wn * 32 + nt * 8 + (lane & 3) * 2;
            float b0 = bias ? bias[col] : 0.f;
            float b1 = bias ? bias[col + 1] : 0.f;
            *(float2*)(C + (size_t)row * N + col) =
                make_float2(acc[mt][nt][0] + b0, acc[mt][nt][1] + b1);
            *(float2*)(C + (size_t)(row + 8) * N + col) =
                make_float2(acc[mt][nt][2] + b0, acc[mt][nt][3] + b1);
        }
    }
}

// =================== fused scan step: GEMM + GRU gate =========================
#define SLD    40
#define SATILE (128 * SLD)
#define SBTILE (64 * SLD)
#define SSTAGE (2 * SATILE + 2 * SBTILE)
#define SSM_BYTES (2 * SSTAGE * 2)     // 61440
#define SLDF   68

__device__ __forceinline__ float sigmoidf_(float x) { return 1.f / (1.f + expf(-x)); }

__global__ void __launch_bounds__(256)
mma_scan(const float* __restrict__ actions,
         const float* __restrict__ je_w,
         const float* __restrict__ je_b, int t)
{
    extern __shared__ bf16 ssm[];

    const int tid = threadIdx.x;
    const int wid = tid >> 5, lane = tid & 31;
    const int wm = wid >> 2, wn = wid & 3;
    const int rowBase = blockIdx.y * 128;
    const int colBase = blockIdx.x * 64;
    const int NC = Dd >> 5;   // 32

    float acc[4][2][4];
#pragma unroll
    for (int i = 0; i < 4; i++)
#pragma unroll
        for (int j = 0; j < 2; j++)
#pragma unroll
            for (int k = 0; k < 4; k++) acc[i][j][k] = 0.f;

    auto load = [&](int c, int st) {
        const int koff = c << 5;
        bf16* stp = ssm + st * SSTAGE;
#pragma unroll
        for (int tI = 0; tI < 2; tI++) {
            const bf16* src = tI ? g_hl : g_hh;
#pragma unroll
            for (int i = 0; i < 2; i++) {
                int u = tid * 2 + i;
                int row = u >> 2;
                int seg = (u & 3) << 3;
                cp16(smem_u32(stp + tI * SATILE + row * SLD + seg),
                     src + (size_t)(rowBase + row) * Dd + koff + seg);
            }
        }
#pragma unroll
        for (int tI = 0; tI < 2; tI++) {
            const bf16* src = tI ? g_wsl : g_wsh;
            int row = tid >> 2;
            int seg = (tid & 3) << 3;
            cp16(smem_u32(stp + 2 * SATILE + tI * SBTILE + row * SLD + seg),
                 src + (size_t)(colBase + row) * Dd + koff + seg);
        }
        cp_commit();
    };

    load(0, 0);
    int st = 0;
    for (int c = 0; c < NC; c++) {
        const bool more = (c + 1) < NC;
        if (more) { load(c + 1, st ^ 1); cp_wait1(); }
        else      { cp_wait0(); }
        __syncthreads();

        const bf16* stp = ssm + st * SSTAGE;
#pragma unroll
        for (int kh = 0; kh < 2; kh++) {
            const int kcol = kh << 4;
            uint32_t a[2][4][4];
            uint32_t b[2][2][2];
#pragma unroll
            for (int tI = 0; tI < 2; tI++) {
                const bf16* base = stp + tI * SATILE;
#pragma unroll
                for (int mt = 0; mt < 4; mt++) {
                    int r = wm * 64 + mt * 16 + (lane & 15);
                    int cc = kcol + ((lane >> 4) << 3);
                    ldm_x4(a[tI][mt], smem_u32(base + r * SLD + cc));
                }
            }
#pragma unroll
            for (int tI = 0; tI < 2; tI++) {
                const bf16* base = stp + 2 * SATILE + tI * SBTILE;
#pragma unroll
                for (int nt = 0; nt < 2; nt++) {
                    int r = wn * 16 + nt * 8 + (lane & 7);
                    int cc = kcol + (((lane >> 3) & 1) << 3);
                    ldm_x2(b[tI][nt], smem_u32(base + r * SLD + cc));
                }
            }
#pragma unroll
            for (int mt = 0; mt < 4; mt++)
#pragma unroll
                for (int nt = 0; nt < 2; nt++) {
                    mma_bf16(acc[mt][nt], a[0][mt], b[0][nt]);
                    mma_bf16(acc[mt][nt], a[0][mt], b[1][nt]);
                    mma_bf16(acc[mt][nt], a[1][mt], b[0][nt]);
                }
        }
        __syncthreads();
        st ^= 1;
    }

    float* smf = (float*)ssm;
#pragma unroll
    for (int mt = 0; mt < 4; mt++) {
        const int row = wm * 64 + mt * 16 + (lane >> 2);
#pragma unroll
        for (int nt = 0; nt < 2; nt++) {
            const int col = wn * 16 + nt * 8 + (lane & 3) * 2;
            smf[row * SLDF + col]     = acc[mt][nt][0];
            smf[row * SLDF + col + 1] = acc[mt][nt][1];
            smf[(row + 8) * SLDF + col]     = acc[mt][nt][2];
            smf[(row + 8) * SLDF + col + 1] = acc[mt][nt][3];
        }
    }
    __syncthreads();

    const int dl = tid & 15;
    const int rg = tid >> 4;
    const int dg = (colBase >> 2) + dl;

    const float c0 = g_c[dg], c1 = g_c[Dd + dg], c2 = g_c[2 * Dd + dg];
    const float jb = je_b[dg];
    float m2r[8], m2z[8], m2n[8], jea[8];
#pragma unroll
    for (int j = 0; j < 8; j++) {
        m2r[j] = g_M2[(size_t)dg * 8 + j];
        m2z[j] = g_M2[(size_t)(Dd + dg) * 8 + j];
        m2n[j] = g_M2[(size_t)(2 * Dd + dg) * 8 + j];
        jea[j] = je_w[(size_t)dg * JEW_LD + Dd + j];
    }

#pragma unroll
    for (int r8 = 0; r8 < 8; r8++) {
        const int row = rg * 8 + r8;
        const int b = rowBase + row;
        const int trow = b * Tt + t;

        float4 G4 = *(float4*)&smf[row * SLDF + 4 * dl];
        float hr = G4.x + c0;
        float hz = G4.y + c1;
        float hn = G4.z + c2;
        float hj = G4.w + jb;

        const float* a = actions + (size_t)trow * Aa;
#pragma unroll
        for (int j = 0; j < 8; j++) {
            float av = a[j];
            hr = fmaf(av, m2r[j], hr);
            hz = fmaf(av, m2z[j], hz);
            hn = fmaf(av, m2n[j], hn);
            hj = fmaf(av, jea[j], hj);
        }

        const float* gi = g_gi + (size_t)trow * (3 * Dd);
        float r = sigmoidf_(gi[dg] + hr);
        float z = sigmoidf_(gi[Dd + dg] + hz);
        float n = tanhf(gi[2 * Dd + dg] + r * hn);
        float xv = g_x[(size_t)trow * Dd + dg];
        float hnew = (1.f - z) * n + z * hj + xv;

        const int oi = b * Dd + dg;
        g_h[oi] = hnew;
        bf16 hh = __float2bfloat16(hnew);
        g_hh[oi] = hh;
        g_hl[oi] = __float2bfloat16(hnew - __bfloat162float(hh));
    }
}

// =============== hi/lo conversion (decoder weights) ==========================
__global__ void cvt_hl(const float* __restrict__ X, bf16* __restrict__ Xh,
                       bf16* __restrict__ Xl, int n4)
{
    int i = blockIdx.x * blockDim.x + threadIdx.x;
    if (i >= n4) return;
    float4 v = ((const float4*)X)[i];
    bf16 h0 = __float2bfloat16(v.x), h1 = __float2bfloat16(v.y);
    bf16 h2 = __float2bfloat16(v.z), h3 = __float2bfloat16(v.w);
    float l0 = v.x - __bfloat162float(h0), l1 = v.y - __bfloat162float(h1);
    float l2 = v.z - __bfloat162float(h2), l3 = v.w - __bfloat162float(h3);
    __nv_bfloat162* H = (__nv_bfloat162*)Xh;
    __nv_bfloat162* L = (__nv_bfloat162*)Xl;
    H[2 * i]     = __nv_bfloat162(h0, h1);
    H[2 * i + 1] = __nv_bfloat162(h2, h3);
    L[2 * i]     = __nv_bfloat162(__float2bfloat16(l0), __float2bfloat16(l1));
    L[2 * i + 1] = __nv_bfloat162(__float2bfloat16(l2), __float2bfloat16(l3));
}

// permuted cvt of W_scan: new row 4d+comp <- old row comp*1024+d / 3072+d
__global__ void cvt_hl_perm_ws()
{
    int i = blockIdx.x * blockDim.x + threadIdx.x;
    if (i >= 4 * Dd * Dd / 4) return;
    int flat = i * 4;
    int nrow = flat >> 10;
    int k = flat & 1023;
    int d = nrow >> 2, comp = nrow & 3;
    int orow = (comp < 3) ? comp * Dd + d : 3 * Dd + d;
    float4 v = *(const float4*)&g_wscan[(size_t)orow * Dd + k];
    bf16 h0 = __float2bfloat16(v.x), h1 = __float2bfloat16(v.y);
    bf16 h2 = __float2bfloat16(v.z), h3 = __float2bfloat16(v.w);
    __nv_bfloat162* H = (__nv_bfloat162*)g_wsh;
    __nv_bfloat162* L = (__nv_bfloat162*)g_wsl;
    H[2*i]   = __nv_bfloat162(h0, h1);
    H[2*i+1] = __nv_bfloat162(h2, h3);
    L[2*i]   = __nv_bfloat162(__float2bfloat16(v.x - __bfloat162float(h0)),
                              __float2bfloat16(v.y - __bfloat162float(h1)));
    L[2*i+1] = __nv_bfloat162(__float2bfloat16(v.z - __bfloat162float(h2)),
                              __float2bfloat16(v.w - __bfloat162float(h3)));
}

// =============== SIMT GEMM (precompute only) ==================================
#define BKd 8
__global__ void __launch_bounds__(256)
sgemm_ab(const float* __restrict__ A, const float* __restrict__ Bm,
         float* __restrict__ C, int M, int N, int K, int lda, int ldb, int ldc)
{
    __shared__ float As[BKd][128];
    __shared__ float Bs[BKd][128];
    const int tid = threadIdx.x;
    const int tx = tid & 15, ty = tid >> 4;
    const int rowBase = blockIdx.y * 128, colBase = blockIdx.x * 128;
    const int lrA = tid >> 1, lcA = (tid & 1) * 4;
    const int kkB = tid >> 5, c4B = (tid & 31) * 4;
    const float* Aptr = A + (size_t)(rowBase + lrA) * lda + lcA;
    const float* Bptr = Bm + (size_t)kkB * ldb + colBase + c4B;
    float acc[8][8];
#pragma unroll
    for (int i = 0; i < 8; i++)
#pragma unroll
        for (int j = 0; j < 8; j++) acc[i][j] = 0.f;
    for (int k0 = 0; k0 < K; k0 += BKd) {
        float4 av = *(const float4*)(Aptr + k0);
        float4 bv = *(const float4*)(Bptr + (size_t)k0 * ldb);
        As[lcA+0][lrA]=av.x; As[lcA+1][lrA]=av.y;
        As[lcA+2][lrA]=av.z; As[lcA+3][lrA]=av.w;
        *(float4*)&Bs[kkB][c4B] = bv;
        __syncthreads();
#pragma unroll
        for (int kk = 0; kk < BKd; kk++) {
            float a[8], b[8];
#pragma unroll
            for (int i = 0; i < 8; i++) a[i] = As[kk][ty*8+i];
#pragma unroll
            for (int j = 0; j < 8; j++) b[j] = Bs[kk][tx*8+j];
#pragma unroll
            for (int i = 0; i < 8; i++)
#pragma unroll
                for (int j = 0; j < 8; j++)
                    acc[i][j] = fmaf(a[i], b[j], acc[i][j]);
        }
        __syncthreads();
    }
#pragma unroll
    for (int i = 0; i < 8; i++) {
        const int r = rowBase + ty * 8 + i;
#pragma unroll
        for (int j = 0; j < 8; j++)
            C[(size_t)r * ldc + colBase + tx * 8 + j] = acc[i][j];
    }
}

__global__ void copy_jew(const float* __restrict__ je_w)
{
    int idx = blockIdx.x * blockDim.x + threadIdx.x;
    if (idx >= Dd * Dd) return;
    int j = idx >> 10, k = idx & 1023;
    g_wscan[(size_t)(3 * Dd + j) * Dd + k] = je_w[(size_t)j * JEW_LD + k];
}

__global__ void __launch_bounds__(128)
m2c_k(const float* __restrict__ whh, const float* __restrict__ je_w,
      const float* __restrict__ je_b, const float* __restrict__ bhh)
{
    const int i = blockIdx.x;
    const int t = threadIdx.x;
    float acc[9];
#pragma unroll
    for (int j = 0; j < 9; j++) acc[j] = 0.f;
    for (int k = t; k < Dd; k += 128) {
        float w = whh[(size_t)i * Dd + k];
        const float* jr = je_w + (size_t)k * JEW_LD + Dd;
#pragma unroll
        for (int j = 0; j < 8; j++) acc[j] = fmaf(w, jr[j], acc[j]);
        acc[8] = fmaf(w, je_b[k], acc[8]);
    }
    __shared__ float sh[9][128];
#pragma unroll
    for (int j = 0; j < 9; j++) sh[j][t] = acc[j];
    __syncthreads();
    for (int s = 64; s > 0; s >>= 1) {
        if (t < s)
#pragma unroll
            for (int j = 0; j < 9; j++) sh[j][t] += sh[j][t + s];
        __syncthreads();
    }
    if (t == 0) {
#pragma unroll
        for (int j = 0; j < 8; j++) g_M2[i * 8 + j] = sh[j][0];
        g_c[i] = sh[8][0] + bhh[i];
    }
}

// ---------------- batch stats + BN ------------------------------------------
__global__ void col_stats(const float* __restrict__ X, int M, int N,
                          float* __restrict__ mean, float* __restrict__ var)
{
    const int c = blockIdx.x * 32 + threadIdx.x;
    const int ry = threadIdx.y;
    float s = 0.f, s2 = 0.f;
    for (int r = ry; r < M; r += 8) {
        float v = X[(size_t)r * N + c];
        s += v; s2 += v * v;
    }
    __shared__ float sh[8][32], sh2[8][32];
    sh[ry][threadIdx.x] = s; sh2[ry][threadIdx.x] = s2;
    __syncthreads();
    if (ry == 0) {
#pragma unroll
        for (int y = 1; y < 8; y++) { s += sh[y][threadIdx.x]; s2 += sh2[y][threadIdx.x]; }
        float m = s / (float)M;
        mean[c] = m;
        var[c]  = s2 / (float)M - m * m;
    }
}

__global__ void bn_apply(const float* __restrict__ X, float* __restrict__ Y,
                         const float* __restrict__ mean, const float* __restrict__ var,
                         const float* __restrict__ g, const float* __restrict__ beta,
                         int total, int N, int relu)
{
    int idx = blockIdx.x * blockDim.x + threadIdx.x;
    if (idx >= total) return;
    int c = idx % N;
    float v = g[c] * (X[idx] - mean[c]) * rsqrtf(var[c] + EPSf) + beta[c];
    if (relu) v = fmaxf(v, 0.f);
    Y[idx] = v;
}

__global__ void bn_apply_cvt(const float* __restrict__ X, float* __restrict__ Yf,
                             bf16* __restrict__ Yh, bf16* __restrict__ Yl,
                             const float* __restrict__ mean, const float* __restrict__ var,
                             const float* __restrict__ g, const float* __restrict__ beta,
                             int total4, int N, int relu)
{
    int i = blockIdx.x * blockDim.x + threadIdx.x;
    if (i >= total4) return;
    int c0 = (i * 4) % N;
    float4 v = ((const float4*)X)[i];
    float o[4] = { v.x, v.y, v.z, v.w };
#pragma unroll
    for (int j = 0; j < 4; j++) {
        int c = c0 + j;
        float t = g[c] * (o[j] - mean[c]) * rsqrtf(var[c] + EPSf) + beta[c];
        if (relu) t = fmaxf(t, 0.f);
        o[j] = t;
    }
    if (Yf) ((float4*)Yf)[i] = make_float4(o[0], o[1], o[2], o[3]);
    bf16 h0 = __float2bfloat16(o[0]), h1 = __float2bfloat16(o[1]);
    bf16 h2 = __float2bfloat16(o[2]), h3 = __float2bfloat16(o[3]);
    __nv_bfloat162* H = (__nv_bfloat162*)Yh;
    __nv_bfloat162* L = (__nv_bfloat162*)Yl;
    H[2*i]   = __nv_bfloat162(h0, h1);
    H[2*i+1] = __nv_bfloat162(h2, h3);
    L[2*i]   = __nv_bfloat162(__float2bfloat16(o[0] - __bfloat162float(h0)),
                              __float2bfloat16(o[1] - __bfloat162float(h1)));
    L[2*i+1] = __nv_bfloat162(__float2bfloat16(o[2] - __bfloat162float(h2)),
                              __float2bfloat16(o[3] - __bfloat162float(h3)));
}

// ---------------- misc ------------------------------------------------------
__global__ void zero_h() {
    int idx = blockIdx.x * blockDim.x + threadIdx.x;
    if (idx < Bb * Dd) {
        g_h[idx] = 0.f;
        g_hh[idx] = __float2bfloat16(0.f);
        g_hl[idx] = __float2bfloat16(0.f);
    }
}

// ---------------- threefry2x32-20 (JAX partitionable) ------------------------
__device__ __forceinline__ uint32_t rotl32_(uint32_t x, int r) {
    return (x << r) | (x >> (32 - r));
}
__device__ __forceinline__ void threefry2x32_(uint32_t k0, uint32_t k1,
                                              uint32_t& x0, uint32_t& x1)
{
    const uint32_t k2 = k0 ^ k1 ^ 0x1BD11BDAu;
    x0 += k0; x1 += k1;
#define TF_R4(a,b,c,d) \
    x0 += x1; x1 = rotl32_(x1, a); x1 ^= x0; \
    x0 += x1; x1 = rotl32_(x1, b); x1 ^= x0; \
    x0 += x1; x1 = rotl32_(x1, c); x1 ^= x0; \
    x0 += x1; x1 = rotl32_(x1, d); x1 ^= x0;
    TF_R4(13,15,26,6)  x0 += k1; x1 += k2 + 1u;
    TF_R4(17,29,16,24) x0 += k2; x1 += k0 + 2u;
    TF_R4(13,15,26,6)  x0 += k0; x1 += k1 + 3u;
    TF_R4(17,29,16,24) x0 += k1; x1 += k2 + 4u;
    TF_R4(13,15,26,6)  x0 += k2; x1 += k0 + 5u;
#undef TF_R4
}

__global__ void gumbel_softmax_k(float* __restrict__ out)
{
    const int bl = blockIdx.x;
    const int d  = threadIdx.x;
    const int i  = bl * ZDn + d;
    const float logit = g_h[i];

    uint32_t c0 = 0u;
    uint32_t c1 = (uint32_t)i;
    threefry2x32_(0u, 42u, c0, c1);
    const uint32_t bits = c0 ^ c1;
    float f = __uint_as_float((bits >> 9) | 0x3f800000u) - 1.0f;
    const float tiny = 1.1754943508222875e-38f;
    float u = fmaxf(f * (1.0f - tiny) + tiny, tiny);
    float gum = -logf(-logf(u));

    float v = logit + gum;

    __shared__ float red[ZDn];
    red[d] = v; __syncthreads();
    for (int s = ZDn / 2; s > 0; s >>= 1) {
        if (d < s) red[d] = fmaxf(red[d], red[d + s]);
        __syncthreads();
    }
    float mx = red[0];
    __syncthreads();
    float e = expf(v - mx);
    red[d] = e; __syncthreads();
    for (int s = ZDn / 2; s > 0; s >>= 1) {
        if (d < s) red[d] += red[d + s];
        __syncthreads();
    }
    float z = e / red[0];

    out[i] = logit;
    out[Bb * ZLn * ZDn + i] = z;
    g_z[i] = z;
    bf16 zh = __float2bfloat16(z);
    g_zh[i] = zh;
    g_zl[i] = __float2bfloat16(z - __bfloat162float(zh));
}

// ---------------- launch ------------------------------------------------------
static inline float* symf(const void* s) {
    void* p = nullptr;
    cudaGetSymbolAddress(&p, s);
    return (float*)p;
}
static inline bf16* symb(const void* s) {
    void* p = nullptr;
    cudaGetSymbolAddress(&p, s);
    return (bf16*)p;
}
static inline int8_t* symq(const void* s) {
    void* p = nullptr;
    cudaGetSymbolAddress(&p, s);
    return (int8_t*)p;
}

extern "C" void kernel_launch(void* const* d_in, const int* in_sizes, int n_in,
                              void* d_out, int out_size)
{
    (void)in_sizes; (void)n_in; (void)out_size;
    const float* obs      = (const float*)d_in[0];
    const float* actions  = (const float*)d_in[1];
    const float* enc_w1   = (const float*)d_in[2];
    const float* enc_b1   = (const float*)d_in[3];
    const float* enc_g1   = (const float*)d_in[4];
    const float* enc_bt1  = (const float*)d_in[5];
    const float* enc_w2   = (const float*)d_in[6];
    const float* enc_b2   = (const float*)d_in[7];
    const float* enc_g2   = (const float*)d_in[8];
    const float* enc_bt2  = (const float*)d_in[9];
    const float* je_w     = (const float*)d_in[10];
    const float* je_b     = (const float*)d_in[11];
    const float* gru_wih  = (const float*)d_in[12];
    const float* gru_bih  = (const float*)d_in[13];
    const float* gru_whh  = (const float*)d_in[14];
    const float* gru_bhh  = (const float*)d_in[15];
    const float* dec_w1   = (const float*)d_in[16];
    const float* dec_b1   = (const float*)d_in[17];
    const float* dec_g1   = (const float*)d_in[18];
    const float* dec_bt1  = (const float*)d_in[19];
    const float* dec_w2   = (const float*)d_in[20];
    const float* dec_b2   = (const float*)d_in[21];
    const float* dec_g2   = (const float*)d_in[22];
    const float* dec_bt2  = (const float*)d_in[23];
    float* out = (float*)d_out;

    float* p_h1 = symf(g_h1);
    float* p_x  = symf(g_x);
    float* p_gi = symf(g_gi);
    float* p_d1 = symf(g_d1);
    float* p_d2 = symf(g_d2);
    float* p_m  = symf(g_mean);
    float* p_v  = symf(g_var);
    float* p_ws = symf(g_wscan);

    int8_t *pq_obs1 = symq(q_obs1), *pq_obs0 = symq(q_obs0);
    int8_t *pq_w1a = symq(q_w1a), *pq_w1b = symq(q_w1b);
    int8_t *pq_h1a = symq(q_h1a), *pq_h1b = symq(q_h1b);
    int8_t *pq_w2a = symq(q_w2a), *pq_w2b = symq(q_w2b);
    int8_t *pq_xa = symq(q_xa), *pq_xb = symq(q_xb);
    int8_t *pq_wiha = symq(q_wiha), *pq_wihb = symq(q_wihb);
    float *ps_obs = symf(s_obs), *ps_w1 = symf(s_w1), *ps_h1 = symf(s_h1);
    float *ps_w2 = symf(s_w2), *ps_x = symf(s_x), *ps_wih = symf(s_wih);

    bf16 *p_zh = symb(g_zh), *p_zl = symb(g_zl);
    bf16 *p_d1h = symb(g_d1h), *p_d1l = symb(g_d1l);
    bf16 *p_dw1h = symb(g_dw1h), *p_dw1l = symb(g_dw1l);
    bf16 *p_dw2h = symb(g_dw2h), *p_dw2l = symb(g_dw2l);

    cudaFuncSetAttribute(mma_gemm, cudaFuncAttributeMaxDynamicSharedMemorySize, SM3_BYTES);
    cudaFuncSetAttribute(mma_scan, cudaFuncAttributeMaxDynamicSharedMemorySize, SSM_BYTES);
    cudaFuncSetAttribute(imma_gemm, cudaFuncAttributeMaxDynamicSharedMemorySize, QSM_BYTES);

    dim3 blk(256);
    dim3 statsBlk(32, 8);

    // ---- quantize inputs/weights (int8 split) ----
    quant_rows<<<BT, blk>>>(obs, pq_obs1, pq_obs0, ps_obs, OBSn);
    quant_rows<<<Hh, blk>>>(enc_w1, pq_w1a, pq_w1b, ps_w1, OBSn);
    quant_rows<<<Dd, blk>>>(enc_w2, pq_w2a, pq_w2b, ps_w2, Hh);
    quant_rows<<<3 * Dd, blk>>>(gru_wih, pq_wiha, pq_wihb, ps_wih, Dd);
    // decoder weights (bf16 path)
    cvt_hl<<<(Hh * Dd / 4 + 255) / 256, blk>>>(dec_w1, p_dw1h, p_dw1l, Hh * Dd / 4);
    cvt_hl<<<(OBSn * Hh / 4 + 255) / 256, blk>>>(dec_w2, p_dw2h, p_dw2l, OBSn * Hh / 4);

    // ---- precompute scan operators ----
    {
        dim3 grid(Dd / 128, 3 * Dd / 128);
        sgemm_ab<<<grid, blk>>>(gru_whh, je_w, p_ws, 3 * Dd, Dd, Dd, Dd, JEW_LD, Dd);
        copy_jew<<<(Dd * Dd + 255) / 256, blk>>>(je_w);
        m2c_k<<<3 * Dd, 128>>>(gru_whh, je_w, je_b, gru_bhh);
        cvt_hl_perm_ws<<<(4 * Dd * Dd / 4 + 255) / 256, blk>>>();
    }

    // ---- encoder layer 1 (IMMA) ----
    {
        dim3 grid(Hh / 128, BT / 128);
        imma_gemm<<<grid, blk, QSM_BYTES>>>(pq_obs1, pq_obs0, ps_obs,
                                            pq_w1a, pq_w1b, ps_w1,
                                            enc_b1, p_h1, BT, Hh, OBSn);
        col_stats<<<Hh / 32, statsBlk>>>(p_h1, BT, Hh, p_m, p_v);
        bn_apply<<<(BT * Hh + 255) / 256, blk>>>(p_h1, p_h1, p_m, p_v,
                                                 enc_g1, enc_bt1, BT * Hh, Hh, 1);
        quant_rows<<<BT, blk>>>(p_h1, pq_h1a, pq_h1b, ps_h1, Hh);
    }
    // ---- encoder layer 2 (IMMA) ----
    {
        dim3 grid(Dd / 128, BT / 128);
        imma_gemm<<<grid, blk, QSM_BYTES>>>(pq_h1a, pq_h1b, ps_h1,
                                            pq_w2a, pq_w2b, ps_w2,
                                            enc_b2, p_x, BT, Dd, Hh);
        col_stats<<<Dd / 32, statsBlk>>>(p_x, BT, Dd, p_m, p_v);
        bn_apply<<<(BT * Dd + 255) / 256, blk>>>(p_x, p_x, p_m, p_v,
                                                 enc_g2, enc_bt2, BT * Dd, Dd, 0);
        quant_rows<<<BT, blk>>>(p_x, pq_xa, pq_xb, ps_x, Dd);
    }
    // ---- gi (IMMA) ----
    {
        dim3 grid(3 * Dd / 128, BT / 128);
        imma_gemm<<<grid, blk, QSM_BYTES>>>(pq_xa, pq_xb, ps_x,
                                            pq_wiha, pq_wihb, ps_wih,
                                            gru_bih, p_gi, BT, 3 * Dd, Dd);
    }
    // ---- recurrent scan: fused kernel per step (bf16) ----
    zero_h<<<(Bb * Dd + 255) / 256, blk>>>();
    {
        dim3 gridS(4 * Dd / 64, Bb / 128);
        for (int t = 0; t < Tt; t++)
            mma_scan<<<gridS, blk, SSM_BYTES>>>(actions, je_w, je_b, t);
    }
    // ---- gumbel softmax ----
    gumbel_softmax_k<<<Bb * ZLn, ZDn>>>(out);
    // ---- decoder layer 1 (HMMA) ----
    {
        dim3 grid(Hh / 128, Bb / 128);
        mma_gemm<<<grid, blk, SM3_BYTES>>>(p_zh, p_zl, p_dw1h, p_dw1l, dec_b1, p_d1,
                                           Bb, Hh, Dd);
        col_stats<<<Hh / 32, statsBlk>>>(p_d1, Bb, Hh, p_m, p_v);
        bn_apply_cvt<<<(Bb * Hh / 4 + 255) / 256, blk>>>(p_d1, nullptr, p_d1h, p_d1l,
                                                         p_m, p_v, dec_g1, dec_bt1,
                                                         Bb * Hh / 4, Hh, 1);
    }
    // ---- decoder layer 2 (HMMA) -> x_hat ----
    {
        dim3 grid(OBSn / 128, Bb / 128);
        mma_gemm<<<grid, blk, SM3_BYTES>>>(p_d1h, p_d1l, p_dw2h, p_dw2l, dec_b2, p_d2,
                                           Bb, OBSn, Hh);
        col_stats<<<OBSn / 32, statsBlk>>>(p_d2, Bb, OBSn, p_m, p_v);
        int total = Bb * OBSn;
        bn_apply<<<(total + 255) / 256, blk>>>(p_d2, out + 2 * Bb * ZLn * ZDn,
                                               p_m, p_v, dec_g2, dec_bt2, total, OBSn, 0);
    }
}

// round 9
// speedup vs baseline: 1.6000x; 1.6000x over previous
#include <cuda_runtime.h>
#include <cuda_bf16.h>
#include <cstdint>

#define Bb   256
#define Tt   64
#define OBSn 4096
#define Dd   1024
#define Aa   8
#define Hh   2048
#define ZLn  4
#define ZDn  256
#define BT   (Bb*Tt)          // 16384
#define EPSf 1e-5f
#define JEW_LD (Dd + Aa)      // 1032

typedef __nv_bfloat16 bf16;

// ---------------- scratch (static device globals; no allocation) -------------
__device__ float g_h1[BT * Hh];
__device__ float g_x [BT * Dd];
__device__ float g_gi[BT * 3 * Dd];
__device__ float g_h [Bb * Dd];
__device__ float g_z [Bb * ZLn * ZDn];
__device__ float g_d1[Bb * Hh];
__device__ float g_d2[Bb * OBSn];
__device__ float g_mean[4096];
__device__ float g_var [4096];
__device__ float g_wscan[4 * Dd * Dd]; // rows: 0-3071 whh@jeW, 3072+ jeW
__device__ float g_M2[3 * Dd * Aa];
__device__ float g_c [3 * Dd];
__device__ unsigned g_bar_cnt;

// bf16 hi/lo split buffers
__device__ bf16 g_obsh[BT * OBSn], g_obsl[BT * OBSn];
__device__ bf16 g_w1h [Hh * OBSn], g_w1l [Hh * OBSn];
__device__ bf16 g_h1h [BT * Hh],   g_h1l [BT * Hh];
__device__ bf16 g_w2h [Dd * Hh],   g_w2l [Dd * Hh];
__device__ bf16 g_xh  [BT * Dd],   g_xl  [BT * Dd];
__device__ bf16 g_wihh[3 * Dd * Dd], g_wihl[3 * Dd * Dd];
__device__ bf16 g_wsh [4 * Dd * Dd], g_wsl [4 * Dd * Dd];  // PERMUTED rows 4d+comp
__device__ bf16 g_hh  [Bb * Dd],   g_hl  [Bb * Dd];
__device__ bf16 g_zh  [Bb * Dd],   g_zl  [Bb * Dd];
__device__ bf16 g_d1h [Bb * Hh],   g_d1l [Bb * Hh];
__device__ bf16 g_dw1h[Hh * Dd],   g_dw1l[Hh * Dd];
__device__ bf16 g_dw2h[OBSn * Hh], g_dw2l[OBSn * Hh];

// ======================= PTX helpers =========================================
__device__ __forceinline__ uint32_t smem_u32(const void* p) {
    uint32_t a;
    asm("{ .reg .u64 t; cvta.to.shared.u64 t, %1; cvt.u32.u64 %0, t; }"
        : "=r"(a) : "l"(p));
    return a;
}
__device__ __forceinline__ void cp16(uint32_t s, const void* g) {
    asm volatile("cp.async.cg.shared.global [%0], [%1], 16;" :: "r"(s), "l"(g));
}
__device__ __forceinline__ void cp_commit() {
    asm volatile("cp.async.commit_group;" ::: "memory");
}
__device__ __forceinline__ void cp_wait0() {
    asm volatile("cp.async.wait_group 0;" ::: "memory");
}
__device__ __forceinline__ void cp_wait1() {
    asm volatile("cp.async.wait_group 1;" ::: "memory");
}
__device__ __forceinline__ void cp_wait2() {
    asm volatile("cp.async.wait_group 2;" ::: "memory");
}
__device__ __forceinline__ void ldm_x4(uint32_t* r, uint32_t a) {
    asm volatile("ldmatrix.sync.aligned.m8n8.x4.shared.b16 {%0,%1,%2,%3}, [%4];"
                 : "=r"(r[0]), "=r"(r[1]), "=r"(r[2]), "=r"(r[3]) : "r"(a));
}
__device__ __forceinline__ void mma_bf16(float* c, const uint32_t* a, const uint32_t* b) {
    asm volatile("mma.sync.aligned.m16n8k16.row.col.f32.bf16.bf16.f32 "
                 "{%0,%1,%2,%3}, {%4,%5,%6,%7}, {%8,%9}, {%0,%1,%2,%3};"
                 : "+f"(c[0]), "+f"(c[1]), "+f"(c[2]), "+f"(c[3])
                 : "r"(a[0]), "r"(a[1]), "r"(a[2]), "r"(a[3]),
                   "r"(b[0]), "r"(b[1]));
}

// =================== HMMA hi/lo GEMM: C = A @ B^T (+bias), 3-stage ===========
// Ah/Al: MxK, Bh/Bl: NxK (bf16, ld=K), C: MxN fp32.
// M%128==0, N%128==0, K%32==0 (NC>=2). Grid (N/128, M/128), 256 threads.
#define LD2   40
#define TILE2 (128 * LD2)
#define STAGE2 (4 * TILE2)
#define SM3_BYTES (3 * STAGE2 * 2)     // 122880

__global__ void __launch_bounds__(256)
mma_gemm(const bf16* __restrict__ Ah, const bf16* __restrict__ Al,
         const bf16* __restrict__ Bh, const bf16* __restrict__ Bl,
         const float* __restrict__ bias, float* __restrict__ C,
         int M, int N, int K)
{
    extern __shared__ bf16 sm2[];

    const int tid = threadIdx.x;
    const int wid = tid >> 5, lane = tid & 31;
    const int wm = wid >> 2, wn = wid & 3;
    const int rowBase = blockIdx.y * 128, colBase = blockIdx.x * 128;
    const int NC = K >> 5;

    float acc[4][4][4];
#pragma unroll
    for (int i = 0; i < 4; i++)
#pragma unroll
        for (int j = 0; j < 4; j++)
#pragma unroll
            for (int k = 0; k < 4; k++) acc[i][j][k] = 0.f;

    const bf16* srcs[4] = { Ah, Al, Bh, Bl };
    const int   rbs [4] = { rowBase, rowBase, colBase, colBase };

    auto load = [&](int c, int st) {
        const int koff = c << 5;
        bf16* stp = sm2 + st * STAGE2;
#pragma unroll
        for (int tI = 0; tI < 4; tI++) {
#pragma unroll
            for (int i = 0; i < 2; i++) {
                int u = tid * 2 + i;
                int row = u >> 2;
                int seg = (u & 3) << 3;
                cp16(smem_u32(stp + tI * TILE2 + row * LD2 + seg),
                     srcs[tI] + (size_t)(rbs[tI] + row) * K + koff + seg);
            }
        }
        cp_commit();
    };

    load(0, 0);
    load(1, 1);
    for (int c = 0; c < NC; c++) {
        const int st = c % 3;
        if (c + 2 < NC) { load(c + 2, (c + 2) % 3); cp_wait2(); }
        else if (c + 1 < NC) cp_wait1();
        else cp_wait0();
        __syncthreads();

        const bf16* stp = sm2 + st * STAGE2;
#pragma unroll
        for (int kh = 0; kh < 2; kh++) {
            const int kcol = kh << 4;
            uint32_t a[2][4][4];
            uint32_t b[2][4][2];
#pragma unroll
            for (int t = 0; t < 2; t++) {
                const bf16* base = stp + t * TILE2;
#pragma unroll
                for (int mt = 0; mt < 4; mt++) {
                    int r = wm * 64 + mt * 16 + (lane & 15);
                    int cc = kcol + ((lane >> 4) << 3);
                    ldm_x4(a[t][mt], smem_u32(base + r * LD2 + cc));
                }
            }
#pragma unroll
            for (int t = 0; t < 2; t++) {
                const bf16* base = stp + (2 + t) * TILE2;
#pragma unroll
                for (int np = 0; np < 2; np++) {
                    int r = wn * 32 + (np * 2 + (lane >> 4)) * 8 + (lane & 7);
                    int cc = kcol + (((lane >> 3) & 1) << 3);
                    uint32_t rr[4];
                    ldm_x4(rr, smem_u32(base + r * LD2 + cc));
                    b[t][np * 2][0] = rr[0];     b[t][np * 2][1] = rr[1];
                    b[t][np * 2 + 1][0] = rr[2]; b[t][np * 2 + 1][1] = rr[3];
                }
            }
#pragma unroll
            for (int mt = 0; mt < 4; mt++)
#pragma unroll
                for (int nt = 0; nt < 4; nt++) {
                    mma_bf16(acc[mt][nt], a[0][mt], b[0][nt]);
                    mma_bf16(acc[mt][nt], a[0][mt], b[1][nt]);
                    mma_bf16(acc[mt][nt], a[1][mt], b[0][nt]);
                }
        }
        __syncthreads();
    }

#pragma unroll
    for (int mt = 0; mt < 4; mt++) {
        const int row = rowBase + wm * 64 + mt * 16 + (lane >> 2);
#pragma unroll
        for (int nt = 0; nt < 4; nt++) {
            const int col = colBase + wn * 32 + nt * 8 + (lane & 3) * 2;
            float b0 = bias ? bias[col] : 0.f;
            float b1 = bias ? bias[col + 1] : 0.f;
            *(float2*)(C + (size_t)row * N + col) =
                make_float2(acc[mt][nt][0] + b0, acc[mt][nt][1] + b1);
            *(float2*)(C + (size_t)(row + 8) * N + col) =
                make_float2(acc[mt][nt][2] + b0, acc[mt][nt][3] + b1);
        }
    }
}

// =================== persistent fused scan: all 64 steps =====================
// Grid MUST be (64, 2) = 128 CTAs (all resident; grid < #SM). One launch.
#define SLD    40
#define SATILE (128 * SLD)
#define SBTILE (64 * SLD)
#define SSTAGE (2 * SATILE + 2 * SBTILE)
#define SSM_BYTES (2 * SSTAGE * 2)     // 61440
#define SLDF   68
#define NCTA_SCAN 128

__device__ __forceinline__ float sigmoidf_(float x) { return 1.f / (1.f + expf(-x)); }

__global__ void __launch_bounds__(256)
mma_scan_persist(const float* __restrict__ actions,
                 const float* __restrict__ je_w,
                 const float* __restrict__ je_b)
{
    extern __shared__ bf16 ssm[];

    const int tid = threadIdx.x;
    const int wid = tid >> 5, lane = tid & 31;
    const int wm = wid >> 2, wn = wid & 3;
    const int rowBase = blockIdx.y * 128;
    const int colBase = blockIdx.x * 64;
    const int NC = Dd >> 5;   // 32

    // ---- per-thread gate constants (invariant across steps) ----
    const int dl = tid & 15;
    const int rg = tid >> 4;
    const int dg = (colBase >> 2) + dl;
    const float c0 = g_c[dg], c1 = g_c[Dd + dg], c2 = g_c[2 * Dd + dg];
    const float jb = je_b[dg];
    float m2r[8], m2z[8], m2n[8], jea[8];
#pragma unroll
    for (int j = 0; j < 8; j++) {
        m2r[j] = g_M2[(size_t)dg * 8 + j];
        m2z[j] = g_M2[(size_t)(Dd + dg) * 8 + j];
        m2n[j] = g_M2[(size_t)(2 * Dd + dg) * 8 + j];
        jea[j] = je_w[(size_t)dg * JEW_LD + Dd + j];
    }

    auto load = [&](int c, int st) {
        const int koff = c << 5;
        bf16* stp = ssm + st * SSTAGE;
#pragma unroll
        for (int tI = 0; tI < 2; tI++) {
            const bf16* src = tI ? g_hl : g_hh;
#pragma unroll
            for (int i = 0; i < 2; i++) {
                int u = tid * 2 + i;
                int row = u >> 2;
                int seg = (u & 3) << 3;
                cp16(smem_u32(stp + tI * SATILE + row * SLD + seg),
                     src + (size_t)(rowBase + row) * Dd + koff + seg);
            }
        }
#pragma unroll
        for (int tI = 0; tI < 2; tI++) {
            const bf16* src = tI ? g_wsl : g_wsh;
            int row = tid >> 2;
            int seg = (tid & 3) << 3;
            cp16(smem_u32(stp + 2 * SATILE + tI * SBTILE + row * SLD + seg),
                 src + (size_t)(colBase + row) * Dd + koff + seg);
        }
        cp_commit();
    };

    for (int t = 0; t < Tt; t++) {
        float acc[4][2][4];
#pragma unroll
        for (int i = 0; i < 4; i++)
#pragma unroll
            for (int j = 0; j < 2; j++)
#pragma unroll
                for (int k = 0; k < 4; k++) acc[i][j][k] = 0.f;

        load(0, 0);
        int st = 0;
        for (int c = 0; c < NC; c++) {
            const bool more = (c + 1) < NC;
            if (more) { load(c + 1, st ^ 1); cp_wait1(); }
            else      { cp_wait0(); }
            __syncthreads();

            const bf16* stp = ssm + st * SSTAGE;
#pragma unroll
            for (int kh = 0; kh < 2; kh++) {
                const int kcol = kh << 4;
                uint32_t a[2][4][4];
                uint32_t b[2][2][2];
#pragma unroll
                for (int tI = 0; tI < 2; tI++) {
                    const bf16* base = stp + tI * SATILE;
#pragma unroll
                    for (int mt = 0; mt < 4; mt++) {
                        int r = wm * 64 + mt * 16 + (lane & 15);
                        int cc = kcol + ((lane >> 4) << 3);
                        ldm_x4(a[tI][mt], smem_u32(base + r * SLD + cc));
                    }
                }
#pragma unroll
                for (int tI = 0; tI < 2; tI++) {
                    const bf16* base = stp + 2 * SATILE + tI * SBTILE;
                    int r = wn * 16 + (lane >> 4) * 8 + (lane & 7);
                    int cc = kcol + (((lane >> 3) & 1) << 3);
                    uint32_t rr[4];
                    ldm_x4(rr, smem_u32(base + r * SLD + cc));
                    b[tI][0][0] = rr[0]; b[tI][0][1] = rr[1];
                    b[tI][1][0] = rr[2]; b[tI][1][1] = rr[3];
                }
#pragma unroll
                for (int mt = 0; mt < 4; mt++)
#pragma unroll
                    for (int nt = 0; nt < 2; nt++) {
                        mma_bf16(acc[mt][nt], a[0][mt], b[0][nt]);
                        mma_bf16(acc[mt][nt], a[0][mt], b[1][nt]);
                        mma_bf16(acc[mt][nt], a[1][mt], b[0][nt]);
                    }
            }
            __syncthreads();
            st ^= 1;
        }

        // ---- epilogue: stage tile to smem, compute GRU gate ----
        float* smf = (float*)ssm;
#pragma unroll
        for (int mt = 0; mt < 4; mt++) {
            const int row = wm * 64 + mt * 16 + (lane >> 2);
#pragma unroll
            for (int nt = 0; nt < 2; nt++) {
                const int col = wn * 16 + nt * 8 + (lane & 3) * 2;
                smf[row * SLDF + col]     = acc[mt][nt][0];
                smf[row * SLDF + col + 1] = acc[mt][nt][1];
                smf[(row + 8) * SLDF + col]     = acc[mt][nt][2];
                smf[(row + 8) * SLDF + col + 1] = acc[mt][nt][3];
            }
        }
        __syncthreads();

#pragma unroll
        for (int r8 = 0; r8 < 8; r8++) {
            const int row = rg * 8 + r8;
            const int b = rowBase + row;
            const int trow = b * Tt + t;

            float4 G4 = *(float4*)&smf[row * SLDF + 4 * dl];
            float hr = G4.x + c0;
            float hz = G4.y + c1;
            float hn = G4.z + c2;
            float hj = G4.w + jb;

            const float* a = actions + (size_t)trow * Aa;
#pragma unroll
            for (int j = 0; j < 8; j++) {
                float av = a[j];
                hr = fmaf(av, m2r[j], hr);
                hz = fmaf(av, m2z[j], hz);
                hn = fmaf(av, m2n[j], hn);
                hj = fmaf(av, jea[j], hj);
            }

            const float* gi = g_gi + (size_t)trow * (3 * Dd);
            float r = sigmoidf_(gi[dg] + hr);
            float z = sigmoidf_(gi[Dd + dg] + hz);
            float n = tanhf(gi[2 * Dd + dg] + r * hn);
            float xv = g_x[(size_t)trow * Dd + dg];
            float hnew = (1.f - z) * n + z * hj + xv;

            const int oi = b * Dd + dg;
            g_h[oi] = hnew;
            bf16 hh = __float2bfloat16(hnew);
            g_hh[oi] = hh;
            g_hl[oi] = __float2bfloat16(hnew - __bfloat162float(hh));
        }

        // ---- grid barrier (monotonic counter; reset by zero_h) ----
        __syncthreads();
        if (tid == 0) {
            __threadfence();
            atomicAdd(&g_bar_cnt, 1u);
            const unsigned target = (unsigned)(t + 1) * NCTA_SCAN;
            while (atomicAdd(&g_bar_cnt, 0u) < target) {}
            __threadfence();
        }
        __syncthreads();
    }
}

// =============== hi/lo conversion ============================================
__global__ void cvt_hl(const float* __restrict__ X, bf16* __restrict__ Xh,
                       bf16* __restrict__ Xl, int n4)
{
    int i = blockIdx.x * blockDim.x + threadIdx.x;
    if (i >= n4) return;
    float4 v = ((const float4*)X)[i];
    bf16 h0 = __float2bfloat16(v.x), h1 = __float2bfloat16(v.y);
    bf16 h2 = __float2bfloat16(v.z), h3 = __float2bfloat16(v.w);
    float l0 = v.x - __bfloat162float(h0), l1 = v.y - __bfloat162float(h1);
    float l2 = v.z - __bfloat162float(h2), l3 = v.w - __bfloat162float(h3);
    __nv_bfloat162* H = (__nv_bfloat162*)Xh;
    __nv_bfloat162* L = (__nv_bfloat162*)Xl;
    H[2 * i]     = __nv_bfloat162(h0, h1);
    H[2 * i + 1] = __nv_bfloat162(h2, h3);
    L[2 * i]     = __nv_bfloat162(__float2bfloat16(l0), __float2bfloat16(l1));
    L[2 * i + 1] = __nv_bfloat162(__float2bfloat16(l2), __float2bfloat16(l3));
}

// permuted cvt of W_scan: new row 4d+comp <- old row comp*1024+d / 3072+d
__global__ void cvt_hl_perm_ws()
{
    int i = blockIdx.x * blockDim.x + threadIdx.x;
    if (i >= 4 * Dd * Dd / 4) return;
    int flat = i * 4;
    int nrow = flat >> 10;
    int k = flat & 1023;
    int d = nrow >> 2, comp = nrow & 3;
    int orow = (comp < 3) ? comp * Dd + d : 3 * Dd + d;
    float4 v = *(const float4*)&g_wscan[(size_t)orow * Dd + k];
    bf16 h0 = __float2bfloat16(v.x), h1 = __float2bfloat16(v.y);
    bf16 h2 = __float2bfloat16(v.z), h3 = __float2bfloat16(v.w);
    __nv_bfloat162* H = (__nv_bfloat162*)g_wsh;
    __nv_bfloat162* L = (__nv_bfloat162*)g_wsl;
    H[2*i]   = __nv_bfloat162(h0, h1);
    H[2*i+1] = __nv_bfloat162(h2, h3);
    L[2*i]   = __nv_bfloat162(__float2bfloat16(v.x - __bfloat162float(h0)),
                              __float2bfloat16(v.y - __bfloat162float(h1)));
    L[2*i+1] = __nv_bfloat162(__float2bfloat16(v.z - __bfloat162float(h2)),
                              __float2bfloat16(v.w - __bfloat162float(h3)));
}

// =============== SIMT GEMM (precompute only) ==================================
#define BKd 8
__global__ void __launch_bounds__(256)
sgemm_ab(const float* __restrict__ A, const float* __restrict__ Bm,
         float* __restrict__ C, int M, int N, int K, int lda, int ldb, int ldc)
{
    __shared__ float As[BKd][128];
    __shared__ float Bs[BKd][128];
    const int tid = threadIdx.x;
    const int tx = tid & 15, ty = tid >> 4;
    const int rowBase = blockIdx.y * 128, colBase = blockIdx.x * 128;
    const int lrA = tid >> 1, lcA = (tid & 1) * 4;
    const int kkB = tid >> 5, c4B = (tid & 31) * 4;
    const float* Aptr = A + (size_t)(rowBase + lrA) * lda + lcA;
    const float* Bptr = Bm + (size_t)kkB * ldb + colBase + c4B;
    float acc[8][8];
#pragma unroll
    for (int i = 0; i < 8; i++)
#pragma unroll
        for (int j = 0; j < 8; j++) acc[i][j] = 0.f;
    for (int k0 = 0; k0 < K; k0 += BKd) {
        float4 av = *(const float4*)(Aptr + k0);
        float4 bv = *(const float4*)(Bptr + (size_t)k0 * ldb);
        As[lcA+0][lrA]=av.x; As[lcA+1][lrA]=av.y;
        As[lcA+2][lrA]=av.z; As[lcA+3][lrA]=av.w;
        *(float4*)&Bs[kkB][c4B] = bv;
        __syncthreads();
#pragma unroll
        for (int kk = 0; kk < BKd; kk++) {
            float a[8], b[8];
#pragma unroll
            for (int i = 0; i < 8; i++) a[i] = As[kk][ty*8+i];
#pragma unroll
            for (int j = 0; j < 8; j++) b[j] = Bs[kk][tx*8+j];
#pragma unroll
            for (int i = 0; i < 8; i++)
#pragma unroll
                for (int j = 0; j < 8; j++)
                    acc[i][j] = fmaf(a[i], b[j], acc[i][j]);
        }
        __syncthreads();
    }
#pragma unroll
    for (int i = 0; i < 8; i++) {
        const int r = rowBase + ty * 8 + i;
#pragma unroll
        for (int j = 0; j < 8; j++)
            C[(size_t)r * ldc + colBase + tx * 8 + j] = acc[i][j];
    }
}

__global__ void copy_jew(const float* __restrict__ je_w)
{
    int idx = blockIdx.x * blockDim.x + threadIdx.x;
    if (idx >= Dd * Dd) return;
    int j = idx >> 10, k = idx & 1023;
    g_wscan[(size_t)(3 * Dd + j) * Dd + k] = je_w[(size_t)j * JEW_LD + k];
}

__global__ void __launch_bounds__(128)
m2c_k(const float* __restrict__ whh, const float* __restrict__ je_w,
      const float* __restrict__ je_b, const float* __restrict__ bhh)
{
    const int i = blockIdx.x;
    const int t = threadIdx.x;
    float acc[9];
#pragma unroll
    for (int j = 0; j < 9; j++) acc[j] = 0.f;
    for (int k = t; k < Dd; k += 128) {
        float w = whh[(size_t)i * Dd + k];
        const float* jr = je_w + (size_t)k * JEW_LD + Dd;
#pragma unroll
        for (int j = 0; j < 8; j++) acc[j] = fmaf(w, jr[j], acc[j]);
        acc[8] = fmaf(w, je_b[k], acc[8]);
    }
    __shared__ float sh[9][128];
#pragma unroll
    for (int j = 0; j < 9; j++) sh[j][t] = acc[j];
    __syncthreads();
    for (int s = 64; s > 0; s >>= 1) {
        if (t < s)
#pragma unroll
            for (int j = 0; j < 9; j++) sh[j][t] += sh[j][t + s];
        __syncthreads();
    }
    if (t == 0) {
#pragma unroll
        for (int j = 0; j < 8; j++) g_M2[i * 8 + j] = sh[j][0];
        g_c[i] = sh[8][0] + bhh[i];
    }
}

// ---------------- batch stats + BN ------------------------------------------
__global__ void col_stats(const float* __restrict__ X, int M, int N,
                          float* __restrict__ mean, float* __restrict__ var)
{
    const int c = blockIdx.x * 32 + threadIdx.x;
    const int ry = threadIdx.y;
    float s = 0.f, s2 = 0.f;
    for (int r = ry; r < M; r += 8) {
        float v = X[(size_t)r * N + c];
        s += v; s2 += v * v;
    }
    __shared__ float sh[8][32], sh2[8][32];
    sh[ry][threadIdx.x] = s; sh2[ry][threadIdx.x] = s2;
    __syncthreads();
    if (ry == 0) {
#pragma unroll
        for (int y = 1; y < 8; y++) { s += sh[y][threadIdx.x]; s2 += sh2[y][threadIdx.x]; }
        float m = s / (float)M;
        mean[c] = m;
        var[c]  = s2 / (float)M - m * m;
    }
}

__global__ void bn_apply(const float* __restrict__ X, float* __restrict__ Y,
                         const float* __restrict__ mean, const float* __restrict__ var,
                         const float* __restrict__ g, const float* __restrict__ beta,
                         int total, int N, int relu)
{
    int idx = blockIdx.x * blockDim.x + threadIdx.x;
    if (idx >= total) return;
    int c = idx % N;
    float v = g[c] * (X[idx] - mean[c]) * rsqrtf(var[c] + EPSf) + beta[c];
    if (relu) v = fmaxf(v, 0.f);
    Y[idx] = v;
}

__global__ void bn_apply_cvt(const float* __restrict__ X, float* __restrict__ Yf,
                             bf16* __restrict__ Yh, bf16* __restrict__ Yl,
                             const float* __restrict__ mean, const float* __restrict__ var,
                             const float* __restrict__ g, const float* __restrict__ beta,
                             int total4, int N, int relu)
{
    int i = blockIdx.x * blockDim.x + threadIdx.x;
    if (i >= total4) return;
    int c0 = (i * 4) % N;
    float4 v = ((const float4*)X)[i];
    float o[4] = { v.x, v.y, v.z, v.w };
#pragma unroll
    for (int j = 0; j < 4; j++) {
        int c = c0 + j;
        float t = g[c] * (o[j] - mean[c]) * rsqrtf(var[c] + EPSf) + beta[c];
        if (relu) t = fmaxf(t, 0.f);
        o[j] = t;
    }
    if (Yf) ((float4*)Yf)[i] = make_float4(o[0], o[1], o[2], o[3]);
    bf16 h0 = __float2bfloat16(o[0]), h1 = __float2bfloat16(o[1]);
    bf16 h2 = __float2bfloat16(o[2]), h3 = __float2bfloat16(o[3]);
    __nv_bfloat162* H = (__nv_bfloat162*)Yh;
    __nv_bfloat162* L = (__nv_bfloat162*)Yl;
    H[2*i]   = __nv_bfloat162(h0, h1);
    H[2*i+1] = __nv_bfloat162(h2, h3);
    L[2*i]   = __nv_bfloat162(__float2bfloat16(o[0] - __bfloat162float(h0)),
                              __float2bfloat16(o[1] - __bfloat162float(h1)));
    L[2*i+1] = __nv_bfloat162(__float2bfloat16(o[2] - __bfloat162float(h2)),
                              __float2bfloat16(o[3] - __bfloat162float(h3)));
}

// ---------------- misc ------------------------------------------------------
__global__ void zero_h() {
    int idx = blockIdx.x * blockDim.x + threadIdx.x;
    if (idx == 0) g_bar_cnt = 0u;
    if (idx < Bb * Dd) {
        g_h[idx] = 0.f;
        g_hh[idx] = __float2bfloat16(0.f);
        g_hl[idx] = __float2bfloat16(0.f);
    }
}

// ---------------- threefry2x32-20 (JAX partitionable) ------------------------
__device__ __forceinline__ uint32_t rotl32_(uint32_t x, int r) {
    return (x << r) | (x >> (32 - r));
}
__device__ __forceinline__ void threefry2x32_(uint32_t k0, uint32_t k1,
                                              uint32_t& x0, uint32_t& x1)
{
    const uint32_t k2 = k0 ^ k1 ^ 0x1BD11BDAu;
    x0 += k0; x1 += k1;
#define TF_R4(a,b,c,d) \
    x0 += x1; x1 = rotl32_(x1, a); x1 ^= x0; \
    x0 += x1; x1 = rotl32_(x1, b); x1 ^= x0; \
    x0 += x1; x1 = rotl32_(x1, c); x1 ^= x0; \
    x0 += x1; x1 = rotl32_(x1, d); x1 ^= x0;
    TF_R4(13,15,26,6)  x0 += k1; x1 += k2 + 1u;
    TF_R4(17,29,16,24) x0 += k2; x1 += k0 + 2u;
    TF_R4(13,15,26,6)  x0 += k0; x1 += k1 + 3u;
    TF_R4(17,29,16,24) x0 += k1; x1 += k2 + 4u;
    TF_R4(13,15,26,6)  x0 += k2; x1 += k0 + 5u;
#undef TF_R4
}

__global__ void gumbel_softmax_k(float* __restrict__ out)
{
    const int bl = blockIdx.x;
    const int d  = threadIdx.x;
    const int i  = bl * ZDn + d;
    const float logit = g_h[i];

    uint32_t c0 = 0u;
    uint32_t c1 = (uint32_t)i;
    threefry2x32_(0u, 42u, c0, c1);
    const uint32_t bits = c0 ^ c1;
    float f = __uint_as_float((bits >> 9) | 0x3f800000u) - 1.0f;
    const float tiny = 1.1754943508222875e-38f;
    float u = fmaxf(f * (1.0f - tiny) + tiny, tiny);
    float gum = -logf(-logf(u));

    float v = logit + gum;

    __shared__ float red[ZDn];
    red[d] = v; __syncthreads();
    for (int s = ZDn / 2; s > 0; s >>= 1) {
        if (d < s) red[d] = fmaxf(red[d], red[d + s]);
        __syncthreads();
    }
    float mx = red[0];
    __syncthreads();
    float e = expf(v - mx);
    red[d] = e; __syncthreads();
    for (int s = ZDn / 2; s > 0; s >>= 1) {
        if (d < s) red[d] += red[d + s];
        __syncthreads();
    }
    float z = e / red[0];

    out[i] = logit;
    out[Bb * ZLn * ZDn + i] = z;
    g_z[i] = z;
    bf16 zh = __float2bfloat16(z);
    g_zh[i] = zh;
    g_zl[i] = __float2bfloat16(z - __bfloat162float(zh));
}

// ---------------- launch ------------------------------------------------------
static inline float* symf(const void* s) {
    void* p = nullptr;
    cudaGetSymbolAddress(&p, s);
    return (float*)p;
}
static inline bf16* symb(const void* s) {
    void* p = nullptr;
    cudaGetSymbolAddress(&p, s);
    return (bf16*)p;
}

extern "C" void kernel_launch(void* const* d_in, const int* in_sizes, int n_in,
                              void* d_out, int out_size)
{
    (void)in_sizes; (void)n_in; (void)out_size;
    const float* obs      = (const float*)d_in[0];
    const float* actions  = (const float*)d_in[1];
    const float* enc_w1   = (const float*)d_in[2];
    const float* enc_b1   = (const float*)d_in[3];
    const float* enc_g1   = (const float*)d_in[4];
    const float* enc_bt1  = (const float*)d_in[5];
    const float* enc_w2   = (const float*)d_in[6];
    const float* enc_b2   = (const float*)d_in[7];
    const float* enc_g2   = (const float*)d_in[8];
    const float* enc_bt2  = (const float*)d_in[9];
    const float* je_w     = (const float*)d_in[10];
    const float* je_b     = (const float*)d_in[11];
    const float* gru_wih  = (const float*)d_in[12];
    const float* gru_bih  = (const float*)d_in[13];
    const float* gru_whh  = (const float*)d_in[14];
    const float* gru_bhh  = (const float*)d_in[15];
    const float* dec_w1   = (const float*)d_in[16];
    const float* dec_b1   = (const float*)d_in[17];
    const float* dec_g1   = (const float*)d_in[18];
    const float* dec_bt1  = (const float*)d_in[19];
    const float* dec_w2   = (const float*)d_in[20];
    const float* dec_b2   = (const float*)d_in[21];
    const float* dec_g2   = (const float*)d_in[22];
    const float* dec_bt2  = (const float*)d_in[23];
    float* out = (float*)d_out;

    float* p_h1 = symf(g_h1);
    float* p_x  = symf(g_x);
    float* p_gi = symf(g_gi);
    float* p_d1 = symf(g_d1);
    float* p_d2 = symf(g_d2);
    float* p_m  = symf(g_mean);
    float* p_v  = symf(g_var);
    float* p_ws = symf(g_wscan);

    bf16 *p_obsh = symb(g_obsh), *p_obsl = symb(g_obsl);
    bf16 *p_w1h = symb(g_w1h), *p_w1l = symb(g_w1l);
    bf16 *p_h1h = symb(g_h1h), *p_h1l = symb(g_h1l);
    bf16 *p_w2h = symb(g_w2h), *p_w2l = symb(g_w2l);
    bf16 *p_xh = symb(g_xh), *p_xl = symb(g_xl);
    bf16 *p_wihh = symb(g_wihh), *p_wihl = symb(g_wihl);
    bf16 *p_zh = symb(g_zh), *p_zl = symb(g_zl);
    bf16 *p_d1h = symb(g_d1h), *p_d1l = symb(g_d1l);
    bf16 *p_dw1h = symb(g_dw1h), *p_dw1l = symb(g_dw1l);
    bf16 *p_dw2h = symb(g_dw2h), *p_dw2l = symb(g_dw2l);

    cudaFuncSetAttribute(mma_gemm, cudaFuncAttributeMaxDynamicSharedMemorySize, SM3_BYTES);
    cudaFuncSetAttribute(mma_scan_persist, cudaFuncAttributeMaxDynamicSharedMemorySize, SSM_BYTES);

    dim3 blk(256);
    dim3 statsBlk(32, 8);

    // ---- input/weight conversions ----
    cvt_hl<<<(BT * OBSn / 4 + 255) / 256, blk>>>(obs, p_obsh, p_obsl, BT * OBSn / 4);
    cvt_hl<<<(Hh * OBSn / 4 + 255) / 256, blk>>>(enc_w1, p_w1h, p_w1l, Hh * OBSn / 4);
    cvt_hl<<<(Dd * Hh / 4 + 255) / 256, blk>>>(enc_w2, p_w2h, p_w2l, Dd * Hh / 4);
    cvt_hl<<<(3 * Dd * Dd / 4 + 255) / 256, blk>>>(gru_wih, p_wihh, p_wihl, 3 * Dd * Dd / 4);
    cvt_hl<<<(Hh * Dd / 4 + 255) / 256, blk>>>(dec_w1, p_dw1h, p_dw1l, Hh * Dd / 4);
    cvt_hl<<<(OBSn * Hh / 4 + 255) / 256, blk>>>(dec_w2, p_dw2h, p_dw2l, OBSn * Hh / 4);

    // ---- precompute scan operators ----
    {
        dim3 grid(Dd / 128, 3 * Dd / 128);
        sgemm_ab<<<grid, blk>>>(gru_whh, je_w, p_ws, 3 * Dd, Dd, Dd, Dd, JEW_LD, Dd);
        copy_jew<<<(Dd * Dd + 255) / 256, blk>>>(je_w);
        m2c_k<<<3 * Dd, 128>>>(gru_whh, je_w, je_b, gru_bhh);
        cvt_hl_perm_ws<<<(4 * Dd * Dd / 4 + 255) / 256, blk>>>();
    }

    // ---- encoder layer 1 (HMMA) ----
    {
        dim3 grid(Hh / 128, BT / 128);
        mma_gemm<<<grid, blk, SM3_BYTES>>>(p_obsh, p_obsl, p_w1h, p_w1l, enc_b1, p_h1,
                                           BT, Hh, OBSn);
        col_stats<<<Hh / 32, statsBlk>>>(p_h1, BT, Hh, p_m, p_v);
        bn_apply_cvt<<<(BT * Hh / 4 + 255) / 256, blk>>>(p_h1, nullptr, p_h1h, p_h1l,
                                                         p_m, p_v, enc_g1, enc_bt1,
                                                         BT * Hh / 4, Hh, 1);
    }
    // ---- encoder layer 2 (HMMA) ----
    {
        dim3 grid(Dd / 128, BT / 128);
        mma_gemm<<<grid, blk, SM3_BYTES>>>(p_h1h, p_h1l, p_w2h, p_w2l, enc_b2, p_x,
                                           BT, Dd, Hh);
        col_stats<<<Dd / 32, statsBlk>>>(p_x, BT, Dd, p_m, p_v);
        bn_apply_cvt<<<(BT * Dd / 4 + 255) / 256, blk>>>(p_x, p_x, p_xh, p_xl,
                                                         p_m, p_v, enc_g2, enc_bt2,
                                                         BT * Dd / 4, Dd, 0);
    }
    // ---- gi (HMMA) ----
    {
        dim3 grid(3 * Dd / 128, BT / 128);
        mma_gemm<<<grid, blk, SM3_BYTES>>>(p_xh, p_xl, p_wihh, p_wihl, gru_bih, p_gi,
                                           BT, 3 * Dd, Dd);
    }
    // ---- recurrent scan: ONE persistent kernel (all 64 steps) ----
    zero_h<<<(Bb * Dd + 255) / 256, blk>>>();
    {
        dim3 gridS(4 * Dd / 64, Bb / 128);   // (64, 2) = 128 CTAs, all resident
        mma_scan_persist<<<gridS, blk, SSM_BYTES>>>(actions, je_w, je_b);
    }
    // ---- gumbel softmax ----
    gumbel_softmax_k<<<Bb * ZLn, ZDn>>>(out);
    // ---- decoder layer 1 (HMMA) ----
    {
        dim3 grid(Hh / 128, Bb / 128);
        mma_gemm<<<grid, blk, SM3_BYTES>>>(p_zh, p_zl, p_dw1h, p_dw1l, dec_b1, p_d1,
                                           Bb, Hh, Dd);
        col_stats<<<Hh / 32, statsBlk>>>(p_d1, Bb, Hh, p_m, p_v);
        bn_apply_cvt<<<(Bb * Hh / 4 + 255) / 256, blk>>>(p_d1, nullptr, p_d1h, p_d1l,
                                                         p_m, p_v, dec_g1, dec_bt1,
                                                         Bb * Hh / 4, Hh, 1);
    }
    // ---- decoder layer 2 (HMMA) -> x_hat ----
    {
        dim3 grid(OBSn / 128, Bb / 128);
        mma_gemm<<<grid, blk, SM3_BYTES>>>(p_d1h, p_d1l, p_dw2h, p_dw2l, dec_b2, p_d2,
                                           Bb, OBSn, Hh);
        col_stats<<<OBSn / 32, statsBlk>>>(p_d2, Bb, OBSn, p_m, p_v);
        int total = Bb * OBSn;
        bn_apply<<<(total + 255) / 256, blk>>>(p_d2, out + 2 * Bb * ZLn * ZDn,
                                               p_m, p_v, dec_g2, dec_bt2, total, OBSn, 0);
    }
}

// round 10
// speedup vs baseline: 1.6362x; 1.0226x over previous
#include <cuda_runtime.h>
#include <cuda_bf16.h>
#include <cstdint>

#define Bb   256
#define Tt   64
#define OBSn 4096
#define Dd   1024
#define Aa   8
#define Hh   2048
#define ZLn  4
#define ZDn  256
#define BT   (Bb*Tt)          // 16384
#define EPSf 1e-5f
#define JEW_LD (Dd + Aa)      // 1032

typedef __nv_bfloat16 bf16;

// ---------------- scratch (static device globals; no allocation) -------------
__device__ float g_h1[BT * Hh];
__device__ float g_x [BT * Dd];
__device__ float g_gi[BT * 3 * Dd];
__device__ float g_h [Bb * Dd];
__device__ float g_d1[Bb * Hh];
__device__ float g_d2[Bb * OBSn];
__device__ float g_mean[4096];
__device__ float g_var [4096];
__device__ float g_wscan[4 * Dd * Dd]; // rows: 0-3071 whh@jeW, 3072+ jeW
__device__ float g_M2[3 * Dd * Aa];
__device__ float g_c [3 * Dd];
__device__ unsigned g_bar_cnt;

// bf16 hi/lo split buffers
__device__ bf16 g_obsh[BT * OBSn], g_obsl[BT * OBSn];
__device__ bf16 g_w1h [Hh * OBSn], g_w1l [Hh * OBSn];
__device__ bf16 g_h1h [BT * Hh],   g_h1l [BT * Hh];
__device__ bf16 g_w2h [Dd * Hh],   g_w2l [Dd * Hh];
__device__ bf16 g_xh  [BT * Dd],   g_xl  [BT * Dd];
__device__ bf16 g_wihh[3 * Dd * Dd], g_wihl[3 * Dd * Dd];
__device__ bf16 g_wsh [4 * Dd * Dd], g_wsl [4 * Dd * Dd];  // PERMUTED rows 4d+comp
__device__ bf16 g_hh  [Bb * Dd],   g_hl  [Bb * Dd];
__device__ bf16 g_zh  [Bb * Dd],   g_zl  [Bb * Dd];
__device__ bf16 g_d1h [Bb * Hh],   g_d1l [Bb * Hh];
__device__ bf16 g_dw1h[Hh * Dd],   g_dw1l[Hh * Dd];
__device__ bf16 g_dw2h[OBSn * Hh], g_dw2l[OBSn * Hh];

// ======================= PTX helpers =========================================
__device__ __forceinline__ uint32_t smem_u32(const void* p) {
    uint32_t a;
    asm("{ .reg .u64 t; cvta.to.shared.u64 t, %1; cvt.u32.u64 %0, t; }"
        : "=r"(a) : "l"(p));
    return a;
}
__device__ __forceinline__ void cp16(uint32_t s, const void* g) {
    asm volatile("cp.async.cg.shared.global [%0], [%1], 16;" :: "r"(s), "l"(g));
}
__device__ __forceinline__ void cp_commit() {
    asm volatile("cp.async.commit_group;" ::: "memory");
}
__device__ __forceinline__ void cp_wait0() {
    asm volatile("cp.async.wait_group 0;" ::: "memory");
}
__device__ __forceinline__ void cp_wait1() {
    asm volatile("cp.async.wait_group 1;" ::: "memory");
}
__device__ __forceinline__ void cp_wait2() {
    asm volatile("cp.async.wait_group 2;" ::: "memory");
}
__device__ __forceinline__ void ldm_x4(uint32_t* r, uint32_t a) {
    asm volatile("ldmatrix.sync.aligned.m8n8.x4.shared.b16 {%0,%1,%2,%3}, [%4];"
                 : "=r"(r[0]), "=r"(r[1]), "=r"(r[2]), "=r"(r[3]) : "r"(a));
}
__device__ __forceinline__ void mma_bf16(float* c, const uint32_t* a, const uint32_t* b) {
    asm volatile("mma.sync.aligned.m16n8k16.row.col.f32.bf16.bf16.f32 "
                 "{%0,%1,%2,%3}, {%4,%5,%6,%7}, {%8,%9}, {%0,%1,%2,%3};"
                 : "+f"(c[0]), "+f"(c[1]), "+f"(c[2]), "+f"(c[3])
                 : "r"(a[0]), "r"(a[1]), "r"(a[2]), "r"(a[3]),
                   "r"(b[0]), "r"(b[1]));
}

// =================== HMMA hi/lo GEMM: C = A @ B^T (+bias), 3-stage ===========
#define LD2   40
#define TILE2 (128 * LD2)
#define STAGE2 (4 * TILE2)
#define SM3_BYTES (3 * STAGE2 * 2)     // 122880

__global__ void __launch_bounds__(256)
mma_gemm(const bf16* __restrict__ Ah, const bf16* __restrict__ Al,
         const bf16* __restrict__ Bh, const bf16* __restrict__ Bl,
         const float* __restrict__ bias, float* __restrict__ C,
         int M, int N, int K)
{
    extern __shared__ bf16 sm2[];

    const int tid = threadIdx.x;
    const int wid = tid >> 5, lane = tid & 31;
    const int wm = wid >> 2, wn = wid & 3;
    const int rowBase = blockIdx.y * 128, colBase = blockIdx.x * 128;
    const int NC = K >> 5;

    float acc[4][4][4];
#pragma unroll
    for (int i = 0; i < 4; i++)
#pragma unroll
        for (int j = 0; j < 4; j++)
#pragma unroll
            for (int k = 0; k < 4; k++) acc[i][j][k] = 0.f;

    const bf16* srcs[4] = { Ah, Al, Bh, Bl };
    const int   rbs [4] = { rowBase, rowBase, colBase, colBase };

    auto load = [&](int c, int st) {
        const int koff = c << 5;
        bf16* stp = sm2 + st * STAGE2;
#pragma unroll
        for (int tI = 0; tI < 4; tI++) {
#pragma unroll
            for (int i = 0; i < 2; i++) {
                int u = tid * 2 + i;
                int row = u >> 2;
                int seg = (u & 3) << 3;
                cp16(smem_u32(stp + tI * TILE2 + row * LD2 + seg),
                     srcs[tI] + (size_t)(rbs[tI] + row) * K + koff + seg);
            }
        }
        cp_commit();
    };

    load(0, 0);
    load(1, 1);
    for (int c = 0; c < NC; c++) {
        const int st = c % 3;
        if (c + 2 < NC) { load(c + 2, (c + 2) % 3); cp_wait2(); }
        else if (c + 1 < NC) cp_wait1();
        else cp_wait0();
        __syncthreads();

        const bf16* stp = sm2 + st * STAGE2;
#pragma unroll
        for (int kh = 0; kh < 2; kh++) {
            const int kcol = kh << 4;
            uint32_t a[2][4][4];
            uint32_t b[2][4][2];
#pragma unroll
            for (int t = 0; t < 2; t++) {
                const bf16* base = stp + t * TILE2;
#pragma unroll
                for (int mt = 0; mt < 4; mt++) {
                    int r = wm * 64 + mt * 16 + (lane & 15);
                    int cc = kcol + ((lane >> 4) << 3);
                    ldm_x4(a[t][mt], smem_u32(base + r * LD2 + cc));
                }
            }
#pragma unroll
            for (int t = 0; t < 2; t++) {
                const bf16* base = stp + (2 + t) * TILE2;
#pragma unroll
                for (int np = 0; np < 2; np++) {
                    int r = wn * 32 + (np * 2 + (lane >> 4)) * 8 + (lane & 7);
                    int cc = kcol + (((lane >> 3) & 1) << 3);
                    uint32_t rr[4];
                    ldm_x4(rr, smem_u32(base + r * LD2 + cc));
                    b[t][np * 2][0] = rr[0];     b[t][np * 2][1] = rr[1];
                    b[t][np * 2 + 1][0] = rr[2]; b[t][np * 2 + 1][1] = rr[3];
                }
            }
#pragma unroll
            for (int mt = 0; mt < 4; mt++)
#pragma unroll
                for (int nt = 0; nt < 4; nt++) {
                    mma_bf16(acc[mt][nt], a[0][mt], b[0][nt]);
                    mma_bf16(acc[mt][nt], a[0][mt], b[1][nt]);
                    mma_bf16(acc[mt][nt], a[1][mt], b[0][nt]);
                }
        }
        __syncthreads();
    }

#pragma unroll
    for (int mt = 0; mt < 4; mt++) {
        const int row = rowBase + wm * 64 + mt * 16 + (lane >> 2);
#pragma unroll
        for (int nt = 0; nt < 4; nt++) {
            const int col = colBase + wn * 32 + nt * 8 + (lane & 3) * 2;
            float b0 = bias ? bias[col] : 0.f;
            float b1 = bias ? bias[col + 1] : 0.f;
            *(float2*)(C + (size_t)row * N + col) =
                make_float2(acc[mt][nt][0] + b0, acc[mt][nt][1] + b1);
            *(float2*)(C + (size_t)(row + 8) * N + col) =
                make_float2(acc[mt][nt][2] + b0, acc[mt][nt][3] + b1);
        }
    }
}

// =================== persistent fused scan: all 64 steps =====================
#define SLD    40
#define SATILE (128 * SLD)
#define SBTILE (64 * SLD)
#define SSTAGE (2 * SATILE + 2 * SBTILE)
#define SSM_BYTES (2 * SSTAGE * 2)     // 61440
#define SLDF   68
#define NCTA_SCAN 128

__device__ __forceinline__ float sigmoidf_(float x) { return 1.f / (1.f + expf(-x)); }

__global__ void __launch_bounds__(256)
mma_scan_persist(const float* __restrict__ actions,
                 const float* __restrict__ je_w,
                 const float* __restrict__ je_b)
{
    extern __shared__ bf16 ssm[];

    const int tid = threadIdx.x;
    const int wid = tid >> 5, lane = tid & 31;
    const int wm = wid >> 2, wn = wid & 3;
    const int rowBase = blockIdx.y * 128;
    const int colBase = blockIdx.x * 64;
    const int NC = Dd >> 5;   // 32

    const int dl = tid & 15;
    const int rg = tid >> 4;
    const int dg = (colBase >> 2) + dl;
    const float c0 = g_c[dg], c1 = g_c[Dd + dg], c2 = g_c[2 * Dd + dg];
    const float jb = je_b[dg];
    float m2r[8], m2z[8], m2n[8], jea[8];
#pragma unroll
    for (int j = 0; j < 8; j++) {
        m2r[j] = g_M2[(size_t)dg * 8 + j];
        m2z[j] = g_M2[(size_t)(Dd + dg) * 8 + j];
        m2n[j] = g_M2[(size_t)(2 * Dd + dg) * 8 + j];
        jea[j] = je_w[(size_t)dg * JEW_LD + Dd + j];
    }

    auto load = [&](int c, int st) {
        const int koff = c << 5;
        bf16* stp = ssm + st * SSTAGE;
#pragma unroll
        for (int tI = 0; tI < 2; tI++) {
            const bf16* src = tI ? g_hl : g_hh;
#pragma unroll
            for (int i = 0; i < 2; i++) {
                int u = tid * 2 + i;
                int row = u >> 2;
                int seg = (u & 3) << 3;
                cp16(smem_u32(stp + tI * SATILE + row * SLD + seg),
                     src + (size_t)(rowBase + row) * Dd + koff + seg);
            }
        }
#pragma unroll
        for (int tI = 0; tI < 2; tI++) {
            const bf16* src = tI ? g_wsl : g_wsh;
            int row = tid >> 2;
            int seg = (tid & 3) << 3;
            cp16(smem_u32(stp + 2 * SATILE + tI * SBTILE + row * SLD + seg),
                 src + (size_t)(colBase + row) * Dd + koff + seg);
        }
        cp_commit();
    };

    for (int t = 0; t < Tt; t++) {
        float acc[4][2][4];
#pragma unroll
        for (int i = 0; i < 4; i++)
#pragma unroll
            for (int j = 0; j < 2; j++)
#pragma unroll
                for (int k = 0; k < 4; k++) acc[i][j][k] = 0.f;

        load(0, 0);
        int st = 0;
        for (int c = 0; c < NC; c++) {
            const bool more = (c + 1) < NC;
            if (more) { load(c + 1, st ^ 1); cp_wait1(); }
            else      { cp_wait0(); }
            __syncthreads();

            const bf16* stp = ssm + st * SSTAGE;
#pragma unroll
            for (int kh = 0; kh < 2; kh++) {
                const int kcol = kh << 4;
                uint32_t a[2][4][4];
                uint32_t b[2][2][2];
#pragma unroll
                for (int tI = 0; tI < 2; tI++) {
                    const bf16* base = stp + tI * SATILE;
#pragma unroll
                    for (int mt = 0; mt < 4; mt++) {
                        int r = wm * 64 + mt * 16 + (lane & 15);
                        int cc = kcol + ((lane >> 4) << 3);
                        ldm_x4(a[tI][mt], smem_u32(base + r * SLD + cc));
                    }
                }
#pragma unroll
                for (int tI = 0; tI < 2; tI++) {
                    const bf16* base = stp + 2 * SATILE + tI * SBTILE;
                    int r = wn * 16 + (lane >> 4) * 8 + (lane & 7);
                    int cc = kcol + (((lane >> 3) & 1) << 3);
                    uint32_t rr[4];
                    ldm_x4(rr, smem_u32(base + r * SLD + cc));
                    b[tI][0][0] = rr[0]; b[tI][0][1] = rr[1];
                    b[tI][1][0] = rr[2]; b[tI][1][1] = rr[3];
                }
#pragma unroll
                for (int mt = 0; mt < 4; mt++)
#pragma unroll
                    for (int nt = 0; nt < 2; nt++) {
                        mma_bf16(acc[mt][nt], a[0][mt], b[0][nt]);
                        mma_bf16(acc[mt][nt], a[0][mt], b[1][nt]);
                        mma_bf16(acc[mt][nt], a[1][mt], b[0][nt]);
                    }
            }
            __syncthreads();
            st ^= 1;
        }

        float* smf = (float*)ssm;
#pragma unroll
        for (int mt = 0; mt < 4; mt++) {
            const int row = wm * 64 + mt * 16 + (lane >> 2);
#pragma unroll
            for (int nt = 0; nt < 2; nt++) {
                const int col = wn * 16 + nt * 8 + (lane & 3) * 2;
                smf[row * SLDF + col]     = acc[mt][nt][0];
                smf[row * SLDF + col + 1] = acc[mt][nt][1];
                smf[(row + 8) * SLDF + col]     = acc[mt][nt][2];
                smf[(row + 8) * SLDF + col + 1] = acc[mt][nt][3];
            }
        }
        __syncthreads();

#pragma unroll
        for (int r8 = 0; r8 < 8; r8++) {
            const int row = rg * 8 + r8;
            const int b = rowBase + row;
            const int trow = b * Tt + t;

            float4 G4 = *(float4*)&smf[row * SLDF + 4 * dl];
            float hr = G4.x + c0;
            float hz = G4.y + c1;
            float hn = G4.z + c2;
            float hj = G4.w + jb;

            const float* a = actions + (size_t)trow * Aa;
#pragma unroll
            for (int j = 0; j < 8; j++) {
                float av = a[j];
                hr = fmaf(av, m2r[j], hr);
                hz = fmaf(av, m2z[j], hz);
                hn = fmaf(av, m2n[j], hn);
                hj = fmaf(av, jea[j], hj);
            }

            const float* gi = g_gi + (size_t)trow * (3 * Dd);
            float r = sigmoidf_(gi[dg] + hr);
            float z = sigmoidf_(gi[Dd + dg] + hz);
            float n = tanhf(gi[2 * Dd + dg] + r * hn);
            float xv = g_x[(size_t)trow * Dd + dg];
            float hnew = (1.f - z) * n + z * hj + xv;

            const int oi = b * Dd + dg;
            g_h[oi] = hnew;
            bf16 hh = __float2bfloat16(hnew);
            g_hh[oi] = hh;
            g_hl[oi] = __float2bfloat16(hnew - __bfloat162float(hh));
        }

        __syncthreads();
        if (tid == 0) {
            __threadfence();
            atomicAdd(&g_bar_cnt, 1u);
            const unsigned target = (unsigned)(t + 1) * NCTA_SCAN;
            while (atomicAdd(&g_bar_cnt, 0u) < target) {}
            __threadfence();
        }
        __syncthreads();
    }
}

// =============== hi/lo conversion ============================================
__global__ void cvt_hl(const float* __restrict__ X, bf16* __restrict__ Xh,
                       bf16* __restrict__ Xl, int n4)
{
    int i = blockIdx.x * blockDim.x + threadIdx.x;
    if (i >= n4) return;
    float4 v = ((const float4*)X)[i];
    bf16 h0 = __float2bfloat16(v.x), h1 = __float2bfloat16(v.y);
    bf16 h2 = __float2bfloat16(v.z), h3 = __float2bfloat16(v.w);
    float l0 = v.x - __bfloat162float(h0), l1 = v.y - __bfloat162float(h1);
    float l2 = v.z - __bfloat162float(h2), l3 = v.w - __bfloat162float(h3);
    __nv_bfloat162* H = (__nv_bfloat162*)Xh;
    __nv_bfloat162* L = (__nv_bfloat162*)Xl;
    H[2 * i]     = __nv_bfloat162(h0, h1);
    H[2 * i + 1] = __nv_bfloat162(h2, h3);
    L[2 * i]     = __nv_bfloat162(__float2bfloat16(l0), __float2bfloat16(l1));
    L[2 * i + 1] = __nv_bfloat162(__float2bfloat16(l2), __float2bfloat16(l3));
}

// permuted cvt of W_scan: new row 4d+comp <- old row comp*1024+d / 3072+d
__global__ void cvt_hl_perm_ws()
{
    int i = blockIdx.x * blockDim.x + threadIdx.x;
    if (i >= 4 * Dd * Dd / 4) return;
    int flat = i * 4;
    int nrow = flat >> 10;
    int k = flat & 1023;
    int d = nrow >> 2, comp = nrow & 3;
    int orow = (comp < 3) ? comp * Dd + d : 3 * Dd + d;
    float4 v = *(const float4*)&g_wscan[(size_t)orow * Dd + k];
    bf16 h0 = __float2bfloat16(v.x), h1 = __float2bfloat16(v.y);
    bf16 h2 = __float2bfloat16(v.z), h3 = __float2bfloat16(v.w);
    __nv_bfloat162* H = (__nv_bfloat162*)g_wsh;
    __nv_bfloat162* L = (__nv_bfloat162*)g_wsl;
    H[2*i]   = __nv_bfloat162(h0, h1);
    H[2*i+1] = __nv_bfloat162(h2, h3);
    L[2*i]   = __nv_bfloat162(__float2bfloat16(v.x - __bfloat162float(h0)),
                              __float2bfloat16(v.y - __bfloat162float(h1)));
    L[2*i+1] = __nv_bfloat162(__float2bfloat16(v.z - __bfloat162float(h2)),
                              __float2bfloat16(v.w - __bfloat162float(h3)));
}

// =============== SIMT GEMM (precompute only) ==================================
#define BKd 8
__global__ void __launch_bounds__(256)
sgemm_ab(const float* __restrict__ A, const float* __restrict__ Bm,
         float* __restrict__ C, int M, int N, int K, int lda, int ldb, int ldc)
{
    __shared__ float As[BKd][128];
    __shared__ float Bs[BKd][128];
    const int tid = threadIdx.x;
    const int tx = tid & 15, ty = tid >> 4;
    const int rowBase = blockIdx.y * 128, colBase = blockIdx.x * 128;
    const int lrA = tid >> 1, lcA = (tid & 1) * 4;
    const int kkB = tid >> 5, c4B = (tid & 31) * 4;
    const float* Aptr = A + (size_t)(rowBase + lrA) * lda + lcA;
    const float* Bptr = Bm + (size_t)kkB * ldb + colBase + c4B;
    float acc[8][8];
#pragma unroll
    for (int i = 0; i < 8; i++)
#pragma unroll
        for (int j = 0; j < 8; j++) acc[i][j] = 0.f;
    for (int k0 = 0; k0 < K; k0 += BKd) {
        float4 av = *(const float4*)(Aptr + k0);
        float4 bv = *(const float4*)(Bptr + (size_t)k0 * ldb);
        As[lcA+0][lrA]=av.x; As[lcA+1][lrA]=av.y;
        As[lcA+2][lrA]=av.z; As[lcA+3][lrA]=av.w;
        *(float4*)&Bs[kkB][c4B] = bv;
        __syncthreads();
#pragma unroll
        for (int kk = 0; kk < BKd; kk++) {
            float a[8], b[8];
#pragma unroll
            for (int i = 0; i < 8; i++) a[i] = As[kk][ty*8+i];
#pragma unroll
            for (int j = 0; j < 8; j++) b[j] = Bs[kk][tx*8+j];
#pragma unroll
            for (int i = 0; i < 8; i++)
#pragma unroll
                for (int j = 0; j < 8; j++)
                    acc[i][j] = fmaf(a[i], b[j], acc[i][j]);
        }
        __syncthreads();
    }
#pragma unroll
    for (int i = 0; i < 8; i++) {
        const int r = rowBase + ty * 8 + i;
#pragma unroll
        for (int j = 0; j < 8; j++)
            C[(size_t)r * ldc + colBase + tx * 8 + j] = acc[i][j];
    }
}

__global__ void copy_jew(const float* __restrict__ je_w)
{
    int idx = blockIdx.x * blockDim.x + threadIdx.x;
    if (idx >= Dd * Dd) return;
    int j = idx >> 10, k = idx & 1023;
    g_wscan[(size_t)(3 * Dd + j) * Dd + k] = je_w[(size_t)j * JEW_LD + k];
}

__global__ void __launch_bounds__(128)
m2c_k(const float* __restrict__ whh, const float* __restrict__ je_w,
      const float* __restrict__ je_b, const float* __restrict__ bhh)
{
    const int i = blockIdx.x;
    const int t = threadIdx.x;
    float acc[9];
#pragma unroll
    for (int j = 0; j < 9; j++) acc[j] = 0.f;
    for (int k = t; k < Dd; k += 128) {
        float w = whh[(size_t)i * Dd + k];
        const float* jr = je_w + (size_t)k * JEW_LD + Dd;
#pragma unroll
        for (int j = 0; j < 8; j++) acc[j] = fmaf(w, jr[j], acc[j]);
        acc[8] = fmaf(w, je_b[k], acc[8]);
    }
    __shared__ float sh[9][128];
#pragma unroll
    for (int j = 0; j < 9; j++) sh[j][t] = acc[j];
    __syncthreads();
    for (int s = 64; s > 0; s >>= 1) {
        if (t < s)
#pragma unroll
            for (int j = 0; j < 9; j++) sh[j][t] += sh[j][t + s];
        __syncthreads();
    }
    if (t == 0) {
#pragma unroll
        for (int j = 0; j < 8; j++) g_M2[i * 8 + j] = sh[j][0];
        g_c[i] = sh[8][0] + bhh[i];
    }
}

// ---------------- batch stats + BN ------------------------------------------
__global__ void col_stats(const float* __restrict__ X, int M, int N,
                          float* __restrict__ mean, float* __restrict__ var)
{
    const int c = blockIdx.x * 32 + threadIdx.x;
    const int ry = threadIdx.y;
    float s = 0.f, s2 = 0.f;
    for (int r = ry; r < M; r += 8) {
        float v = X[(size_t)r * N + c];
        s += v; s2 += v * v;
    }
    __shared__ float sh[8][32], sh2[8][32];
    sh[ry][threadIdx.x] = s; sh2[ry][threadIdx.x] = s2;
    __syncthreads();
    if (ry == 0) {
#pragma unroll
        for (int y = 1; y < 8; y++) { s += sh[y][threadIdx.x]; s2 += sh2[y][threadIdx.x]; }
        float m = s / (float)M;
        mean[c] = m;
        var[c]  = s2 / (float)M - m * m;
    }
}

__global__ void bn_apply(const float* __restrict__ X, float* __restrict__ Y,
                         const float* __restrict__ mean, const float* __restrict__ var,
                         const float* __restrict__ g, const float* __restrict__ beta,
                         int total, int N, int relu)
{
    int idx = blockIdx.x * blockDim.x + threadIdx.x;
    if (idx >= total) return;
    int c = idx % N;
    float v = g[c] * (X[idx] - mean[c]) * rsqrtf(var[c] + EPSf) + beta[c];
    if (relu) v = fmaxf(v, 0.f);
    Y[idx] = v;
}

__global__ void bn_apply_cvt(const float* __restrict__ X, float* __restrict__ Yf,
                             bf16* __restrict__ Yh, bf16* __restrict__ Yl,
                             const float* __restrict__ mean, const float* __restrict__ var,
                             const float* __restrict__ g, const float* __restrict__ beta,
                             int total4, int N, int relu)
{
    int i = blockIdx.x * blockDim.x + threadIdx.x;
    if (i >= total4) return;
    int c0 = (i * 4) % N;
    float4 v = ((const float4*)X)[i];
    float o[4] = { v.x, v.y, v.z, v.w };
#pragma unroll
    for (int j = 0; j < 4; j++) {
        int c = c0 + j;
        float t = g[c] * (o[j] - mean[c]) * rsqrtf(var[c] + EPSf) + beta[c];
        if (relu) t = fmaxf(t, 0.f);
        o[j] = t;
    }
    if (Yf) ((float4*)Yf)[i] = make_float4(o[0], o[1], o[2], o[3]);
    bf16 h0 = __float2bfloat16(o[0]), h1 = __float2bfloat16(o[1]);
    bf16 h2 = __float2bfloat16(o[2]), h3 = __float2bfloat16(o[3]);
    __nv_bfloat162* H = (__nv_bfloat162*)Yh;
    __nv_bfloat162* L = (__nv_bfloat162*)Yl;
    H[2*i]   = __nv_bfloat162(h0, h1);
    H[2*i+1] = __nv_bfloat162(h2, h3);
    L[2*i]   = __nv_bfloat162(__float2bfloat16(o[0] - __bfloat162float(h0)),
                              __float2bfloat16(o[1] - __bfloat162float(h1)));
    L[2*i+1] = __nv_bfloat162(__float2bfloat16(o[2] - __bfloat162float(h2)),
                              __float2bfloat16(o[3] - __bfloat162float(h3)));
}

// ---------------- misc ------------------------------------------------------
__global__ void zero_h() {
    int idx = blockIdx.x * blockDim.x + threadIdx.x;
    if (idx == 0) g_bar_cnt = 0u;
    if (idx < Bb * Dd) {
        g_h[idx] = 0.f;
        g_hh[idx] = __float2bfloat16(0.f);
        g_hl[idx] = __float2bfloat16(0.f);
    }
}

// ---------------- threefry2x32-20 (JAX partitionable) ------------------------
__device__ __forceinline__ uint32_t rotl32_(uint32_t x, int r) {
    return (x << r) | (x >> (32 - r));
}
__device__ __forceinline__ void threefry2x32_(uint32_t k0, uint32_t k1,
                                              uint32_t& x0, uint32_t& x1)
{
    const uint32_t k2 = k0 ^ k1 ^ 0x1BD11BDAu;
    x0 += k0; x1 += k1;
#define TF_R4(a,b,c,d) \
    x0 += x1; x1 = rotl32_(x1, a); x1 ^= x0; \
    x0 += x1; x1 = rotl32_(x1, b); x1 ^= x0; \
    x0 += x1; x1 = rotl32_(x1, c); x1 ^= x0; \
    x0 += x1; x1 = rotl32_(x1, d); x1 ^= x0;
    TF_R4(13,15,26,6)  x0 += k1; x1 += k2 + 1u;
    TF_R4(17,29,16,24) x0 += k2; x1 += k0 + 2u;
    TF_R4(13,15,26,6)  x0 += k0; x1 += k1 + 3u;
    TF_R4(17,29,16,24) x0 += k1; x1 += k2 + 4u;
    TF_R4(13,15,26,6)  x0 += k2; x1 += k0 + 5u;
#undef TF_R4
}

__global__ void gumbel_softmax_k(float* __restrict__ out)
{
    const int bl = blockIdx.x;
    const int d  = threadIdx.x;
    const int i  = bl * ZDn + d;
    const float logit = g_h[i];

    uint32_t c0 = 0u;
    uint32_t c1 = (uint32_t)i;
    threefry2x32_(0u, 42u, c0, c1);
    const uint32_t bits = c0 ^ c1;
    float f = __uint_as_float((bits >> 9) | 0x3f800000u) - 1.0f;
    const float tiny = 1.1754943508222875e-38f;
    float u = fmaxf(f * (1.0f - tiny) + tiny, tiny);
    float gum = -logf(-logf(u));

    float v = logit + gum;

    __shared__ float red[ZDn];
    red[d] = v; __syncthreads();
    for (int s = ZDn / 2; s > 0; s >>= 1) {
        if (d < s) red[d] = fmaxf(red[d], red[d + s]);
        __syncthreads();
    }
    float mx = red[0];
    __syncthreads();
    float e = expf(v - mx);
    red[d] = e; __syncthreads();
    for (int s = ZDn / 2; s > 0; s >>= 1) {
        if (d < s) red[d] += red[d + s];
        __syncthreads();
    }
    float z = e / red[0];

    out[i] = logit;
    out[Bb * ZLn * ZDn + i] = z;
    bf16 zh = __float2bfloat16(z);
    g_zh[i] = zh;
    g_zl[i] = __float2bfloat16(z - __bfloat162float(zh));
}

// ---------------- launch ------------------------------------------------------
static inline float* symf(const void* s) {
    void* p = nullptr;
    cudaGetSymbolAddress(&p, s);
    return (float*)p;
}
static inline bf16* symb(const void* s) {
    void* p = nullptr;
    cudaGetSymbolAddress(&p, s);
    return (bf16*)p;
}

extern "C" void kernel_launch(void* const* d_in, const int* in_sizes, int n_in,
                              void* d_out, int out_size)
{
    (void)in_sizes; (void)n_in; (void)out_size;
    const float* obs      = (const float*)d_in[0];
    const float* actions  = (const float*)d_in[1];
    const float* enc_w1   = (const float*)d_in[2];
    const float* enc_b1   = (const float*)d_in[3];
    const float* enc_g1   = (const float*)d_in[4];
    const float* enc_bt1  = (const float*)d_in[5];
    const float* enc_w2   = (const float*)d_in[6];
    const float* enc_b2   = (const float*)d_in[7];
    const float* enc_g2   = (const float*)d_in[8];
    const float* enc_bt2  = (const float*)d_in[9];
    const float* je_w     = (const float*)d_in[10];
    const float* je_b     = (const float*)d_in[11];
    const float* gru_wih  = (const float*)d_in[12];
    const float* gru_bih  = (const float*)d_in[13];
    const float* gru_whh  = (const float*)d_in[14];
    const float* gru_bhh  = (const float*)d_in[15];
    const float* dec_w1   = (const float*)d_in[16];
    const float* dec_b1   = (const float*)d_in[17];
    const float* dec_g1   = (const float*)d_in[18];
    const float* dec_bt1  = (const float*)d_in[19];
    const float* dec_w2   = (const float*)d_in[20];
    const float* dec_b2   = (const float*)d_in[21];
    const float* dec_g2   = (const float*)d_in[22];
    const float* dec_bt2  = (const float*)d_in[23];
    float* out = (float*)d_out;

    float* p_h1 = symf(g_h1);
    float* p_x  = symf(g_x);
    float* p_gi = symf(g_gi);
    float* p_d1 = symf(g_d1);
    float* p_d2 = symf(g_d2);
    float* p_m  = symf(g_mean);
    float* p_v  = symf(g_var);
    float* p_ws = symf(g_wscan);

    bf16 *p_obsh = symb(g_obsh), *p_obsl = symb(g_obsl);
    bf16 *p_w1h = symb(g_w1h), *p_w1l = symb(g_w1l);
    bf16 *p_h1h = symb(g_h1h), *p_h1l = symb(g_h1l);
    bf16 *p_w2h = symb(g_w2h), *p_w2l = symb(g_w2l);
    bf16 *p_xh = symb(g_xh), *p_xl = symb(g_xl);
    bf16 *p_wihh = symb(g_wihh), *p_wihl = symb(g_wihl);
    bf16 *p_zh = symb(g_zh), *p_zl = symb(g_zl);
    bf16 *p_d1h = symb(g_d1h), *p_d1l = symb(g_d1l);
    bf16 *p_dw1h = symb(g_dw1h), *p_dw1l = symb(g_dw1l);
    bf16 *p_dw2h = symb(g_dw2h), *p_dw2l = symb(g_dw2l);

    // one-time resources (host-side; no device memory involved)
    static cudaStream_t sSide = nullptr;
    static cudaEvent_t evFork = nullptr, evJoin = nullptr;
    static bool attrDone = false;
    if (!attrDone) {
        cudaFuncSetAttribute(mma_gemm, cudaFuncAttributeMaxDynamicSharedMemorySize, SM3_BYTES);
        cudaFuncSetAttribute(mma_scan_persist, cudaFuncAttributeMaxDynamicSharedMemorySize, SSM_BYTES);
        cudaStreamCreateWithFlags(&sSide, cudaStreamNonBlocking);
        cudaEventCreateWithFlags(&evFork, cudaEventDisableTiming);
        cudaEventCreateWithFlags(&evJoin, cudaEventDisableTiming);
        attrDone = true;
    }

    dim3 blk(256);
    dim3 statsBlk(32, 8);

    // ================== FORK: side stream does setup work =====================
    cudaEventRecord(evFork, 0);
    cudaStreamWaitEvent(sSide, evFork, 0);

    // side chain: weight cvts + scan-operator precompute (independent of enc1)
    cvt_hl<<<(Dd * Hh / 4 + 255) / 256, blk, 0, sSide>>>(enc_w2, p_w2h, p_w2l, Dd * Hh / 4);
    cvt_hl<<<(3 * Dd * Dd / 4 + 255) / 256, blk, 0, sSide>>>(gru_wih, p_wihh, p_wihl, 3 * Dd * Dd / 4);
    cvt_hl<<<(Hh * Dd / 4 + 255) / 256, blk, 0, sSide>>>(dec_w1, p_dw1h, p_dw1l, Hh * Dd / 4);
    cvt_hl<<<(OBSn * Hh / 4 + 255) / 256, blk, 0, sSide>>>(dec_w2, p_dw2h, p_dw2l, OBSn * Hh / 4);
    {
        dim3 grid(Dd / 128, 3 * Dd / 128);
        sgemm_ab<<<grid, blk, 0, sSide>>>(gru_whh, je_w, p_ws, 3 * Dd, Dd, Dd, Dd, JEW_LD, Dd);
        copy_jew<<<(Dd * Dd + 255) / 256, blk, 0, sSide>>>(je_w);
        m2c_k<<<3 * Dd, 128, 0, sSide>>>(gru_whh, je_w, je_b, gru_bhh);
        cvt_hl_perm_ws<<<(4 * Dd * Dd / 4 + 255) / 256, blk, 0, sSide>>>();
    }
    zero_h<<<(Bb * Dd + 255) / 256, blk, 0, sSide>>>();
    cudaEventRecord(evJoin, sSide);

    // main chain: obs/w1 cvt -> enc1
    cvt_hl<<<(BT * OBSn / 4 + 255) / 256, blk>>>(obs, p_obsh, p_obsl, BT * OBSn / 4);
    cvt_hl<<<(Hh * OBSn / 4 + 255) / 256, blk>>>(enc_w1, p_w1h, p_w1l, Hh * OBSn / 4);

    // ---- encoder layer 1 (HMMA) ----
    {
        dim3 grid(Hh / 128, BT / 128);
        mma_gemm<<<grid, blk, SM3_BYTES>>>(p_obsh, p_obsl, p_w1h, p_w1l, enc_b1, p_h1,
                                           BT, Hh, OBSn);
        col_stats<<<Hh / 32, statsBlk>>>(p_h1, BT, Hh, p_m, p_v);
        bn_apply_cvt<<<(BT * Hh / 4 + 255) / 256, blk>>>(p_h1, nullptr, p_h1h, p_h1l,
                                                         p_m, p_v, enc_g1, enc_bt1,
                                                         BT * Hh / 4, Hh, 1);
    }

    // ================== JOIN: side setup must be done from here ===============
    cudaStreamWaitEvent(0, evJoin, 0);

    // ---- encoder layer 2 (HMMA) ----
    {
        dim3 grid(Dd / 128, BT / 128);
        mma_gemm<<<grid, blk, SM3_BYTES>>>(p_h1h, p_h1l, p_w2h, p_w2l, enc_b2, p_x,
                                           BT, Dd, Hh);
        col_stats<<<Dd / 32, statsBlk>>>(p_x, BT, Dd, p_m, p_v);
        bn_apply_cvt<<<(BT * Dd / 4 + 255) / 256, blk>>>(p_x, p_x, p_xh, p_xl,
                                                         p_m, p_v, enc_g2, enc_bt2,
                                                         BT * Dd / 4, Dd, 0);
    }
    // ---- gi (HMMA) ----
    {
        dim3 grid(3 * Dd / 128, BT / 128);
        mma_gemm<<<grid, blk, SM3_BYTES>>>(p_xh, p_xl, p_wihh, p_wihl, gru_bih, p_gi,
                                           BT, 3 * Dd, Dd);
    }
    // ---- recurrent scan: ONE persistent kernel (all 64 steps) ----
    {
        dim3 gridS(4 * Dd / 64, Bb / 128);   // (64, 2) = 128 CTAs, all resident
        mma_scan_persist<<<gridS, blk, SSM_BYTES>>>(actions, je_w, je_b);
    }
    // ---- gumbel softmax ----
    gumbel_softmax_k<<<Bb * ZLn, ZDn>>>(out);
    // ---- decoder layer 1 (HMMA) ----
    {
        dim3 grid(Hh / 128, Bb / 128);
        mma_gemm<<<grid, blk, SM3_BYTES>>>(p_zh, p_zl, p_dw1h, p_dw1l, dec_b1, p_d1,
                                           Bb, Hh, Dd);
        col_stats<<<Hh / 32, statsBlk>>>(p_d1, Bb, Hh, p_m, p_v);
        bn_apply_cvt<<<(Bb * Hh / 4 + 255) / 256, blk>>>(p_d1, nullptr, p_d1h, p_d1l,
                                                         p_m, p_v, dec_g1, dec_bt1,
                                                         Bb * Hh / 4, Hh, 1);
    }
    // ---- decoder layer 2 (HMMA) -> x_hat ----
    {
        dim3 grid(OBSn / 128, Bb / 128);
        mma_gemm<<<grid, blk, SM3_BYTES>>>(p_d1h, p_d1l, p_dw2h, p_dw2l, dec_b2, p_d2,
                                           Bb, OBSn, Hh);
        col_stats<<<OBSn / 32, statsBlk>>>(p_d2, Bb, OBSn, p_m, p_v);
        int total = Bb * OBSn;
        bn_apply<<<(total + 255) / 256, blk>>>(p_d2, out + 2 * Bb * ZLn * ZDn,
                                               p_m, p_v, dec_g2, dec_bt2, total, OBSn, 0);
    }
}

// round 11
// speedup vs baseline: 1.6436x; 1.0045x over previous
#include <cuda_runtime.h>
#include <cuda_bf16.h>
#include <cstdint>

#define Bb   256
#define Tt   64
#define OBSn 4096
#define Dd   1024
#define Aa   8
#define Hh   2048
#define ZLn  4
#define ZDn  256
#define BT   (Bb*Tt)          // 16384
#define EPSf 1e-5f
#define JEW_LD (Dd + Aa)      // 1032

typedef __nv_bfloat16 bf16;

// ---------------- scratch (static device globals; no allocation) -------------
__device__ float g_h1[BT * Hh];
__device__ float g_x [BT * Dd];
__device__ float g_gi[BT * 3 * Dd];
__device__ float g_h [Bb * Dd];
__device__ float g_d1[Bb * Hh];
__device__ float g_d2[Bb * OBSn];
__device__ float g_mean[4096];
__device__ float g_var [4096];
__device__ float g_wscan[4 * Dd * Dd]; // rows: 0-3071 whh@jeW, 3072+ jeW
__device__ float g_M2[3 * Dd * Aa];
__device__ float g_c [3 * Dd];
__device__ unsigned g_bar_cnt;

// bf16 hi/lo split buffers
__device__ bf16 g_obsh[BT * OBSn], g_obsl[BT * OBSn];
__device__ bf16 g_w1h [Hh * OBSn], g_w1l [Hh * OBSn];
__device__ bf16 g_h1h [BT * Hh],   g_h1l [BT * Hh];
__device__ bf16 g_w2h [Dd * Hh],   g_w2l [Dd * Hh];
__device__ bf16 g_xh  [BT * Dd],   g_xl  [BT * Dd];
__device__ bf16 g_wihh[3 * Dd * Dd], g_wihl[3 * Dd * Dd];
__device__ bf16 g_wsh [4 * Dd * Dd], g_wsl [4 * Dd * Dd];  // PERMUTED rows 4d+comp
__device__ bf16 g_hh  [Bb * Dd],   g_hl  [Bb * Dd];
__device__ bf16 g_zh  [Bb * Dd],   g_zl  [Bb * Dd];
__device__ bf16 g_d1h [Bb * Hh],   g_d1l [Bb * Hh];
__device__ bf16 g_dw1h[Hh * Dd],   g_dw1l[Hh * Dd];
__device__ bf16 g_dw2h[OBSn * Hh], g_dw2l[OBSn * Hh];

// ======================= PTX helpers =========================================
__device__ __forceinline__ uint32_t smem_u32(const void* p) {
    uint32_t a;
    asm("{ .reg .u64 t; cvta.to.shared.u64 t, %1; cvt.u32.u64 %0, t; }"
        : "=r"(a) : "l"(p));
    return a;
}
__device__ __forceinline__ void cp16(uint32_t s, const void* g) {
    asm volatile("cp.async.cg.shared.global [%0], [%1], 16;" :: "r"(s), "l"(g));
}
__device__ __forceinline__ void cp_commit() {
    asm volatile("cp.async.commit_group;" ::: "memory");
}
__device__ __forceinline__ void cp_wait0() {
    asm volatile("cp.async.wait_group 0;" ::: "memory");
}
__device__ __forceinline__ void cp_wait1() {
    asm volatile("cp.async.wait_group 1;" ::: "memory");
}
__device__ __forceinline__ void cp_wait2() {
    asm volatile("cp.async.wait_group 2;" ::: "memory");
}
__device__ __forceinline__ void ldm_x4(uint32_t* r, uint32_t a) {
    asm volatile("ldmatrix.sync.aligned.m8n8.x4.shared.b16 {%0,%1,%2,%3}, [%4];"
                 : "=r"(r[0]), "=r"(r[1]), "=r"(r[2]), "=r"(r[3]) : "r"(a));
}
__device__ __forceinline__ void mma_bf16(float* c, const uint32_t* a, const uint32_t* b) {
    asm volatile("mma.sync.aligned.m16n8k16.row.col.f32.bf16.bf16.f32 "
                 "{%0,%1,%2,%3}, {%4,%5,%6,%7}, {%8,%9}, {%0,%1,%2,%3};"
                 : "+f"(c[0]), "+f"(c[1]), "+f"(c[2]), "+f"(c[3])
                 : "r"(a[0]), "r"(a[1]), "r"(a[2]), "r"(a[3]),
                   "r"(b[0]), "r"(b[1]));
}

// =================== HMMA hi/lo GEMM: C = A @ B^T (+bias), 3-stage ===========
#define LD2   40
#define TILE2 (128 * LD2)
#define STAGE2 (4 * TILE2)
#define SM3_BYTES (3 * STAGE2 * 2)     // 122880

__global__ void __launch_bounds__(256)
mma_gemm(const bf16* __restrict__ Ah, const bf16* __restrict__ Al,
         const bf16* __restrict__ Bh, const bf16* __restrict__ Bl,
         const float* __restrict__ bias, float* __restrict__ C,
         int M, int N, int K)
{
    extern __shared__ bf16 sm2[];

    const int tid = threadIdx.x;
    const int wid = tid >> 5, lane = tid & 31;
    const int wm = wid >> 2, wn = wid & 3;
    const int rowBase = blockIdx.y * 128, colBase = blockIdx.x * 128;
    const int NC = K >> 5;

    float acc[4][4][4];
#pragma unroll
    for (int i = 0; i < 4; i++)
#pragma unroll
        for (int j = 0; j < 4; j++)
#pragma unroll
            for (int k = 0; k < 4; k++) acc[i][j][k] = 0.f;

    const bf16* srcs[4] = { Ah, Al, Bh, Bl };
    const int   rbs [4] = { rowBase, rowBase, colBase, colBase };

    auto load = [&](int c, int st) {
        const int koff = c << 5;
        bf16* stp = sm2 + st * STAGE2;
#pragma unroll
        for (int tI = 0; tI < 4; tI++) {
#pragma unroll
            for (int i = 0; i < 2; i++) {
                int u = tid * 2 + i;
                int row = u >> 2;
                int seg = (u & 3) << 3;
                cp16(smem_u32(stp + tI * TILE2 + row * LD2 + seg),
                     srcs[tI] + (size_t)(rbs[tI] + row) * K + koff + seg);
            }
        }
        cp_commit();
    };

    load(0, 0);
    load(1, 1);
    for (int c = 0; c < NC; c++) {
        const int st = c % 3;
        if (c + 2 < NC) { load(c + 2, (c + 2) % 3); cp_wait2(); }
        else if (c + 1 < NC) cp_wait1();
        else cp_wait0();
        __syncthreads();

        const bf16* stp = sm2 + st * STAGE2;
#pragma unroll
        for (int kh = 0; kh < 2; kh++) {
            const int kcol = kh << 4;
            uint32_t a[2][4][4];
            uint32_t b[2][4][2];
#pragma unroll
            for (int t = 0; t < 2; t++) {
                const bf16* base = stp + t * TILE2;
#pragma unroll
                for (int mt = 0; mt < 4; mt++) {
                    int r = wm * 64 + mt * 16 + (lane & 15);
                    int cc = kcol + ((lane >> 4) << 3);
                    ldm_x4(a[t][mt], smem_u32(base + r * LD2 + cc));
                }
            }
#pragma unroll
            for (int t = 0; t < 2; t++) {
                const bf16* base = stp + (2 + t) * TILE2;
#pragma unroll
                for (int np = 0; np < 2; np++) {
                    int r = wn * 32 + (np * 2 + (lane >> 4)) * 8 + (lane & 7);
                    int cc = kcol + (((lane >> 3) & 1) << 3);
                    uint32_t rr[4];
                    ldm_x4(rr, smem_u32(base + r * LD2 + cc));
                    b[t][np * 2][0] = rr[0];     b[t][np * 2][1] = rr[1];
                    b[t][np * 2 + 1][0] = rr[2]; b[t][np * 2 + 1][1] = rr[3];
                }
            }
#pragma unroll
            for (int mt = 0; mt < 4; mt++)
#pragma unroll
                for (int nt = 0; nt < 4; nt++) {
                    mma_bf16(acc[mt][nt], a[0][mt], b[0][nt]);
                    mma_bf16(acc[mt][nt], a[0][mt], b[1][nt]);
                    mma_bf16(acc[mt][nt], a[1][mt], b[0][nt]);
                }
        }
        __syncthreads();
    }

#pragma unroll
    for (int mt = 0; mt < 4; mt++) {
        const int row = rowBase + wm * 64 + mt * 16 + (lane >> 2);
#pragma unroll
        for (int nt = 0; nt < 4; nt++) {
            const int col = colBase + wn * 32 + nt * 8 + (lane & 3) * 2;
            float b0 = bias ? bias[col] : 0.f;
            float b1 = bias ? bias[col + 1] : 0.f;
            *(float2*)(C + (size_t)row * N + col) =
                make_float2(acc[mt][nt][0] + b0, acc[mt][nt][1] + b1);
            *(float2*)(C + (size_t)(row + 8) * N + col) =
                make_float2(acc[mt][nt][2] + b0, acc[mt][nt][3] + b1);
        }
    }
}

// =================== persistent fused scan: all 64 steps =====================
// Warp grid 4x2 (warp tile 32x32): 8 ldmatrix per 24 MMAs per chunk-half.
#define SLD    40
#define SATILE (128 * SLD)
#define SBTILE (64 * SLD)
#define SSTAGE (2 * SATILE + 2 * SBTILE)
#define SSM_BYTES (2 * SSTAGE * 2)     // 61440
#define SLDF   68
#define NCTA_SCAN 128

__device__ __forceinline__ float sigmoidf_(float x) { return 1.f / (1.f + expf(-x)); }

__global__ void __launch_bounds__(256)
mma_scan_persist(const float* __restrict__ actions,
                 const float* __restrict__ je_w,
                 const float* __restrict__ je_b)
{
    extern __shared__ bf16 ssm[];

    const int tid = threadIdx.x;
    const int wid = tid >> 5, lane = tid & 31;
    const int wm = wid & 3;        // 4 m-groups of 32 rows
    const int wn = wid >> 2;       // 2 n-groups of 32 cols
    const int rowBase = blockIdx.y * 128;
    const int colBase = blockIdx.x * 64;
    const int NC = Dd >> 5;   // 32

    const int dl = tid & 15;
    const int rg = tid >> 4;
    const int dg = (colBase >> 2) + dl;
    const float c0 = g_c[dg], c1 = g_c[Dd + dg], c2 = g_c[2 * Dd + dg];
    const float jb = je_b[dg];
    float m2r[8], m2z[8], m2n[8], jea[8];
#pragma unroll
    for (int j = 0; j < 8; j++) {
        m2r[j] = g_M2[(size_t)dg * 8 + j];
        m2z[j] = g_M2[(size_t)(Dd + dg) * 8 + j];
        m2n[j] = g_M2[(size_t)(2 * Dd + dg) * 8 + j];
        jea[j] = je_w[(size_t)dg * JEW_LD + Dd + j];
    }

    auto load = [&](int c, int st) {
        const int koff = c << 5;
        bf16* stp = ssm + st * SSTAGE;
#pragma unroll
        for (int tI = 0; tI < 2; tI++) {
            const bf16* src = tI ? g_hl : g_hh;
#pragma unroll
            for (int i = 0; i < 2; i++) {
                int u = tid * 2 + i;
                int row = u >> 2;
                int seg = (u & 3) << 3;
                cp16(smem_u32(stp + tI * SATILE + row * SLD + seg),
                     src + (size_t)(rowBase + row) * Dd + koff + seg);
            }
        }
#pragma unroll
        for (int tI = 0; tI < 2; tI++) {
            const bf16* src = tI ? g_wsl : g_wsh;
            int row = tid >> 2;
            int seg = (tid & 3) << 3;
            cp16(smem_u32(stp + 2 * SATILE + tI * SBTILE + row * SLD + seg),
                 src + (size_t)(colBase + row) * Dd + koff + seg);
        }
        cp_commit();
    };

    for (int t = 0; t < Tt; t++) {
        float acc[2][4][4];
#pragma unroll
        for (int i = 0; i < 2; i++)
#pragma unroll
            for (int j = 0; j < 4; j++)
#pragma unroll
                for (int k = 0; k < 4; k++) acc[i][j][k] = 0.f;

        load(0, 0);
        int st = 0;
        for (int c = 0; c < NC; c++) {
            const bool more = (c + 1) < NC;
            if (more) { load(c + 1, st ^ 1); cp_wait1(); }
            else      { cp_wait0(); }
            __syncthreads();

            const bf16* stp = ssm + st * SSTAGE;
#pragma unroll
            for (int kh = 0; kh < 2; kh++) {
                const int kcol = kh << 4;
                uint32_t a[2][2][4];
                uint32_t b[2][4][2];
#pragma unroll
                for (int tI = 0; tI < 2; tI++) {
                    const bf16* base = stp + tI * SATILE;
#pragma unroll
                    for (int mt = 0; mt < 2; mt++) {
                        int r = wm * 32 + mt * 16 + (lane & 15);
                        int cc = kcol + ((lane >> 4) << 3);
                        ldm_x4(a[tI][mt], smem_u32(base + r * SLD + cc));
                    }
                }
#pragma unroll
                for (int tI = 0; tI < 2; tI++) {
                    const bf16* base = stp + 2 * SATILE + tI * SBTILE;
#pragma unroll
                    for (int np = 0; np < 2; np++) {
                        int r = wn * 32 + (np * 2 + (lane >> 4)) * 8 + (lane & 7);
                        int cc = kcol + (((lane >> 3) & 1) << 3);
                        uint32_t rr[4];
                        ldm_x4(rr, smem_u32(base + r * SLD + cc));
                        b[tI][np * 2][0] = rr[0];     b[tI][np * 2][1] = rr[1];
                        b[tI][np * 2 + 1][0] = rr[2]; b[tI][np * 2 + 1][1] = rr[3];
                    }
                }
#pragma unroll
                for (int mt = 0; mt < 2; mt++)
#pragma unroll
                    for (int nt = 0; nt < 4; nt++) {
                        mma_bf16(acc[mt][nt], a[0][mt], b[0][nt]);
                        mma_bf16(acc[mt][nt], a[0][mt], b[1][nt]);
                        mma_bf16(acc[mt][nt], a[1][mt], b[0][nt]);
                    }
            }
            __syncthreads();
            st ^= 1;
        }

        float* smf = (float*)ssm;
#pragma unroll
        for (int mt = 0; mt < 2; mt++) {
            const int row = wm * 32 + mt * 16 + (lane >> 2);
#pragma unroll
            for (int nt = 0; nt < 4; nt++) {
                const int col = wn * 32 + nt * 8 + (lane & 3) * 2;
                smf[row * SLDF + col]     = acc[mt][nt][0];
                smf[row * SLDF + col + 1] = acc[mt][nt][1];
                smf[(row + 8) * SLDF + col]     = acc[mt][nt][2];
                smf[(row + 8) * SLDF + col + 1] = acc[mt][nt][3];
            }
        }
        __syncthreads();

        const bool lastStep = (t == Tt - 1);
#pragma unroll
        for (int r8 = 0; r8 < 8; r8++) {
            const int row = rg * 8 + r8;
            const int b = rowBase + row;
            const int trow = b * Tt + t;

            float4 G4 = *(float4*)&smf[row * SLDF + 4 * dl];
            float hr = G4.x + c0;
            float hz = G4.y + c1;
            float hn = G4.z + c2;
            float hj = G4.w + jb;

            const float* a = actions + (size_t)trow * Aa;
#pragma unroll
            for (int j = 0; j < 8; j++) {
                float av = a[j];
                hr = fmaf(av, m2r[j], hr);
                hz = fmaf(av, m2z[j], hz);
                hn = fmaf(av, m2n[j], hn);
                hj = fmaf(av, jea[j], hj);
            }

            const float* gi = g_gi + (size_t)trow * (3 * Dd);
            float r = sigmoidf_(gi[dg] + hr);
            float z = sigmoidf_(gi[Dd + dg] + hz);
            float n = tanhf(gi[2 * Dd + dg] + r * hn);
            float xv = g_x[(size_t)trow * Dd + dg];
            float hnew = (1.f - z) * n + z * hj + xv;

            const int oi = b * Dd + dg;
            if (lastStep) g_h[oi] = hnew;    // only final h is consumed (gumbel)
            bf16 hh = __float2bfloat16(hnew);
            g_hh[oi] = hh;
            g_hl[oi] = __float2bfloat16(hnew - __bfloat162float(hh));
        }

        __syncthreads();
        if (tid == 0) {
            __threadfence();
            atomicAdd(&g_bar_cnt, 1u);
            const unsigned target = (unsigned)(t + 1) * NCTA_SCAN;
            while (atomicAdd(&g_bar_cnt, 0u) < target) {}
            __threadfence();
        }
        __syncthreads();
    }
}

// =============== hi/lo conversion ============================================
__global__ void cvt_hl(const float* __restrict__ X, bf16* __restrict__ Xh,
                       bf16* __restrict__ Xl, int n4)
{
    int i = blockIdx.x * blockDim.x + threadIdx.x;
    if (i >= n4) return;
    float4 v = ((const float4*)X)[i];
    bf16 h0 = __float2bfloat16(v.x), h1 = __float2bfloat16(v.y);
    bf16 h2 = __float2bfloat16(v.z), h3 = __float2bfloat16(v.w);
    float l0 = v.x - __bfloat162float(h0), l1 = v.y - __bfloat162float(h1);
    float l2 = v.z - __bfloat162float(h2), l3 = v.w - __bfloat162float(h3);
    __nv_bfloat162* H = (__nv_bfloat162*)Xh;
    __nv_bfloat162* L = (__nv_bfloat162*)Xl;
    H[2 * i]     = __nv_bfloat162(h0, h1);
    H[2 * i + 1] = __nv_bfloat162(h2, h3);
    L[2 * i]     = __nv_bfloat162(__float2bfloat16(l0), __float2bfloat16(l1));
    L[2 * i + 1] = __nv_bfloat162(__float2bfloat16(l2), __float2bfloat16(l3));
}

// permuted cvt of W_scan: new row 4d+comp <- old row comp*1024+d / 3072+d
__global__ void cvt_hl_perm_ws()
{
    int i = blockIdx.x * blockDim.x + threadIdx.x;
    if (i >= 4 * Dd * Dd / 4) return;
    int flat = i * 4;
    int nrow = flat >> 10;
    int k = flat & 1023;
    int d = nrow >> 2, comp = nrow & 3;
    int orow = (comp < 3) ? comp * Dd + d : 3 * Dd + d;
    float4 v = *(const float4*)&g_wscan[(size_t)orow * Dd + k];
    bf16 h0 = __float2bfloat16(v.x), h1 = __float2bfloat16(v.y);
    bf16 h2 = __float2bfloat16(v.z), h3 = __float2bfloat16(v.w);
    __nv_bfloat162* H = (__nv_bfloat162*)g_wsh;
    __nv_bfloat162* L = (__nv_bfloat162*)g_wsl;
    H[2*i]   = __nv_bfloat162(h0, h1);
    H[2*i+1] = __nv_bfloat162(h2, h3);
    L[2*i]   = __nv_bfloat162(__float2bfloat16(v.x - __bfloat162float(h0)),
                              __float2bfloat16(v.y - __bfloat162float(h1)));
    L[2*i+1] = __nv_bfloat162(__float2bfloat16(v.z - __bfloat162float(h2)),
                              __float2bfloat16(v.w - __bfloat162float(h3)));
}

// =============== SIMT GEMM (precompute only) ==================================
#define BKd 8
__global__ void __launch_bounds__(256)
sgemm_ab(const float* __restrict__ A, const float* __restrict__ Bm,
         float* __restrict__ C, int M, int N, int K, int lda, int ldb, int ldc)
{
    __shared__ float As[BKd][128];
    __shared__ float Bs[BKd][128];
    const int tid = threadIdx.x;
    const int tx = tid & 15, ty = tid >> 4;
    const int rowBase = blockIdx.y * 128, colBase = blockIdx.x * 128;
    const int lrA = tid >> 1, lcA = (tid & 1) * 4;
    const int kkB = tid >> 5, c4B = (tid & 31) * 4;
    const float* Aptr = A + (size_t)(rowBase + lrA) * lda + lcA;
    const float* Bptr = Bm + (size_t)kkB * ldb + colBase + c4B;
    float acc[8][8];
#pragma unroll
    for (int i = 0; i < 8; i++)
#pragma unroll
        for (int j = 0; j < 8; j++) acc[i][j] = 0.f;
    for (int k0 = 0; k0 < K; k0 += BKd) {
        float4 av = *(const float4*)(Aptr + k0);
        float4 bv = *(const float4*)(Bptr + (size_t)k0 * ldb);
        As[lcA+0][lrA]=av.x; As[lcA+1][lrA]=av.y;
        As[lcA+2][lrA]=av.z; As[lcA+3][lrA]=av.w;
        *(float4*)&Bs[kkB][c4B] = bv;
        __syncthreads();
#pragma unroll
        for (int kk = 0; kk < BKd; kk++) {
            float a[8], b[8];
#pragma unroll
            for (int i = 0; i < 8; i++) a[i] = As[kk][ty*8+i];
#pragma unroll
            for (int j = 0; j < 8; j++) b[j] = Bs[kk][tx*8+j];
#pragma unroll
            for (int i = 0; i < 8; i++)
#pragma unroll
                for (int j = 0; j < 8; j++)
                    acc[i][j] = fmaf(a[i], b[j], acc[i][j]);
        }
        __syncthreads();
    }
#pragma unroll
    for (int i = 0; i < 8; i++) {
        const int r = rowBase + ty * 8 + i;
#pragma unroll
        for (int j = 0; j < 8; j++)
            C[(size_t)r * ldc + colBase + tx * 8 + j] = acc[i][j];
    }
}

__global__ void copy_jew(const float* __restrict__ je_w)
{
    int idx = blockIdx.x * blockDim.x + threadIdx.x;
    if (idx >= Dd * Dd) return;
    int j = idx >> 10, k = idx & 1023;
    g_wscan[(size_t)(3 * Dd + j) * Dd + k] = je_w[(size_t)j * JEW_LD + k];
}

__global__ void __launch_bounds__(128)
m2c_k(const float* __restrict__ whh, const float* __restrict__ je_w,
      const float* __restrict__ je_b, const float* __restrict__ bhh)
{
    const int i = blockIdx.x;
    const int t = threadIdx.x;
    float acc[9];
#pragma unroll
    for (int j = 0; j < 9; j++) acc[j] = 0.f;
    for (int k = t; k < Dd; k += 128) {
        float w = whh[(size_t)i * Dd + k];
        const float* jr = je_w + (size_t)k * JEW_LD + Dd;
#pragma unroll
        for (int j = 0; j < 8; j++) acc[j] = fmaf(w, jr[j], acc[j]);
        acc[8] = fmaf(w, je_b[k], acc[8]);
    }
    __shared__ float sh[9][128];
#pragma unroll
    for (int j = 0; j < 9; j++) sh[j][t] = acc[j];
    __syncthreads();
    for (int s = 64; s > 0; s >>= 1) {
        if (t < s)
#pragma unroll
            for (int j = 0; j < 9; j++) sh[j][t] += sh[j][t + s];
        __syncthreads();
    }
    if (t == 0) {
#pragma unroll
        for (int j = 0; j < 8; j++) g_M2[i * 8 + j] = sh[j][0];
        g_c[i] = sh[8][0] + bhh[i];
    }
}

// ---------------- batch stats + BN ------------------------------------------
__global__ void col_stats(const float* __restrict__ X, int M, int N,
                          float* __restrict__ mean, float* __restrict__ var)
{
    const int c = blockIdx.x * 32 + threadIdx.x;
    const int ry = threadIdx.y;
    float s = 0.f, s2 = 0.f;
    for (int r = ry; r < M; r += 8) {
        float v = X[(size_t)r * N + c];
        s += v; s2 += v * v;
    }
    __shared__ float sh[8][32], sh2[8][32];
    sh[ry][threadIdx.x] = s; sh2[ry][threadIdx.x] = s2;
    __syncthreads();
    if (ry == 0) {
#pragma unroll
        for (int y = 1; y < 8; y++) { s += sh[y][threadIdx.x]; s2 += sh2[y][threadIdx.x]; }
        float m = s / (float)M;
        mean[c] = m;
        var[c]  = s2 / (float)M - m * m;
    }
}

__global__ void bn_apply(const float* __restrict__ X, float* __restrict__ Y,
                         const float* __restrict__ mean, const float* __restrict__ var,
                         const float* __restrict__ g, const float* __restrict__ beta,
                         int total, int N, int relu)
{
    int idx = blockIdx.x * blockDim.x + threadIdx.x;
    if (idx >= total) return;
    int c = idx % N;
    float v = g[c] * (X[idx] - mean[c]) * rsqrtf(var[c] + EPSf) + beta[c];
    if (relu) v = fmaxf(v, 0.f);
    Y[idx] = v;
}

__global__ void bn_apply_cvt(const float* __restrict__ X, float* __restrict__ Yf,
                             bf16* __restrict__ Yh, bf16* __restrict__ Yl,
                             const float* __restrict__ mean, const float* __restrict__ var,
                             const float* __restrict__ g, const float* __restrict__ beta,
                             int total4, int N, int relu)
{
    int i = blockIdx.x * blockDim.x + threadIdx.x;
    if (i >= total4) return;
    int c0 = (i * 4) % N;
    float4 v = ((const float4*)X)[i];
    float o[4] = { v.x, v.y, v.z, v.w };
#pragma unroll
    for (int j = 0; j < 4; j++) {
        int c = c0 + j;
        float t = g[c] * (o[j] - mean[c]) * rsqrtf(var[c] + EPSf) + beta[c];
        if (relu) t = fmaxf(t, 0.f);
        o[j] = t;
    }
    if (Yf) ((float4*)Yf)[i] = make_float4(o[0], o[1], o[2], o[3]);
    bf16 h0 = __float2bfloat16(o[0]), h1 = __float2bfloat16(o[1]);
    bf16 h2 = __float2bfloat16(o[2]), h3 = __float2bfloat16(o[3]);
    __nv_bfloat162* H = (__nv_bfloat162*)Yh;
    __nv_bfloat162* L = (__nv_bfloat162*)Yl;
    H[2*i]   = __nv_bfloat162(h0, h1);
    H[2*i+1] = __nv_bfloat162(h2, h3);
    L[2*i]   = __nv_bfloat162(__float2bfloat16(o[0] - __bfloat162float(h0)),
                              __float2bfloat16(o[1] - __bfloat162float(h1)));
    L[2*i+1] = __nv_bfloat162(__float2bfloat16(o[2] - __bfloat162float(h2)),
                              __float2bfloat16(o[3] - __bfloat162float(h3)));
}

// ---------------- misc ------------------------------------------------------
__global__ void zero_h() {
    int idx = blockIdx.x * blockDim.x + threadIdx.x;
    if (idx == 0) g_bar_cnt = 0u;
    if (idx < Bb * Dd) {
        g_h[idx] = 0.f;
        g_hh[idx] = __float2bfloat16(0.f);
        g_hl[idx] = __float2bfloat16(0.f);
    }
}

// ---------------- threefry2x32-20 (JAX partitionable) ------------------------
__device__ __forceinline__ uint32_t rotl32_(uint32_t x, int r) {
    return (x << r) | (x >> (32 - r));
}
__device__ __forceinline__ void threefry2x32_(uint32_t k0, uint32_t k1,
                                              uint32_t& x0, uint32_t& x1)
{
    const uint32_t k2 = k0 ^ k1 ^ 0x1BD11BDAu;
    x0 += k0; x1 += k1;
#define TF_R4(a,b,c,d) \
    x0 += x1; x1 = rotl32_(x1, a); x1 ^= x0; \
    x0 += x1; x1 = rotl32_(x1, b); x1 ^= x0; \
    x0 += x1; x1 = rotl32_(x1, c); x1 ^= x0; \
    x0 += x1; x1 = rotl32_(x1, d); x1 ^= x0;
    TF_R4(13,15,26,6)  x0 += k1; x1 += k2 + 1u;
    TF_R4(17,29,16,24) x0 += k2; x1 += k0 + 2u;
    TF_R4(13,15,26,6)  x0 += k0; x1 += k1 + 3u;
    TF_R4(17,29,16,24) x0 += k1; x1 += k2 + 4u;
    TF_R4(13,15,26,6)  x0 += k2; x1 += k0 + 5u;
#undef TF_R4
}

__global__ void gumbel_softmax_k(float* __restrict__ out)
{
    const int bl = blockIdx.x;
    const int d  = threadIdx.x;
    const int i  = bl * ZDn + d;
    const float logit = g_h[i];

    uint32_t c0 = 0u;
    uint32_t c1 = (uint32_t)i;
    threefry2x32_(0u, 42u, c0, c1);
    const uint32_t bits = c0 ^ c1;
    float f = __uint_as_float((bits >> 9) | 0x3f800000u) - 1.0f;
    const float tiny = 1.1754943508222875e-38f;
    float u = fmaxf(f * (1.0f - tiny) + tiny, tiny);
    float gum = -logf(-logf(u));

    float v = logit + gum;

    __shared__ float red[ZDn];
    red[d] = v; __syncthreads();
    for (int s = ZDn / 2; s > 0; s >>= 1) {
        if (d < s) red[d] = fmaxf(red[d], red[d + s]);
        __syncthreads();
    }
    float mx = red[0];
    __syncthreads();
    float e = expf(v - mx);
    red[d] = e; __syncthreads();
    for (int s = ZDn / 2; s > 0; s >>= 1) {
        if (d < s) red[d] += red[d + s];
        __syncthreads();
    }
    float z = e / red[0];

    out[i] = logit;
    out[Bb * ZLn * ZDn + i] = z;
    bf16 zh = __float2bfloat16(z);
    g_zh[i] = zh;
    g_zl[i] = __float2bfloat16(z - __bfloat162float(zh));
}

// ---------------- launch ------------------------------------------------------
static inline float* symf(const void* s) {
    void* p = nullptr;
    cudaGetSymbolAddress(&p, s);
    return (float*)p;
}
static inline bf16* symb(const void* s) {
    void* p = nullptr;
    cudaGetSymbolAddress(&p, s);
    return (bf16*)p;
}

extern "C" void kernel_launch(void* const* d_in, const int* in_sizes, int n_in,
                              void* d_out, int out_size)
{
    (void)in_sizes; (void)n_in; (void)out_size;
    const float* obs      = (const float*)d_in[0];
    const float* actions  = (const float*)d_in[1];
    const float* enc_w1   = (const float*)d_in[2];
    const float* enc_b1   = (const float*)d_in[3];
    const float* enc_g1   = (const float*)d_in[4];
    const float* enc_bt1  = (const float*)d_in[5];
    const float* enc_w2   = (const float*)d_in[6];
    const float* enc_b2   = (const float*)d_in[7];
    const float* enc_g2   = (const float*)d_in[8];
    const float* enc_bt2  = (const float*)d_in[9];
    const float* je_w     = (const float*)d_in[10];
    const float* je_b     = (const float*)d_in[11];
    const float* gru_wih  = (const float*)d_in[12];
    const float* gru_bih  = (const float*)d_in[13];
    const float* gru_whh  = (const float*)d_in[14];
    const float* gru_bhh  = (const float*)d_in[15];
    const float* dec_w1   = (const float*)d_in[16];
    const float* dec_b1   = (const float*)d_in[17];
    const float* dec_g1   = (const float*)d_in[18];
    const float* dec_bt1  = (const float*)d_in[19];
    const float* dec_w2   = (const float*)d_in[20];
    const float* dec_b2   = (const float*)d_in[21];
    const float* dec_g2   = (const float*)d_in[22];
    const float* dec_bt2  = (const float*)d_in[23];
    float* out = (float*)d_out;

    float* p_h1 = symf(g_h1);
    float* p_x  = symf(g_x);
    float* p_gi = symf(g_gi);
    float* p_d1 = symf(g_d1);
    float* p_d2 = symf(g_d2);
    float* p_m  = symf(g_mean);
    float* p_v  = symf(g_var);
    float* p_ws = symf(g_wscan);

    bf16 *p_obsh = symb(g_obsh), *p_obsl = symb(g_obsl);
    bf16 *p_w1h = symb(g_w1h), *p_w1l = symb(g_w1l);
    bf16 *p_h1h = symb(g_h1h), *p_h1l = symb(g_h1l);
    bf16 *p_w2h = symb(g_w2h), *p_w2l = symb(g_w2l);
    bf16 *p_xh = symb(g_xh), *p_xl = symb(g_xl);
    bf16 *p_wihh = symb(g_wihh), *p_wihl = symb(g_wihl);
    bf16 *p_zh = symb(g_zh), *p_zl = symb(g_zl);
    bf16 *p_d1h = symb(g_d1h), *p_d1l = symb(g_d1l);
    bf16 *p_dw1h = symb(g_dw1h), *p_dw1l = symb(g_dw1l);
    bf16 *p_dw2h = symb(g_dw2h), *p_dw2l = symb(g_dw2l);

    // one-time resources (host-side; no device memory involved)
    static cudaStream_t sSide = nullptr;
    static cudaEvent_t evFork = nullptr, evJoin = nullptr;
    static bool attrDone = false;
    if (!attrDone) {
        cudaFuncSetAttribute(mma_gemm, cudaFuncAttributeMaxDynamicSharedMemorySize, SM3_BYTES);
        cudaFuncSetAttribute(mma_scan_persist, cudaFuncAttributeMaxDynamicSharedMemorySize, SSM_BYTES);
        cudaStreamCreateWithFlags(&sSide, cudaStreamNonBlocking);
        cudaEventCreateWithFlags(&evFork, cudaEventDisableTiming);
        cudaEventCreateWithFlags(&evJoin, cudaEventDisableTiming);
        attrDone = true;
    }

    dim3 blk(256);
    dim3 statsBlk(32, 8);

    // ================== FORK: side stream does setup work =====================
    cudaEventRecord(evFork, 0);
    cudaStreamWaitEvent(sSide, evFork, 0);

    cvt_hl<<<(Dd * Hh / 4 + 255) / 256, blk, 0, sSide>>>(enc_w2, p_w2h, p_w2l, Dd * Hh / 4);
    cvt_hl<<<(3 * Dd * Dd / 4 + 255) / 256, blk, 0, sSide>>>(gru_wih, p_wihh, p_wihl, 3 * Dd * Dd / 4);
    cvt_hl<<<(Hh * Dd / 4 + 255) / 256, blk, 0, sSide>>>(dec_w1, p_dw1h, p_dw1l, Hh * Dd / 4);
    cvt_hl<<<(OBSn * Hh / 4 + 255) / 256, blk, 0, sSide>>>(dec_w2, p_dw2h, p_dw2l, OBSn * Hh / 4);
    {
        dim3 grid(Dd / 128, 3 * Dd / 128);
        sgemm_ab<<<grid, blk, 0, sSide>>>(gru_whh, je_w, p_ws, 3 * Dd, Dd, Dd, Dd, JEW_LD, Dd);
        copy_jew<<<(Dd * Dd + 255) / 256, blk, 0, sSide>>>(je_w);
        m2c_k<<<3 * Dd, 128, 0, sSide>>>(gru_whh, je_w, je_b, gru_bhh);
        cvt_hl_perm_ws<<<(4 * Dd * Dd / 4 + 255) / 256, blk, 0, sSide>>>();
    }
    zero_h<<<(Bb * Dd + 255) / 256, blk, 0, sSide>>>();
    cudaEventRecord(evJoin, sSide);

    // main chain: obs/w1 cvt -> enc1
    cvt_hl<<<(BT * OBSn / 4 + 255) / 256, blk>>>(obs, p_obsh, p_obsl, BT * OBSn / 4);
    cvt_hl<<<(Hh * OBSn / 4 + 255) / 256, blk>>>(enc_w1, p_w1h, p_w1l, Hh * OBSn / 4);

    // ---- encoder layer 1 (HMMA) ----
    {
        dim3 grid(Hh / 128, BT / 128);
        mma_gemm<<<grid, blk, SM3_BYTES>>>(p_obsh, p_obsl, p_w1h, p_w1l, enc_b1, p_h1,
                                           BT, Hh, OBSn);
        col_stats<<<Hh / 32, statsBlk>>>(p_h1, BT, Hh, p_m, p_v);
        bn_apply_cvt<<<(BT * Hh / 4 + 255) / 256, blk>>>(p_h1, nullptr, p_h1h, p_h1l,
                                                         p_m, p_v, enc_g1, enc_bt1,
                                                         BT * Hh / 4, Hh, 1);
    }

    // ================== JOIN ==================================================
    cudaStreamWaitEvent(0, evJoin, 0);

    // ---- encoder layer 2 (HMMA) ----
    {
        dim3 grid(Dd / 128, BT / 128);
        mma_gemm<<<grid, blk, SM3_BYTES>>>(p_h1h, p_h1l, p_w2h, p_w2l, enc_b2, p_x,
                                           BT, Dd, Hh);
        col_stats<<<Dd / 32, statsBlk>>>(p_x, BT, Dd, p_m, p_v);
        bn_apply_cvt<<<(BT * Dd / 4 + 255) / 256, blk>>>(p_x, p_x, p_xh, p_xl,
                                                         p_m, p_v, enc_g2, enc_bt2,
                                                         BT * Dd / 4, Dd, 0);
    }
    // ---- gi (HMMA) ----
    {
        dim3 grid(3 * Dd / 128, BT / 128);
        mma_gemm<<<grid, blk, SM3_BYTES>>>(p_xh, p_xl, p_wihh, p_wihl, gru_bih, p_gi,
                                           BT, 3 * Dd, Dd);
    }
    // ---- recurrent scan: ONE persistent kernel (all 64 steps) ----
    {
        dim3 gridS(4 * Dd / 64, Bb / 128);   // (64, 2) = 128 CTAs, all resident
        mma_scan_persist<<<gridS, blk, SSM_BYTES>>>(actions, je_w, je_b);
    }
    // ---- gumbel softmax ----
    gumbel_softmax_k<<<Bb * ZLn, ZDn>>>(out);
    // ---- decoder layer 1 (HMMA) ----
    {
        dim3 grid(Hh / 128, Bb / 128);
        mma_gemm<<<grid, blk, SM3_BYTES>>>(p_zh, p_zl, p_dw1h, p_dw1l, dec_b1, p_d1,
                                           Bb, Hh, Dd);
        col_stats<<<Hh / 32, statsBlk>>>(p_d1, Bb, Hh, p_m, p_v);
        bn_apply_cvt<<<(Bb * Hh / 4 + 255) / 256, blk>>>(p_d1, nullptr, p_d1h, p_d1l,
                                                         p_m, p_v, dec_g1, dec_bt1,
                                                         Bb * Hh / 4, Hh, 1);
    }
    // ---- decoder layer 2 (HMMA) -> x_hat ----
    {
        dim3 grid(OBSn / 128, Bb / 128);
        mma_gemm<<<grid, blk, SM3_BYTES>>>(p_d1h, p_d1l, p_dw2h, p_dw2l, dec_b2, p_d2,
                                           Bb, OBSn, Hh);
        col_stats<<<OBSn / 32, statsBlk>>>(p_d2, Bb, OBSn, p_m, p_v);
        int total = Bb * OBSn;
        bn_apply<<<(total + 255) / 256, blk>>>(p_d2, out + 2 * Bb * ZLn * ZDn,
                                               p_m, p_v, dec_g2, dec_bt2, total, OBSn, 0);
    }
}

// round 12
// speedup vs baseline: 2.1218x; 1.2910x over previous
#include <cuda_runtime.h>
#include <cuda_bf16.h>
#include <cuda_fp16.h>
#include <cstdint>

#define Bb   256
#define Tt   64
#define OBSn 4096
#define Dd   1024
#define Aa   8
#define Hh   2048
#define ZLn  4
#define ZDn  256
#define BT   (Bb*Tt)          // 16384
#define EPSf 1e-5f
#define JEW_LD (Dd + Aa)      // 1032

typedef __nv_bfloat16 bf16;
typedef __half f16;

// ---------------- scratch (static device globals; no allocation) -------------
__device__ float g_h1[BT * Hh];
__device__ float g_x [BT * Dd];
__device__ float g_gi[BT * 3 * Dd];
__device__ float g_h [Bb * Dd];
__device__ float g_d1[Bb * Hh];
__device__ float g_d2[Bb * OBSn];
__device__ float g_mean[4096];
__device__ float g_var [4096];
__device__ float g_wscan[4 * Dd * Dd];
__device__ float g_M2[3 * Dd * Aa];
__device__ float g_c [3 * Dd];
__device__ unsigned g_bar_cnt;

// fp16 buffers (feed-forward path): activations 2-digit, weights 1-digit
__device__ f16 g_obsH[BT * OBSn], g_obsL[BT * OBSn];
__device__ f16 g_w1  [Hh * OBSn];
__device__ f16 g_h1H [BT * Hh],   g_h1L [BT * Hh];
__device__ f16 g_w2  [Dd * Hh];
__device__ f16 g_xH  [BT * Dd],   g_xL  [BT * Dd];
__device__ f16 g_wih [3 * Dd * Dd];
__device__ f16 g_zH  [Bb * Dd],   g_zL  [Bb * Dd];
__device__ f16 g_d1H [Bb * Hh],   g_d1L [Bb * Hh];
__device__ f16 g_dw1 [Hh * Dd];
__device__ f16 g_dw2 [OBSn * Hh];

// bf16 buffers (scan path; 3-term split retained)
__device__ bf16 g_wsh [4 * Dd * Dd], g_wsl [4 * Dd * Dd];  // PERMUTED rows 4d+comp
__device__ bf16 g_hh  [Bb * Dd],   g_hl  [Bb * Dd];

// ======================= PTX helpers =========================================
__device__ __forceinline__ uint32_t smem_u32(const void* p) {
    uint32_t a;
    asm("{ .reg .u64 t; cvta.to.shared.u64 t, %1; cvt.u32.u64 %0, t; }"
        : "=r"(a) : "l"(p));
    return a;
}
__device__ __forceinline__ void cp16(uint32_t s, const void* g) {
    asm volatile("cp.async.cg.shared.global [%0], [%1], 16;" :: "r"(s), "l"(g));
}
__device__ __forceinline__ void cp_commit() {
    asm volatile("cp.async.commit_group;" ::: "memory");
}
__device__ __forceinline__ void cp_wait0() {
    asm volatile("cp.async.wait_group 0;" ::: "memory");
}
__device__ __forceinline__ void cp_wait1() {
    asm volatile("cp.async.wait_group 1;" ::: "memory");
}
__device__ __forceinline__ void cp_wait2() {
    asm volatile("cp.async.wait_group 2;" ::: "memory");
}
__device__ __forceinline__ void ldm_x4(uint32_t* r, uint32_t a) {
    asm volatile("ldmatrix.sync.aligned.m8n8.x4.shared.b16 {%0,%1,%2,%3}, [%4];"
                 : "=r"(r[0]), "=r"(r[1]), "=r"(r[2]), "=r"(r[3]) : "r"(a));
}
__device__ __forceinline__ void mma_bf16(float* c, const uint32_t* a, const uint32_t* b) {
    asm volatile("mma.sync.aligned.m16n8k16.row.col.f32.bf16.bf16.f32 "
                 "{%0,%1,%2,%3}, {%4,%5,%6,%7}, {%8,%9}, {%0,%1,%2,%3};"
                 : "+f"(c[0]), "+f"(c[1]), "+f"(c[2]), "+f"(c[3])
                 : "r"(a[0]), "r"(a[1]), "r"(a[2]), "r"(a[3]),
                   "r"(b[0]), "r"(b[1]));
}
__device__ __forceinline__ void mma_f16(float* c, const uint32_t* a, const uint32_t* b) {
    asm volatile("mma.sync.aligned.m16n8k16.row.col.f32.f16.f16.f32 "
                 "{%0,%1,%2,%3}, {%4,%5,%6,%7}, {%8,%9}, {%0,%1,%2,%3};"
                 : "+f"(c[0]), "+f"(c[1]), "+f"(c[2]), "+f"(c[3])
                 : "r"(a[0]), "r"(a[1]), "r"(a[2]), "r"(a[3]),
                   "r"(b[0]), "r"(b[1]));
}

// ============ fp16 2-term GEMM: C = (Ah+Al) @ Bh^T (+bias), 3-stage ==========
// Ah/Al: MxK fp16 (ld=K); Bh: NxK fp16; C: MxN fp32.
// M%128==0, N%128==0, K%32==0. Grid (N/128, M/128), 256 threads.
#define LD2   40
#define TILE2 (128 * LD2)
#define STG16 (3 * TILE2)              // Ah, Al, Bh
#define SM16_BYTES (3 * STG16 * 2)     // 92160

__global__ void __launch_bounds__(256)
mma_gemm16(const f16* __restrict__ Ah, const f16* __restrict__ Al,
           const f16* __restrict__ Bh,
           const float* __restrict__ bias, float* __restrict__ C,
           int M, int N, int K)
{
    extern __shared__ f16 smh[];

    const int tid = threadIdx.x;
    const int wid = tid >> 5, lane = tid & 31;
    const int wm = wid >> 2, wn = wid & 3;
    const int rowBase = blockIdx.y * 128, colBase = blockIdx.x * 128;
    const int NC = K >> 5;

    float acc[4][4][4];
#pragma unroll
    for (int i = 0; i < 4; i++)
#pragma unroll
        for (int j = 0; j < 4; j++)
#pragma unroll
            for (int k = 0; k < 4; k++) acc[i][j][k] = 0.f;

    const f16* srcs[3] = { Ah, Al, Bh };
    const int  rbs [3] = { rowBase, rowBase, colBase };

    auto load = [&](int c, int st) {
        const int koff = c << 5;
        f16* stp = smh + st * STG16;
#pragma unroll
        for (int tI = 0; tI < 3; tI++) {
#pragma unroll
            for (int i = 0; i < 2; i++) {
                int u = tid * 2 + i;
                int row = u >> 2;
                int seg = (u & 3) << 3;
                cp16(smem_u32(stp + tI * TILE2 + row * LD2 + seg),
                     srcs[tI] + (size_t)(rbs[tI] + row) * K + koff + seg);
            }
        }
        cp_commit();
    };

    load(0, 0);
    load(1, 1);
    for (int c = 0; c < NC; c++) {
        const int st = c % 3;
        if (c + 2 < NC) { load(c + 2, (c + 2) % 3); cp_wait2(); }
        else if (c + 1 < NC) cp_wait1();
        else cp_wait0();
        __syncthreads();

        const f16* stp = smh + st * STG16;
#pragma unroll
        for (int kh = 0; kh < 2; kh++) {
            const int kcol = kh << 4;
            uint32_t a[2][4][4];
            uint32_t b[4][2];
#pragma unroll
            for (int t = 0; t < 2; t++) {
                const f16* base = stp + t * TILE2;
#pragma unroll
                for (int mt = 0; mt < 4; mt++) {
                    int r = wm * 64 + mt * 16 + (lane & 15);
                    int cc = kcol + ((lane >> 4) << 3);
                    ldm_x4(a[t][mt], smem_u32(base + r * LD2 + cc));
                }
            }
            {
                const f16* base = stp + 2 * TILE2;
#pragma unroll
                for (int np = 0; np < 2; np++) {
                    int r = wn * 32 + (np * 2 + (lane >> 4)) * 8 + (lane & 7);
                    int cc = kcol + (((lane >> 3) & 1) << 3);
                    uint32_t rr[4];
                    ldm_x4(rr, smem_u32(base + r * LD2 + cc));
                    b[np * 2][0] = rr[0];     b[np * 2][1] = rr[1];
                    b[np * 2 + 1][0] = rr[2]; b[np * 2 + 1][1] = rr[3];
                }
            }
#pragma unroll
            for (int mt = 0; mt < 4; mt++)
#pragma unroll
                for (int nt = 0; nt < 4; nt++) {
                    mma_f16(acc[mt][nt], a[0][mt], b[nt]);
                    mma_f16(acc[mt][nt], a[1][mt], b[nt]);
                }
        }
        __syncthreads();
    }

#pragma unroll
    for (int mt = 0; mt < 4; mt++) {
        const int row = rowBase + wm * 64 + mt * 16 + (lane >> 2);
#pragma unroll
        for (int nt = 0; nt < 4; nt++) {
            const int col = colBase + wn * 32 + nt * 8 + (lane & 3) * 2;
            float b0 = bias ? bias[col] : 0.f;
            float b1 = bias ? bias[col + 1] : 0.f;
            *(float2*)(C + (size_t)row * N + col) =
                make_float2(acc[mt][nt][0] + b0, acc[mt][nt][1] + b1);
            *(float2*)(C + (size_t)(row + 8) * N + col) =
                make_float2(acc[mt][nt][2] + b0, acc[mt][nt][3] + b1);
        }
    }
}

// =================== persistent fused scan (bf16 3-term, unchanged) ==========
#define SLD    40
#define SATILE (128 * SLD)
#define SBTILE (64 * SLD)
#define SSTAGE (2 * SATILE + 2 * SBTILE)
#define SSM_BYTES (2 * SSTAGE * 2)     // 61440
#define SLDF   68
#define NCTA_SCAN 128

__device__ __forceinline__ float sigmoidf_(float x) { return 1.f / (1.f + expf(-x)); }

__global__ void __launch_bounds__(256)
mma_scan_persist(const float* __restrict__ actions,
                 const float* __restrict__ je_w,
                 const float* __restrict__ je_b)
{
    extern __shared__ bf16 ssm[];

    const int tid = threadIdx.x;
    const int wid = tid >> 5, lane = tid & 31;
    const int wm = wid & 3;        // 4 m-groups of 32 rows
    const int wn = wid >> 2;       // 2 n-groups of 32 cols
    const int rowBase = blockIdx.y * 128;
    const int colBase = blockIdx.x * 64;
    const int NC = Dd >> 5;   // 32

    const int dl = tid & 15;
    const int rg = tid >> 4;
    const int dg = (colBase >> 2) + dl;
    const float c0 = g_c[dg], c1 = g_c[Dd + dg], c2 = g_c[2 * Dd + dg];
    const float jb = je_b[dg];
    float m2r[8], m2z[8], m2n[8], jea[8];
#pragma unroll
    for (int j = 0; j < 8; j++) {
        m2r[j] = g_M2[(size_t)dg * 8 + j];
        m2z[j] = g_M2[(size_t)(Dd + dg) * 8 + j];
        m2n[j] = g_M2[(size_t)(2 * Dd + dg) * 8 + j];
        jea[j] = je_w[(size_t)dg * JEW_LD + Dd + j];
    }

    auto load = [&](int c, int st) {
        const int koff = c << 5;
        bf16* stp = ssm + st * SSTAGE;
#pragma unroll
        for (int tI = 0; tI < 2; tI++) {
            const bf16* src = tI ? g_hl : g_hh;
#pragma unroll
            for (int i = 0; i < 2; i++) {
                int u = tid * 2 + i;
                int row = u >> 2;
                int seg = (u & 3) << 3;
                cp16(smem_u32(stp + tI * SATILE + row * SLD + seg),
                     src + (size_t)(rowBase + row) * Dd + koff + seg);
            }
        }
#pragma unroll
        for (int tI = 0; tI < 2; tI++) {
            const bf16* src = tI ? g_wsl : g_wsh;
            int row = tid >> 2;
            int seg = (tid & 3) << 3;
            cp16(smem_u32(stp + 2 * SATILE + tI * SBTILE + row * SLD + seg),
                 src + (size_t)(colBase + row) * Dd + koff + seg);
        }
        cp_commit();
    };

    for (int t = 0; t < Tt; t++) {
        float acc[2][4][4];
#pragma unroll
        for (int i = 0; i < 2; i++)
#pragma unroll
            for (int j = 0; j < 4; j++)
#pragma unroll
                for (int k = 0; k < 4; k++) acc[i][j][k] = 0.f;

        load(0, 0);
        int st = 0;
        for (int c = 0; c < NC; c++) {
            const bool more = (c + 1) < NC;
            if (more) { load(c + 1, st ^ 1); cp_wait1(); }
            else      { cp_wait0(); }
            __syncthreads();

            const bf16* stp = ssm + st * SSTAGE;
#pragma unroll
            for (int kh = 0; kh < 2; kh++) {
                const int kcol = kh << 4;
                uint32_t a[2][2][4];
                uint32_t b[2][4][2];
#pragma unroll
                for (int tI = 0; tI < 2; tI++) {
                    const bf16* base = stp + tI * SATILE;
#pragma unroll
                    for (int mt = 0; mt < 2; mt++) {
                        int r = wm * 32 + mt * 16 + (lane & 15);
                        int cc = kcol + ((lane >> 4) << 3);
                        ldm_x4(a[tI][mt], smem_u32(base + r * SLD + cc));
                    }
                }
#pragma unroll
                for (int tI = 0; tI < 2; tI++) {
                    const bf16* base = stp + 2 * SATILE + tI * SBTILE;
#pragma unroll
                    for (int np = 0; np < 2; np++) {
                        int r = wn * 32 + (np * 2 + (lane >> 4)) * 8 + (lane & 7);
                        int cc = kcol + (((lane >> 3) & 1) << 3);
                        uint32_t rr[4];
                        ldm_x4(rr, smem_u32(base + r * SLD + cc));
                        b[tI][np * 2][0] = rr[0];     b[tI][np * 2][1] = rr[1];
                        b[tI][np * 2 + 1][0] = rr[2]; b[tI][np * 2 + 1][1] = rr[3];
                    }
                }
#pragma unroll
                for (int mt = 0; mt < 2; mt++)
#pragma unroll
                    for (int nt = 0; nt < 4; nt++) {
                        mma_bf16(acc[mt][nt], a[0][mt], b[0][nt]);
                        mma_bf16(acc[mt][nt], a[0][mt], b[1][nt]);
                        mma_bf16(acc[mt][nt], a[1][mt], b[0][nt]);
                    }
            }
            __syncthreads();
            st ^= 1;
        }

        float* smf = (float*)ssm;
#pragma unroll
        for (int mt = 0; mt < 2; mt++) {
            const int row = wm * 32 + mt * 16 + (lane >> 2);
#pragma unroll
            for (int nt = 0; nt < 4; nt++) {
                const int col = wn * 32 + nt * 8 + (lane & 3) * 2;
                smf[row * SLDF + col]     = acc[mt][nt][0];
                smf[row * SLDF + col + 1] = acc[mt][nt][1];
                smf[(row + 8) * SLDF + col]     = acc[mt][nt][2];
                smf[(row + 8) * SLDF + col + 1] = acc[mt][nt][3];
            }
        }
        __syncthreads();

        const bool lastStep = (t == Tt - 1);
#pragma unroll
        for (int r8 = 0; r8 < 8; r8++) {
            const int row = rg * 8 + r8;
            const int b = rowBase + row;
            const int trow = b * Tt + t;

            float4 G4 = *(float4*)&smf[row * SLDF + 4 * dl];
            float hr = G4.x + c0;
            float hz = G4.y + c1;
            float hn = G4.z + c2;
            float hj = G4.w + jb;

            const float* a = actions + (size_t)trow * Aa;
#pragma unroll
            for (int j = 0; j < 8; j++) {
                float av = a[j];
                hr = fmaf(av, m2r[j], hr);
                hz = fmaf(av, m2z[j], hz);
                hn = fmaf(av, m2n[j], hn);
                hj = fmaf(av, jea[j], hj);
            }

            const float* gi = g_gi + (size_t)trow * (3 * Dd);
            float r = sigmoidf_(gi[dg] + hr);
            float z = sigmoidf_(gi[Dd + dg] + hz);
            float n = tanhf(gi[2 * Dd + dg] + r * hn);
            float xv = g_x[(size_t)trow * Dd + dg];
            float hnew = (1.f - z) * n + z * hj + xv;

            const int oi = b * Dd + dg;
            if (lastStep) g_h[oi] = hnew;
            bf16 hh = __float2bfloat16(hnew);
            g_hh[oi] = hh;
            g_hl[oi] = __float2bfloat16(hnew - __bfloat162float(hh));
        }

        __syncthreads();
        if (tid == 0) {
            __threadfence();
            atomicAdd(&g_bar_cnt, 1u);
            const unsigned target = (unsigned)(t + 1) * NCTA_SCAN;
            while (atomicAdd(&g_bar_cnt, 0u) < target) {}
            __threadfence();
        }
        __syncthreads();
    }
}

// =============== conversions =================================================
// fp32 -> fp16 2-digit (activations)
__global__ void cvt16_a(const float* __restrict__ X, f16* __restrict__ Xh,
                        f16* __restrict__ Xl, int n4)
{
    int i = blockIdx.x * blockDim.x + threadIdx.x;
    if (i >= n4) return;
    float4 v = ((const float4*)X)[i];
    f16 h0 = __float2half_rn(v.x), h1 = __float2half_rn(v.y);
    f16 h2 = __float2half_rn(v.z), h3 = __float2half_rn(v.w);
    __half2* H = (__half2*)Xh;
    __half2* L = (__half2*)Xl;
    H[2 * i]     = __halves2half2(h0, h1);
    H[2 * i + 1] = __halves2half2(h2, h3);
    L[2 * i]     = __halves2half2(__float2half_rn(v.x - __half2float(h0)),
                                  __float2half_rn(v.y - __half2float(h1)));
    L[2 * i + 1] = __halves2half2(__float2half_rn(v.z - __half2float(h2)),
                                  __float2half_rn(v.w - __half2float(h3)));
}
// fp32 -> fp16 1-digit (weights)
__global__ void cvt16_w(const float* __restrict__ X, f16* __restrict__ Xh, int n4)
{
    int i = blockIdx.x * blockDim.x + threadIdx.x;
    if (i >= n4) return;
    float4 v = ((const float4*)X)[i];
    __half2* H = (__half2*)Xh;
    H[2 * i]     = __halves2half2(__float2half_rn(v.x), __float2half_rn(v.y));
    H[2 * i + 1] = __halves2half2(__float2half_rn(v.z), __float2half_rn(v.w));
}
// permuted bf16 hi/lo cvt of W_scan (scan path)
__global__ void cvt_hl_perm_ws()
{
    int i = blockIdx.x * blockDim.x + threadIdx.x;
    if (i >= 4 * Dd * Dd / 4) return;
    int flat = i * 4;
    int nrow = flat >> 10;
    int k = flat & 1023;
    int d = nrow >> 2, comp = nrow & 3;
    int orow = (comp < 3) ? comp * Dd + d : 3 * Dd + d;
    float4 v = *(const float4*)&g_wscan[(size_t)orow * Dd + k];
    bf16 h0 = __float2bfloat16(v.x), h1 = __float2bfloat16(v.y);
    bf16 h2 = __float2bfloat16(v.z), h3 = __float2bfloat16(v.w);
    __nv_bfloat162* H = (__nv_bfloat162*)g_wsh;
    __nv_bfloat162* L = (__nv_bfloat162*)g_wsl;
    H[2*i]   = __nv_bfloat162(h0, h1);
    H[2*i+1] = __nv_bfloat162(h2, h3);
    L[2*i]   = __nv_bfloat162(__float2bfloat16(v.x - __bfloat162float(h0)),
                              __float2bfloat16(v.y - __bfloat162float(h1)));
    L[2*i+1] = __nv_bfloat162(__float2bfloat16(v.z - __bfloat162float(h2)),
                              __float2bfloat16(v.w - __bfloat162float(h3)));
}

// =============== SIMT GEMM (precompute only) ==================================
#define BKd 8
__global__ void __launch_bounds__(256)
sgemm_ab(const float* __restrict__ A, const float* __restrict__ Bm,
         float* __restrict__ C, int M, int N, int K, int lda, int ldb, int ldc)
{
    __shared__ float As[BKd][128];
    __shared__ float Bs[BKd][128];
    const int tid = threadIdx.x;
    const int tx = tid & 15, ty = tid >> 4;
    const int rowBase = blockIdx.y * 128, colBase = blockIdx.x * 128;
    const int lrA = tid >> 1, lcA = (tid & 1) * 4;
    const int kkB = tid >> 5, c4B = (tid & 31) * 4;
    const float* Aptr = A + (size_t)(rowBase + lrA) * lda + lcA;
    const float* Bptr = Bm + (size_t)kkB * ldb + colBase + c4B;
    float acc[8][8];
#pragma unroll
    for (int i = 0; i < 8; i++)
#pragma unroll
        for (int j = 0; j < 8; j++) acc[i][j] = 0.f;
    for (int k0 = 0; k0 < K; k0 += BKd) {
        float4 av = *(const float4*)(Aptr + k0);
        float4 bv = *(const float4*)(Bptr + (size_t)k0 * ldb);
        As[lcA+0][lrA]=av.x; As[lcA+1][lrA]=av.y;
        As[lcA+2][lrA]=av.z; As[lcA+3][lrA]=av.w;
        *(float4*)&Bs[kkB][c4B] = bv;
        __syncthreads();
#pragma unroll
        for (int kk = 0; kk < BKd; kk++) {
            float a[8], b[8];
#pragma unroll
            for (int i = 0; i < 8; i++) a[i] = As[kk][ty*8+i];
#pragma unroll
            for (int j = 0; j < 8; j++) b[j] = Bs[kk][tx*8+j];
#pragma unroll
            for (int i = 0; i < 8; i++)
#pragma unroll
                for (int j = 0; j < 8; j++)
                    acc[i][j] = fmaf(a[i], b[j], acc[i][j]);
        }
        __syncthreads();
    }
#pragma unroll
    for (int i = 0; i < 8; i++) {
        const int r = rowBase + ty * 8 + i;
#pragma unroll
        for (int j = 0; j < 8; j++)
            C[(size_t)r * ldc + colBase + tx * 8 + j] = acc[i][j];
    }
}

__global__ void copy_jew(const float* __restrict__ je_w)
{
    int idx = blockIdx.x * blockDim.x + threadIdx.x;
    if (idx >= Dd * Dd) return;
    int j = idx >> 10, k = idx & 1023;
    g_wscan[(size_t)(3 * Dd + j) * Dd + k] = je_w[(size_t)j * JEW_LD + k];
}

__global__ void __launch_bounds__(128)
m2c_k(const float* __restrict__ whh, const float* __restrict__ je_w,
      const float* __restrict__ je_b, const float* __restrict__ bhh)
{
    const int i = blockIdx.x;
    const int t = threadIdx.x;
    float acc[9];
#pragma unroll
    for (int j = 0; j < 9; j++) acc[j] = 0.f;
    for (int k = t; k < Dd; k += 128) {
        float w = whh[(size_t)i * Dd + k];
        const float* jr = je_w + (size_t)k * JEW_LD + Dd;
#pragma unroll
        for (int j = 0; j < 8; j++) acc[j] = fmaf(w, jr[j], acc[j]);
        acc[8] = fmaf(w, je_b[k], acc[8]);
    }
    __shared__ float sh[9][128];
#pragma unroll
    for (int j = 0; j < 9; j++) sh[j][t] = acc[j];
    __syncthreads();
    for (int s = 64; s > 0; s >>= 1) {
        if (t < s)
#pragma unroll
            for (int j = 0; j < 9; j++) sh[j][t] += sh[j][t + s];
        __syncthreads();
    }
    if (t == 0) {
#pragma unroll
        for (int j = 0; j < 8; j++) g_M2[i * 8 + j] = sh[j][0];
        g_c[i] = sh[8][0] + bhh[i];
    }
}

// ---------------- batch stats + BN ------------------------------------------
__global__ void col_stats(const float* __restrict__ X, int M, int N,
                          float* __restrict__ mean, float* __restrict__ var)
{
    const int c = blockIdx.x * 32 + threadIdx.x;
    const int ry = threadIdx.y;
    float s = 0.f, s2 = 0.f;
    for (int r = ry; r < M; r += 8) {
        float v = X[(size_t)r * N + c];
        s += v; s2 += v * v;
    }
    __shared__ float sh[8][32], sh2[8][32];
    sh[ry][threadIdx.x] = s; sh2[ry][threadIdx.x] = s2;
    __syncthreads();
    if (ry == 0) {
#pragma unroll
        for (int y = 1; y < 8; y++) { s += sh[y][threadIdx.x]; s2 += sh2[y][threadIdx.x]; }
        float m = s / (float)M;
        mean[c] = m;
        var[c]  = s2 / (float)M - m * m;
    }
}

__global__ void bn_apply(const float* __restrict__ X, float* __restrict__ Y,
                         const float* __restrict__ mean, const float* __restrict__ var,
                         const float* __restrict__ g, const float* __restrict__ beta,
                         int total, int N, int relu)
{
    int idx = blockIdx.x * blockDim.x + threadIdx.x;
    if (idx >= total) return;
    int c = idx % N;
    float v = g[c] * (X[idx] - mean[c]) * rsqrtf(var[c] + EPSf) + beta[c];
    if (relu) v = fmaxf(v, 0.f);
    Y[idx] = v;
}

// BN + optional relu + optional fp32 out + fp16 2-digit out
__global__ void bn_apply_cvt16(const float* __restrict__ X, float* __restrict__ Yf,
                               f16* __restrict__ Yh, f16* __restrict__ Yl,
                               const float* __restrict__ mean, const float* __restrict__ var,
                               const float* __restrict__ g, const float* __restrict__ beta,
                               int total4, int N, int relu)
{
    int i = blockIdx.x * blockDim.x + threadIdx.x;
    if (i >= total4) return;
    int c0 = (i * 4) % N;
    float4 v = ((const float4*)X)[i];
    float o[4] = { v.x, v.y, v.z, v.w };
#pragma unroll
    for (int j = 0; j < 4; j++) {
        int c = c0 + j;
        float t = g[c] * (o[j] - mean[c]) * rsqrtf(var[c] + EPSf) + beta[c];
        if (relu) t = fmaxf(t, 0.f);
        o[j] = t;
    }
    if (Yf) ((float4*)Yf)[i] = make_float4(o[0], o[1], o[2], o[3]);
    f16 h0 = __float2half_rn(o[0]), h1 = __float2half_rn(o[1]);
    f16 h2 = __float2half_rn(o[2]), h3 = __float2half_rn(o[3]);
    __half2* H = (__half2*)Yh;
    __half2* L = (__half2*)Yl;
    H[2*i]   = __halves2half2(h0, h1);
    H[2*i+1] = __halves2half2(h2, h3);
    L[2*i]   = __halves2half2(__float2half_rn(o[0] - __half2float(h0)),
                              __float2half_rn(o[1] - __half2float(h1)));
    L[2*i+1] = __halves2half2(__float2half_rn(o[2] - __half2float(h2)),
                              __float2half_rn(o[3] - __half2float(h3)));
}

// ---------------- misc ------------------------------------------------------
__global__ void zero_h() {
    int idx = blockIdx.x * blockDim.x + threadIdx.x;
    if (idx == 0) g_bar_cnt = 0u;
    if (idx < Bb * Dd) {
        g_h[idx] = 0.f;
        g_hh[idx] = __float2bfloat16(0.f);
        g_hl[idx] = __float2bfloat16(0.f);
    }
}

// ---------------- threefry2x32-20 (JAX partitionable) ------------------------
__device__ __forceinline__ uint32_t rotl32_(uint32_t x, int r) {
    return (x << r) | (x >> (32 - r));
}
__device__ __forceinline__ void threefry2x32_(uint32_t k0, uint32_t k1,
                                              uint32_t& x0, uint32_t& x1)
{
    const uint32_t k2 = k0 ^ k1 ^ 0x1BD11BDAu;
    x0 += k0; x1 += k1;
#define TF_R4(a,b,c,d) \
    x0 += x1; x1 = rotl32_(x1, a); x1 ^= x0; \
    x0 += x1; x1 = rotl32_(x1, b); x1 ^= x0; \
    x0 += x1; x1 = rotl32_(x1, c); x1 ^= x0; \
    x0 += x1; x1 = rotl32_(x1, d); x1 ^= x0;
    TF_R4(13,15,26,6)  x0 += k1; x1 += k2 + 1u;
    TF_R4(17,29,16,24) x0 += k2; x1 += k0 + 2u;
    TF_R4(13,15,26,6)  x0 += k0; x1 += k1 + 3u;
    TF_R4(17,29,16,24) x0 += k1; x1 += k2 + 4u;
    TF_R4(13,15,26,6)  x0 += k2; x1 += k0 + 5u;
#undef TF_R4
}

__global__ void gumbel_softmax_k(float* __restrict__ out)
{
    const int bl = blockIdx.x;
    const int d  = threadIdx.x;
    const int i  = bl * ZDn + d;
    const float logit = g_h[i];

    uint32_t c0 = 0u;
    uint32_t c1 = (uint32_t)i;
    threefry2x32_(0u, 42u, c0, c1);
    const uint32_t bits = c0 ^ c1;
    float f = __uint_as_float((bits >> 9) | 0x3f800000u) - 1.0f;
    const float tiny = 1.1754943508222875e-38f;
    float u = fmaxf(f * (1.0f - tiny) + tiny, tiny);
    float gum = -logf(-logf(u));

    float v = logit + gum;

    __shared__ float red[ZDn];
    red[d] = v; __syncthreads();
    for (int s = ZDn / 2; s > 0; s >>= 1) {
        if (d < s) red[d] = fmaxf(red[d], red[d + s]);
        __syncthreads();
    }
    float mx = red[0];
    __syncthreads();
    float e = expf(v - mx);
    red[d] = e; __syncthreads();
    for (int s = ZDn / 2; s > 0; s >>= 1) {
        if (d < s) red[d] += red[d + s];
        __syncthreads();
    }
    float z = e / red[0];

    out[i] = logit;
    out[Bb * ZLn * ZDn + i] = z;
    f16 zh = __float2half_rn(z);
    g_zH[i] = zh;
    g_zL[i] = __float2half_rn(z - __half2float(zh));
}

// ---------------- launch ------------------------------------------------------
static inline float* symf(const void* s) {
    void* p = nullptr;
    cudaGetSymbolAddress(&p, s);
    return (float*)p;
}
static inline f16* symh(const void* s) {
    void* p = nullptr;
    cudaGetSymbolAddress(&p, s);
    return (f16*)p;
}

extern "C" void kernel_launch(void* const* d_in, const int* in_sizes, int n_in,
                              void* d_out, int out_size)
{
    (void)in_sizes; (void)n_in; (void)out_size;
    const float* obs      = (const float*)d_in[0];
    const float* actions  = (const float*)d_in[1];
    const float* enc_w1   = (const float*)d_in[2];
    const float* enc_b1   = (const float*)d_in[3];
    const float* enc_g1   = (const float*)d_in[4];
    const float* enc_bt1  = (const float*)d_in[5];
    const float* enc_w2   = (const float*)d_in[6];
    const float* enc_b2   = (const float*)d_in[7];
    const float* enc_g2   = (const float*)d_in[8];
    const float* enc_bt2  = (const float*)d_in[9];
    const float* je_w     = (const float*)d_in[10];
    const float* je_b     = (const float*)d_in[11];
    const float* gru_wih  = (const float*)d_in[12];
    const float* gru_bih  = (const float*)d_in[13];
    const float* gru_whh  = (const float*)d_in[14];
    const float* gru_bhh  = (const float*)d_in[15];
    const float* dec_w1   = (const float*)d_in[16];
    const float* dec_b1   = (const float*)d_in[17];
    const float* dec_g1   = (const float*)d_in[18];
    const float* dec_bt1  = (const float*)d_in[19];
    const float* dec_w2   = (const float*)d_in[20];
    const float* dec_b2   = (const float*)d_in[21];
    const float* dec_g2   = (const float*)d_in[22];
    const float* dec_bt2  = (const float*)d_in[23];
    float* out = (float*)d_out;

    float* p_h1 = symf(g_h1);
    float* p_x  = symf(g_x);
    float* p_gi = symf(g_gi);
    float* p_d1 = symf(g_d1);
    float* p_d2 = symf(g_d2);
    float* p_m  = symf(g_mean);
    float* p_v  = symf(g_var);
    float* p_ws = symf(g_wscan);

    f16 *p_obsH = symh(g_obsH), *p_obsL = symh(g_obsL);
    f16 *p_w1 = symh(g_w1);
    f16 *p_h1H = symh(g_h1H), *p_h1L = symh(g_h1L);
    f16 *p_w2 = symh(g_w2);
    f16 *p_xH = symh(g_xH), *p_xL = symh(g_xL);
    f16 *p_wih = symh(g_wih);
    f16 *p_zH = symh(g_zH), *p_zL = symh(g_zL);
    f16 *p_d1H = symh(g_d1H), *p_d1L = symh(g_d1L);
    f16 *p_dw1 = symh(g_dw1);
    f16 *p_dw2 = symh(g_dw2);

    // one-time resources (host-side; no device memory involved)
    static cudaStream_t sSide = nullptr;
    static cudaEvent_t evFork = nullptr, evJoin = nullptr;
    static bool attrDone = false;
    if (!attrDone) {
        cudaFuncSetAttribute(mma_gemm16, cudaFuncAttributeMaxDynamicSharedMemorySize, SM16_BYTES);
        cudaFuncSetAttribute(mma_scan_persist, cudaFuncAttributeMaxDynamicSharedMemorySize, SSM_BYTES);
        cudaStreamCreateWithFlags(&sSide, cudaStreamNonBlocking);
        cudaEventCreateWithFlags(&evFork, cudaEventDisableTiming);
        cudaEventCreateWithFlags(&evJoin, cudaEventDisableTiming);
        attrDone = true;
    }

    dim3 blk(256);
    dim3 statsBlk(32, 8);

    // ================== FORK: side stream does setup work =====================
    cudaEventRecord(evFork, 0);
    cudaStreamWaitEvent(sSide, evFork, 0);

    cvt16_w<<<(Dd * Hh / 4 + 255) / 256, blk, 0, sSide>>>(enc_w2, p_w2, Dd * Hh / 4);
    cvt16_w<<<(3 * Dd * Dd / 4 + 255) / 256, blk, 0, sSide>>>(gru_wih, p_wih, 3 * Dd * Dd / 4);
    cvt16_w<<<(Hh * Dd / 4 + 255) / 256, blk, 0, sSide>>>(dec_w1, p_dw1, Hh * Dd / 4);
    cvt16_w<<<(OBSn * Hh / 4 + 255) / 256, blk, 0, sSide>>>(dec_w2, p_dw2, OBSn * Hh / 4);
    {
        dim3 grid(Dd / 128, 3 * Dd / 128);
        sgemm_ab<<<grid, blk, 0, sSide>>>(gru_whh, je_w, p_ws, 3 * Dd, Dd, Dd, Dd, JEW_LD, Dd);
        copy_jew<<<(Dd * Dd + 255) / 256, blk, 0, sSide>>>(je_w);
        m2c_k<<<3 * Dd, 128, 0, sSide>>>(gru_whh, je_w, je_b, gru_bhh);
        cvt_hl_perm_ws<<<(4 * Dd * Dd / 4 + 255) / 256, blk, 0, sSide>>>();
    }
    zero_h<<<(Bb * Dd + 255) / 256, blk, 0, sSide>>>();
    cudaEventRecord(evJoin, sSide);

    // main chain: obs/w1 cvt -> enc1
    cvt16_a<<<(BT * OBSn / 4 + 255) / 256, blk>>>(obs, p_obsH, p_obsL, BT * OBSn / 4);
    cvt16_w<<<(Hh * OBSn / 4 + 255) / 256, blk>>>(enc_w1, p_w1, Hh * OBSn / 4);

    // ---- encoder layer 1 (fp16 2-term) ----
    {
        dim3 grid(Hh / 128, BT / 128);
        mma_gemm16<<<grid, blk, SM16_BYTES>>>(p_obsH, p_obsL, p_w1, enc_b1, p_h1,
                                              BT, Hh, OBSn);
        col_stats<<<Hh / 32, statsBlk>>>(p_h1, BT, Hh, p_m, p_v);
        bn_apply_cvt16<<<(BT * Hh / 4 + 255) / 256, blk>>>(p_h1, nullptr, p_h1H, p_h1L,
                                                           p_m, p_v, enc_g1, enc_bt1,
                                                           BT * Hh / 4, Hh, 1);
    }

    // ================== JOIN ==================================================
    cudaStreamWaitEvent(0, evJoin, 0);

    // ---- encoder layer 2 (fp16 2-term) ----
    {
        dim3 grid(Dd / 128, BT / 128);
        mma_gemm16<<<grid, blk, SM16_BYTES>>>(p_h1H, p_h1L, p_w2, enc_b2, p_x,
                                              BT, Dd, Hh);
        col_stats<<<Dd / 32, statsBlk>>>(p_x, BT, Dd, p_m, p_v);
        bn_apply_cvt16<<<(BT * Dd / 4 + 255) / 256, blk>>>(p_x, p_x, p_xH, p_xL,
                                                           p_m, p_v, enc_g2, enc_bt2,
                                                           BT * Dd / 4, Dd, 0);
    }
    // ---- gi (fp16 2-term) ----
    {
        dim3 grid(3 * Dd / 128, BT / 128);
        mma_gemm16<<<grid, blk, SM16_BYTES>>>(p_xH, p_xL, p_wih, gru_bih, p_gi,
                                              BT, 3 * Dd, Dd);
    }
    // ---- recurrent scan: ONE persistent kernel (bf16 3-term) ----
    {
        dim3 gridS(4 * Dd / 64, Bb / 128);   // (64, 2) = 128 CTAs, all resident
        mma_scan_persist<<<gridS, blk, SSM_BYTES>>>(actions, je_w, je_b);
    }
    // ---- gumbel softmax ----
    gumbel_softmax_k<<<Bb * ZLn, ZDn>>>(out);
    // ---- decoder layer 1 (fp16 2-term) ----
    {
        dim3 grid(Hh / 128, Bb / 128);
        mma_gemm16<<<grid, blk, SM16_BYTES>>>(p_zH, p_zL, p_dw1, dec_b1, p_d1,
                                              Bb, Hh, Dd);
        col_stats<<<Hh / 32, statsBlk>>>(p_d1, Bb, Hh, p_m, p_v);
        bn_apply_cvt16<<<(Bb * Hh / 4 + 255) / 256, blk>>>(p_d1, nullptr, p_d1H, p_d1L,
                                                           p_m, p_v, dec_g1, dec_bt1,
                                                           Bb * Hh / 4, Hh, 1);
    }
    // ---- decoder layer 2 (fp16 2-term) -> x_hat ----
    {
        dim3 grid(OBSn / 128, Bb / 128);
        mma_gemm16<<<grid, blk, SM16_BYTES>>>(p_d1H, p_d1L, p_dw2, dec_b2, p_d2,
                                              Bb, OBSn, Hh);
        col_stats<<<OBSn / 32, statsBlk>>>(p_d2, Bb, OBSn, p_m, p_v);
        int total = Bb * OBSn;
        bn_apply<<<(total + 255) / 256, blk>>>(p_d2, out + 2 * Bb * ZLn * ZDn,
                                               p_m, p_v, dec_g2, dec_bt2, total, OBSn, 0);
    }
}

// round 13
// speedup vs baseline: 2.2822x; 1.0756x over previous
#include <cuda_runtime.h>
#include <cuda_bf16.h>
#include <cuda_fp16.h>
#include <cstdint>

#define Bb   256
#define Tt   64
#define OBSn 4096
#define Dd   1024
#define Aa   8
#define Hh   2048
#define ZLn  4
#define ZDn  256
#define BT   (Bb*Tt)          // 16384
#define EPSf 1e-5f
#define JEW_LD (Dd + Aa)      // 1032

typedef __half f16;

// ---------------- scratch (static device globals; no allocation) -------------
__device__ float g_h1[BT * Hh];
__device__ float g_x [BT * Dd];
__device__ float g_gi[BT * 3 * Dd];
__device__ float g_h [Bb * Dd];
__device__ float g_d1[Bb * Hh];
__device__ float g_d2[Bb * OBSn];
__device__ float g_mean[4096];
__device__ float g_var [4096];
__device__ float g_wscan[4 * Dd * Dd];
__device__ float g_M2[3 * Dd * Aa];
__device__ float g_c [3 * Dd];
__device__ unsigned g_bar_cnt;

// fp16 buffers: activations 2-digit, weights 1-digit
__device__ f16 g_obsH[BT * OBSn], g_obsL[BT * OBSn];
__device__ f16 g_w1  [Hh * OBSn];
__device__ f16 g_h1H [BT * Hh],   g_h1L [BT * Hh];
__device__ f16 g_w2  [Dd * Hh];
__device__ f16 g_xH  [BT * Dd],   g_xL  [BT * Dd];
__device__ f16 g_wih [3 * Dd * Dd];
__device__ f16 g_zH  [Bb * Dd],   g_zL  [Bb * Dd];
__device__ f16 g_d1H [Bb * Hh],   g_d1L [Bb * Hh];
__device__ f16 g_dw1 [Hh * Dd];
__device__ f16 g_dw2 [OBSn * Hh];
// scan (fp16 2-term now): h 2-digit, W_scan permuted 1-digit
__device__ f16 g_wsf [4 * Dd * Dd];               // PERMUTED rows 4d+comp
__device__ f16 g_hH  [Bb * Dd],   g_hL  [Bb * Dd];

// ======================= PTX helpers =========================================
__device__ __forceinline__ uint32_t smem_u32(const void* p) {
    uint32_t a;
    asm("{ .reg .u64 t; cvta.to.shared.u64 t, %1; cvt.u32.u64 %0, t; }"
        : "=r"(a) : "l"(p));
    return a;
}
__device__ __forceinline__ void cp16(uint32_t s, const void* g) {
    asm volatile("cp.async.cg.shared.global [%0], [%1], 16;" :: "r"(s), "l"(g));
}
__device__ __forceinline__ void cp_commit() {
    asm volatile("cp.async.commit_group;" ::: "memory");
}
__device__ __forceinline__ void cp_wait0() {
    asm volatile("cp.async.wait_group 0;" ::: "memory");
}
__device__ __forceinline__ void cp_wait1() {
    asm volatile("cp.async.wait_group 1;" ::: "memory");
}
__device__ __forceinline__ void cp_wait2() {
    asm volatile("cp.async.wait_group 2;" ::: "memory");
}
__device__ __forceinline__ void ldm_x4(uint32_t* r, uint32_t a) {
    asm volatile("ldmatrix.sync.aligned.m8n8.x4.shared.b16 {%0,%1,%2,%3}, [%4];"
                 : "=r"(r[0]), "=r"(r[1]), "=r"(r[2]), "=r"(r[3]) : "r"(a));
}
__device__ __forceinline__ void mma_f16(float* c, const uint32_t* a, const uint32_t* b) {
    asm volatile("mma.sync.aligned.m16n8k16.row.col.f32.f16.f16.f32 "
                 "{%0,%1,%2,%3}, {%4,%5,%6,%7}, {%8,%9}, {%0,%1,%2,%3};"
                 : "+f"(c[0]), "+f"(c[1]), "+f"(c[2]), "+f"(c[3])
                 : "r"(a[0]), "r"(a[1]), "r"(a[2]), "r"(a[3]),
                   "r"(b[0]), "r"(b[1]));
}

// ============ fp16 2-term GEMM: C = (Ah+Al) @ Bh^T (+bias), 3-stage ==========
#define LD2   40
#define TILE2 (128 * LD2)
#define STG16 (3 * TILE2)              // Ah, Al, Bh
#define SM16_BYTES (3 * STG16 * 2)     // 92160

__global__ void __launch_bounds__(256)
mma_gemm16(const f16* __restrict__ Ah, const f16* __restrict__ Al,
           const f16* __restrict__ Bh,
           const float* __restrict__ bias, float* __restrict__ C,
           int M, int N, int K)
{
    extern __shared__ f16 smh[];

    const int tid = threadIdx.x;
    const int wid = tid >> 5, lane = tid & 31;
    const int wm = wid >> 2, wn = wid & 3;
    const int rowBase = blockIdx.y * 128, colBase = blockIdx.x * 128;
    const int NC = K >> 5;

    float acc[4][4][4];
#pragma unroll
    for (int i = 0; i < 4; i++)
#pragma unroll
        for (int j = 0; j < 4; j++)
#pragma unroll
            for (int k = 0; k < 4; k++) acc[i][j][k] = 0.f;

    const f16* srcs[3] = { Ah, Al, Bh };
    const int  rbs [3] = { rowBase, rowBase, colBase };

    auto load = [&](int c, int st) {
        const int koff = c << 5;
        f16* stp = smh + st * STG16;
#pragma unroll
        for (int tI = 0; tI < 3; tI++) {
#pragma unroll
            for (int i = 0; i < 2; i++) {
                int u = tid * 2 + i;
                int row = u >> 2;
                int seg = (u & 3) << 3;
                cp16(smem_u32(stp + tI * TILE2 + row * LD2 + seg),
                     srcs[tI] + (size_t)(rbs[tI] + row) * K + koff + seg);
            }
        }
        cp_commit();
    };

    load(0, 0);
    load(1, 1);
    for (int c = 0; c < NC; c++) {
        const int st = c % 3;
        if (c + 2 < NC) { load(c + 2, (c + 2) % 3); cp_wait2(); }
        else if (c + 1 < NC) cp_wait1();
        else cp_wait0();
        __syncthreads();

        const f16* stp = smh + st * STG16;
#pragma unroll
        for (int kh = 0; kh < 2; kh++) {
            const int kcol = kh << 4;
            uint32_t a[2][4][4];
            uint32_t b[4][2];
#pragma unroll
            for (int t = 0; t < 2; t++) {
                const f16* base = stp + t * TILE2;
#pragma unroll
                for (int mt = 0; mt < 4; mt++) {
                    int r = wm * 64 + mt * 16 + (lane & 15);
                    int cc = kcol + ((lane >> 4) << 3);
                    ldm_x4(a[t][mt], smem_u32(base + r * LD2 + cc));
                }
            }
            {
                const f16* base = stp + 2 * TILE2;
#pragma unroll
                for (int np = 0; np < 2; np++) {
                    int r = wn * 32 + (np * 2 + (lane >> 4)) * 8 + (lane & 7);
                    int cc = kcol + (((lane >> 3) & 1) << 3);
                    uint32_t rr[4];
                    ldm_x4(rr, smem_u32(base + r * LD2 + cc));
                    b[np * 2][0] = rr[0];     b[np * 2][1] = rr[1];
                    b[np * 2 + 1][0] = rr[2]; b[np * 2 + 1][1] = rr[3];
                }
            }
#pragma unroll
            for (int mt = 0; mt < 4; mt++)
#pragma unroll
                for (int nt = 0; nt < 4; nt++) {
                    mma_f16(acc[mt][nt], a[0][mt], b[nt]);
                    mma_f16(acc[mt][nt], a[1][mt], b[nt]);
                }
        }
        __syncthreads();
    }

#pragma unroll
    for (int mt = 0; mt < 4; mt++) {
        const int row = rowBase + wm * 64 + mt * 16 + (lane >> 2);
#pragma unroll
        for (int nt = 0; nt < 4; nt++) {
            const int col = colBase + wn * 32 + nt * 8 + (lane & 3) * 2;
            float b0 = bias ? bias[col] : 0.f;
            float b1 = bias ? bias[col + 1] : 0.f;
            *(float2*)(C + (size_t)row * N + col) =
                make_float2(acc[mt][nt][0] + b0, acc[mt][nt][1] + b1);
            *(float2*)(C + (size_t)(row + 8) * N + col) =
                make_float2(acc[mt][nt][2] + b0, acc[mt][nt][3] + b1);
        }
    }
}

// =================== persistent fused scan (fp16 2-term) =====================
// A = h (2-digit fp16) [256,1024]; B = permuted W_scan (1-digit fp16).
#define SLD    40
#define SATILE (128 * SLD)
#define SBTILE (64 * SLD)
#define SSTAGE (2 * SATILE + SBTILE)
#define SSM_BYTES (2 * SSTAGE * 2)     // 51200
#define SLDF   68
#define NCTA_SCAN 128

__device__ __forceinline__ float sigmoidf_(float x) { return 1.f / (1.f + expf(-x)); }

__global__ void __launch_bounds__(256)
mma_scan_persist(const float* __restrict__ actions,
                 const float* __restrict__ je_w,
                 const float* __restrict__ je_b)
{
    extern __shared__ f16 ssm[];

    const int tid = threadIdx.x;
    const int wid = tid >> 5, lane = tid & 31;
    const int wm = wid & 3;        // 4 m-groups of 32 rows
    const int wn = wid >> 2;       // 2 n-groups of 32 cols
    const int rowBase = blockIdx.y * 128;
    const int colBase = blockIdx.x * 64;
    const int NC = Dd >> 5;   // 32

    const int dl = tid & 15;
    const int rg = tid >> 4;
    const int dg = (colBase >> 2) + dl;
    const float c0 = g_c[dg], c1 = g_c[Dd + dg], c2 = g_c[2 * Dd + dg];
    const float jb = je_b[dg];
    float m2r[8], m2z[8], m2n[8], jea[8];
#pragma unroll
    for (int j = 0; j < 8; j++) {
        m2r[j] = g_M2[(size_t)dg * 8 + j];
        m2z[j] = g_M2[(size_t)(Dd + dg) * 8 + j];
        m2n[j] = g_M2[(size_t)(2 * Dd + dg) * 8 + j];
        jea[j] = je_w[(size_t)dg * JEW_LD + Dd + j];
    }

    auto load = [&](int c, int st) {
        const int koff = c << 5;
        f16* stp = ssm + st * SSTAGE;
#pragma unroll
        for (int tI = 0; tI < 2; tI++) {
            const f16* src = tI ? g_hL : g_hH;
#pragma unroll
            for (int i = 0; i < 2; i++) {
                int u = tid * 2 + i;
                int row = u >> 2;
                int seg = (u & 3) << 3;
                cp16(smem_u32(stp + tI * SATILE + row * SLD + seg),
                     src + (size_t)(rowBase + row) * Dd + koff + seg);
            }
        }
        {
            int row = tid >> 2;
            int seg = (tid & 3) << 3;
            cp16(smem_u32(stp + 2 * SATILE + row * SLD + seg),
                 g_wsf + (size_t)(colBase + row) * Dd + koff + seg);
        }
        cp_commit();
    };

    for (int t = 0; t < Tt; t++) {
        float acc[2][4][4];
#pragma unroll
        for (int i = 0; i < 2; i++)
#pragma unroll
            for (int j = 0; j < 4; j++)
#pragma unroll
                for (int k = 0; k < 4; k++) acc[i][j][k] = 0.f;

        load(0, 0);
        int st = 0;
        for (int c = 0; c < NC; c++) {
            const bool more = (c + 1) < NC;
            if (more) { load(c + 1, st ^ 1); cp_wait1(); }
            else      { cp_wait0(); }
            __syncthreads();

            const f16* stp = ssm + st * SSTAGE;
#pragma unroll
            for (int kh = 0; kh < 2; kh++) {
                const int kcol = kh << 4;
                uint32_t a[2][2][4];
                uint32_t b[4][2];
#pragma unroll
                for (int tI = 0; tI < 2; tI++) {
                    const f16* base = stp + tI * SATILE;
#pragma unroll
                    for (int mt = 0; mt < 2; mt++) {
                        int r = wm * 32 + mt * 16 + (lane & 15);
                        int cc = kcol + ((lane >> 4) << 3);
                        ldm_x4(a[tI][mt], smem_u32(base + r * SLD + cc));
                    }
                }
                {
                    const f16* base = stp + 2 * SATILE;
#pragma unroll
                    for (int np = 0; np < 2; np++) {
                        int r = wn * 32 + (np * 2 + (lane >> 4)) * 8 + (lane & 7);
                        int cc = kcol + (((lane >> 3) & 1) << 3);
                        uint32_t rr[4];
                        ldm_x4(rr, smem_u32(base + r * SLD + cc));
                        b[np * 2][0] = rr[0];     b[np * 2][1] = rr[1];
                        b[np * 2 + 1][0] = rr[2]; b[np * 2 + 1][1] = rr[3];
                    }
                }
#pragma unroll
                for (int mt = 0; mt < 2; mt++)
#pragma unroll
                    for (int nt = 0; nt < 4; nt++) {
                        mma_f16(acc[mt][nt], a[0][mt], b[nt]);
                        mma_f16(acc[mt][nt], a[1][mt], b[nt]);
                    }
            }
            __syncthreads();
            st ^= 1;
        }

        float* smf = (float*)ssm;
#pragma unroll
        for (int mt = 0; mt < 2; mt++) {
            const int row = wm * 32 + mt * 16 + (lane >> 2);
#pragma unroll
            for (int nt = 0; nt < 4; nt++) {
                const int col = wn * 32 + nt * 8 + (lane & 3) * 2;
                smf[row * SLDF + col]     = acc[mt][nt][0];
                smf[row * SLDF + col + 1] = acc[mt][nt][1];
                smf[(row + 8) * SLDF + col]     = acc[mt][nt][2];
                smf[(row + 8) * SLDF + col + 1] = acc[mt][nt][3];
            }
        }
        __syncthreads();

        const bool lastStep = (t == Tt - 1);
#pragma unroll
        for (int r8 = 0; r8 < 8; r8++) {
            const int row = rg * 8 + r8;
            const int b = rowBase + row;
            const int trow = b * Tt + t;

            float4 G4 = *(float4*)&smf[row * SLDF + 4 * dl];
            float hr = G4.x + c0;
            float hz = G4.y + c1;
            float hn = G4.z + c2;
            float hj = G4.w + jb;

            const float* a = actions + (size_t)trow * Aa;
#pragma unroll
            for (int j = 0; j < 8; j++) {
                float av = a[j];
                hr = fmaf(av, m2r[j], hr);
                hz = fmaf(av, m2z[j], hz);
                hn = fmaf(av, m2n[j], hn);
                hj = fmaf(av, jea[j], hj);
            }

            const float* gi = g_gi + (size_t)trow * (3 * Dd);
            float r = sigmoidf_(gi[dg] + hr);
            float z = sigmoidf_(gi[Dd + dg] + hz);
            float n = tanhf(gi[2 * Dd + dg] + r * hn);
            float xv = g_x[(size_t)trow * Dd + dg];
            float hnew = (1.f - z) * n + z * hj + xv;

            const int oi = b * Dd + dg;
            if (lastStep) g_h[oi] = hnew;
            f16 hh = __float2half_rn(hnew);
            g_hH[oi] = hh;
            g_hL[oi] = __float2half_rn(hnew - __half2float(hh));
        }

        __syncthreads();
        if (tid == 0) {
            __threadfence();
            atomicAdd(&g_bar_cnt, 1u);
            const unsigned target = (unsigned)(t + 1) * NCTA_SCAN;
            while (atomicAdd(&g_bar_cnt, 0u) < target) {}
            __threadfence();
        }
        __syncthreads();
    }
}

// =============== conversions =================================================
__global__ void cvt16_a(const float* __restrict__ X, f16* __restrict__ Xh,
                        f16* __restrict__ Xl, int n4)
{
    int i = blockIdx.x * blockDim.x + threadIdx.x;
    if (i >= n4) return;
    float4 v = ((const float4*)X)[i];
    f16 h0 = __float2half_rn(v.x), h1 = __float2half_rn(v.y);
    f16 h2 = __float2half_rn(v.z), h3 = __float2half_rn(v.w);
    __half2* H = (__half2*)Xh;
    __half2* L = (__half2*)Xl;
    H[2 * i]     = __halves2half2(h0, h1);
    H[2 * i + 1] = __halves2half2(h2, h3);
    L[2 * i]     = __halves2half2(__float2half_rn(v.x - __half2float(h0)),
                                  __float2half_rn(v.y - __half2float(h1)));
    L[2 * i + 1] = __halves2half2(__float2half_rn(v.z - __half2float(h2)),
                                  __float2half_rn(v.w - __half2float(h3)));
}
__global__ void cvt16_w(const float* __restrict__ X, f16* __restrict__ Xh, int n4)
{
    int i = blockIdx.x * blockDim.x + threadIdx.x;
    if (i >= n4) return;
    float4 v = ((const float4*)X)[i];
    __half2* H = (__half2*)Xh;
    H[2 * i]     = __halves2half2(__float2half_rn(v.x), __float2half_rn(v.y));
    H[2 * i + 1] = __halves2half2(__float2half_rn(v.z), __float2half_rn(v.w));
}
// permuted single-digit fp16 cvt of W_scan: new row 4d+comp
__global__ void cvt16_perm_ws()
{
    int i = blockIdx.x * blockDim.x + threadIdx.x;
    if (i >= 4 * Dd * Dd / 4) return;
    int flat = i * 4;
    int nrow = flat >> 10;
    int k = flat & 1023;
    int d = nrow >> 2, comp = nrow & 3;
    int orow = (comp < 3) ? comp * Dd + d : 3 * Dd + d;
    float4 v = *(const float4*)&g_wscan[(size_t)orow * Dd + k];
    __half2* H = (__half2*)g_wsf;
    H[2*i]   = __halves2half2(__float2half_rn(v.x), __float2half_rn(v.y));
    H[2*i+1] = __halves2half2(__float2half_rn(v.z), __float2half_rn(v.w));
}

// =============== SIMT GEMM (precompute only) ==================================
#define BKd 8
__global__ void __launch_bounds__(256)
sgemm_ab(const float* __restrict__ A, const float* __restrict__ Bm,
         float* __restrict__ C, int M, int N, int K, int lda, int ldb, int ldc)
{
    __shared__ float As[BKd][128];
    __shared__ float Bs[BKd][128];
    const int tid = threadIdx.x;
    const int tx = tid & 15, ty = tid >> 4;
    const int rowBase = blockIdx.y * 128, colBase = blockIdx.x * 128;
    const int lrA = tid >> 1, lcA = (tid & 1) * 4;
    const int kkB = tid >> 5, c4B = (tid & 31) * 4;
    const float* Aptr = A + (size_t)(rowBase + lrA) * lda + lcA;
    const float* Bptr = Bm + (size_t)kkB * ldb + colBase + c4B;
    float acc[8][8];
#pragma unroll
    for (int i = 0; i < 8; i++)
#pragma unroll
        for (int j = 0; j < 8; j++) acc[i][j] = 0.f;
    for (int k0 = 0; k0 < K; k0 += BKd) {
        float4 av = *(const float4*)(Aptr + k0);
        float4 bv = *(const float4*)(Bptr + (size_t)k0 * ldb);
        As[lcA+0][lrA]=av.x; As[lcA+1][lrA]=av.y;
        As[lcA+2][lrA]=av.z; As[lcA+3][lrA]=av.w;
        *(float4*)&Bs[kkB][c4B] = bv;
        __syncthreads();
#pragma unroll
        for (int kk = 0; kk < BKd; kk++) {
            float a[8], b[8];
#pragma unroll
            for (int i = 0; i < 8; i++) a[i] = As[kk][ty*8+i];
#pragma unroll
            for (int j = 0; j < 8; j++) b[j] = Bs[kk][tx*8+j];
#pragma unroll
            for (int i = 0; i < 8; i++)
#pragma unroll
                for (int j = 0; j < 8; j++)
                    acc[i][j] = fmaf(a[i], b[j], acc[i][j]);
        }
        __syncthreads();
    }
#pragma unroll
    for (int i = 0; i < 8; i++) {
        const int r = rowBase + ty * 8 + i;
#pragma unroll
        for (int j = 0; j < 8; j++)
            C[(size_t)r * ldc + colBase + tx * 8 + j] = acc[i][j];
    }
}

__global__ void copy_jew(const float* __restrict__ je_w)
{
    int idx = blockIdx.x * blockDim.x + threadIdx.x;
    if (idx >= Dd * Dd) return;
    int j = idx >> 10, k = idx & 1023;
    g_wscan[(size_t)(3 * Dd + j) * Dd + k] = je_w[(size_t)j * JEW_LD + k];
}

__global__ void __launch_bounds__(128)
m2c_k(const float* __restrict__ whh, const float* __restrict__ je_w,
      const float* __restrict__ je_b, const float* __restrict__ bhh)
{
    const int i = blockIdx.x;
    const int t = threadIdx.x;
    float acc[9];
#pragma unroll
    for (int j = 0; j < 9; j++) acc[j] = 0.f;
    for (int k = t; k < Dd; k += 128) {
        float w = whh[(size_t)i * Dd + k];
        const float* jr = je_w + (size_t)k * JEW_LD + Dd;
#pragma unroll
        for (int j = 0; j < 8; j++) acc[j] = fmaf(w, jr[j], acc[j]);
        acc[8] = fmaf(w, je_b[k], acc[8]);
    }
    __shared__ float sh[9][128];
#pragma unroll
    for (int j = 0; j < 9; j++) sh[j][t] = acc[j];
    __syncthreads();
    for (int s = 64; s > 0; s >>= 1) {
        if (t < s)
#pragma unroll
            for (int j = 0; j < 9; j++) sh[j][t] += sh[j][t + s];
        __syncthreads();
    }
    if (t == 0) {
#pragma unroll
        for (int j = 0; j < 8; j++) g_M2[i * 8 + j] = sh[j][0];
        g_c[i] = sh[8][0] + bhh[i];
    }
}

// ---------------- batch stats + BN ------------------------------------------
__global__ void col_stats(const float* __restrict__ X, int M, int N,
                          float* __restrict__ mean, float* __restrict__ var)
{
    const int c = blockIdx.x * 32 + threadIdx.x;
    const int ry = threadIdx.y;
    float s = 0.f, s2 = 0.f;
    for (int r = ry; r < M; r += 8) {
        float v = X[(size_t)r * N + c];
        s += v; s2 += v * v;
    }
    __shared__ float sh[8][32], sh2[8][32];
    sh[ry][threadIdx.x] = s; sh2[ry][threadIdx.x] = s2;
    __syncthreads();
    if (ry == 0) {
#pragma unroll
        for (int y = 1; y < 8; y++) { s += sh[y][threadIdx.x]; s2 += sh2[y][threadIdx.x]; }
        float m = s / (float)M;
        mean[c] = m;
        var[c]  = s2 / (float)M - m * m;
    }
}

__global__ void bn_apply(const float* __restrict__ X, float* __restrict__ Y,
                         const float* __restrict__ mean, const float* __restrict__ var,
                         const float* __restrict__ g, const float* __restrict__ beta,
                         int total, int N, int relu)
{
    int idx = blockIdx.x * blockDim.x + threadIdx.x;
    if (idx >= total) return;
    int c = idx % N;
    float v = g[c] * (X[idx] - mean[c]) * rsqrtf(var[c] + EPSf) + beta[c];
    if (relu) v = fmaxf(v, 0.f);
    Y[idx] = v;
}

__global__ void bn_apply_cvt16(const float* __restrict__ X, float* __restrict__ Yf,
                               f16* __restrict__ Yh, f16* __restrict__ Yl,
                               const float* __restrict__ mean, const float* __restrict__ var,
                               const float* __restrict__ g, const float* __restrict__ beta,
                               int total4, int N, int relu)
{
    int i = blockIdx.x * blockDim.x + threadIdx.x;
    if (i >= total4) return;
    int c0 = (i * 4) % N;
    float4 v = ((const float4*)X)[i];
    float o[4] = { v.x, v.y, v.z, v.w };
#pragma unroll
    for (int j = 0; j < 4; j++) {
        int c = c0 + j;
        float t = g[c] * (o[j] - mean[c]) * rsqrtf(var[c] + EPSf) + beta[c];
        if (relu) t = fmaxf(t, 0.f);
        o[j] = t;
    }
    if (Yf) ((float4*)Yf)[i] = make_float4(o[0], o[1], o[2], o[3]);
    f16 h0 = __float2half_rn(o[0]), h1 = __float2half_rn(o[1]);
    f16 h2 = __float2half_rn(o[2]), h3 = __float2half_rn(o[3]);
    __half2* H = (__half2*)Yh;
    __half2* L = (__half2*)Yl;
    H[2*i]   = __halves2half2(h0, h1);
    H[2*i+1] = __halves2half2(h2, h3);
    L[2*i]   = __halves2half2(__float2half_rn(o[0] - __half2float(h0)),
                              __float2half_rn(o[1] - __half2float(h1)));
    L[2*i+1] = __halves2half2(__float2half_rn(o[2] - __half2float(h2)),
                              __float2half_rn(o[3] - __half2float(h3)));
}

// ---------------- misc ------------------------------------------------------
__global__ void zero_h() {
    int idx = blockIdx.x * blockDim.x + threadIdx.x;
    if (idx == 0) g_bar_cnt = 0u;
    if (idx < Bb * Dd) {
        g_h[idx] = 0.f;
        g_hH[idx] = __float2half_rn(0.f);
        g_hL[idx] = __float2half_rn(0.f);
    }
}

// ---------------- threefry2x32-20 (JAX partitionable) ------------------------
__device__ __forceinline__ uint32_t rotl32_(uint32_t x, int r) {
    return (x << r) | (x >> (32 - r));
}
__device__ __forceinline__ void threefry2x32_(uint32_t k0, uint32_t k1,
                                              uint32_t& x0, uint32_t& x1)
{
    const uint32_t k2 = k0 ^ k1 ^ 0x1BD11BDAu;
    x0 += k0; x1 += k1;
#define TF_R4(a,b,c,d) \
    x0 += x1; x1 = rotl32_(x1, a); x1 ^= x0; \
    x0 += x1; x1 = rotl32_(x1, b); x1 ^= x0; \
    x0 += x1; x1 = rotl32_(x1, c); x1 ^= x0; \
    x0 += x1; x1 = rotl32_(x1, d); x1 ^= x0;
    TF_R4(13,15,26,6)  x0 += k1; x1 += k2 + 1u;
    TF_R4(17,29,16,24) x0 += k2; x1 += k0 + 2u;
    TF_R4(13,15,26,6)  x0 += k0; x1 += k1 + 3u;
    TF_R4(17,29,16,24) x0 += k1; x1 += k2 + 4u;
    TF_R4(13,15,26,6)  x0 += k2; x1 += k0 + 5u;
#undef TF_R4
}

__global__ void gumbel_softmax_k(float* __restrict__ out)
{
    const int bl = blockIdx.x;
    const int d  = threadIdx.x;
    const int i  = bl * ZDn + d;
    const float logit = g_h[i];

    uint32_t c0 = 0u;
    uint32_t c1 = (uint32_t)i;
    threefry2x32_(0u, 42u, c0, c1);
    const uint32_t bits = c0 ^ c1;
    float f = __uint_as_float((bits >> 9) | 0x3f800000u) - 1.0f;
    const float tiny = 1.1754943508222875e-38f;
    float u = fmaxf(f * (1.0f - tiny) + tiny, tiny);
    float gum = -logf(-logf(u));

    float v = logit + gum;

    __shared__ float red[ZDn];
    red[d] = v; __syncthreads();
    for (int s = ZDn / 2; s > 0; s >>= 1) {
        if (d < s) red[d] = fmaxf(red[d], red[d + s]);
        __syncthreads();
    }
    float mx = red[0];
    __syncthreads();
    float e = expf(v - mx);
    red[d] = e; __syncthreads();
    for (int s = ZDn / 2; s > 0; s >>= 1) {
        if (d < s) red[d] += red[d + s];
        __syncthreads();
    }
    float z = e / red[0];

    out[i] = logit;
    out[Bb * ZLn * ZDn + i] = z;
    f16 zh = __float2half_rn(z);
    g_zH[i] = zh;
    g_zL[i] = __float2half_rn(z - __half2float(zh));
}

// ---------------- launch ------------------------------------------------------
static inline float* symf(const void* s) {
    void* p = nullptr;
    cudaGetSymbolAddress(&p, s);
    return (float*)p;
}
static inline f16* symh(const void* s) {
    void* p = nullptr;
    cudaGetSymbolAddress(&p, s);
    return (f16*)p;
}

extern "C" void kernel_launch(void* const* d_in, const int* in_sizes, int n_in,
                              void* d_out, int out_size)
{
    (void)in_sizes; (void)n_in; (void)out_size;
    const float* obs      = (const float*)d_in[0];
    const float* actions  = (const float*)d_in[1];
    const float* enc_w1   = (const float*)d_in[2];
    const float* enc_b1   = (const float*)d_in[3];
    const float* enc_g1   = (const float*)d_in[4];
    const float* enc_bt1  = (const float*)d_in[5];
    const float* enc_w2   = (const float*)d_in[6];
    const float* enc_b2   = (const float*)d_in[7];
    const float* enc_g2   = (const float*)d_in[8];
    const float* enc_bt2  = (const float*)d_in[9];
    const float* je_w     = (const float*)d_in[10];
    const float* je_b     = (const float*)d_in[11];
    const float* gru_wih  = (const float*)d_in[12];
    const float* gru_bih  = (const float*)d_in[13];
    const float* gru_whh  = (const float*)d_in[14];
    const float* gru_bhh  = (const float*)d_in[15];
    const float* dec_w1   = (const float*)d_in[16];
    const float* dec_b1   = (const float*)d_in[17];
    const float* dec_g1   = (const float*)d_in[18];
    const float* dec_bt1  = (const float*)d_in[19];
    const float* dec_w2   = (const float*)d_in[20];
    const float* dec_b2   = (const float*)d_in[21];
    const float* dec_g2   = (const float*)d_in[22];
    const float* dec_bt2  = (const float*)d_in[23];
    float* out = (float*)d_out;

    float* p_h1 = symf(g_h1);
    float* p_x  = symf(g_x);
    float* p_gi = symf(g_gi);
    float* p_d1 = symf(g_d1);
    float* p_d2 = symf(g_d2);
    float* p_m  = symf(g_mean);
    float* p_v  = symf(g_var);
    float* p_ws = symf(g_wscan);

    f16 *p_obsH = symh(g_obsH), *p_obsL = symh(g_obsL);
    f16 *p_w1 = symh(g_w1);
    f16 *p_h1H = symh(g_h1H), *p_h1L = symh(g_h1L);
    f16 *p_w2 = symh(g_w2);
    f16 *p_xH = symh(g_xH), *p_xL = symh(g_xL);
    f16 *p_wih = symh(g_wih);
    f16 *p_zH = symh(g_zH), *p_zL = symh(g_zL);
    f16 *p_d1H = symh(g_d1H), *p_d1L = symh(g_d1L);
    f16 *p_dw1 = symh(g_dw1);
    f16 *p_dw2 = symh(g_dw2);

    static cudaStream_t sSide = nullptr;
    static cudaEvent_t evFork = nullptr, evJoin = nullptr;
    static bool attrDone = false;
    if (!attrDone) {
        cudaFuncSetAttribute(mma_gemm16, cudaFuncAttributeMaxDynamicSharedMemorySize, SM16_BYTES);
        cudaFuncSetAttribute(mma_scan_persist, cudaFuncAttributeMaxDynamicSharedMemorySize, SSM_BYTES);
        cudaStreamCreateWithFlags(&sSide, cudaStreamNonBlocking);
        cudaEventCreateWithFlags(&evFork, cudaEventDisableTiming);
        cudaEventCreateWithFlags(&evJoin, cudaEventDisableTiming);
        attrDone = true;
    }

    dim3 blk(256);
    dim3 statsBlk(32, 8);

    // ================== FORK: side stream does setup work =====================
    cudaEventRecord(evFork, 0);
    cudaStreamWaitEvent(sSide, evFork, 0);

    cvt16_w<<<(Dd * Hh / 4 + 255) / 256, blk, 0, sSide>>>(enc_w2, p_w2, Dd * Hh / 4);
    cvt16_w<<<(3 * Dd * Dd / 4 + 255) / 256, blk, 0, sSide>>>(gru_wih, p_wih, 3 * Dd * Dd / 4);
    cvt16_w<<<(Hh * Dd / 4 + 255) / 256, blk, 0, sSide>>>(dec_w1, p_dw1, Hh * Dd / 4);
    cvt16_w<<<(OBSn * Hh / 4 + 255) / 256, blk, 0, sSide>>>(dec_w2, p_dw2, OBSn * Hh / 4);
    {
        dim3 grid(Dd / 128, 3 * Dd / 128);
        sgemm_ab<<<grid, blk, 0, sSide>>>(gru_whh, je_w, p_ws, 3 * Dd, Dd, Dd, Dd, JEW_LD, Dd);
        copy_jew<<<(Dd * Dd + 255) / 256, blk, 0, sSide>>>(je_w);
        m2c_k<<<3 * Dd, 128, 0, sSide>>>(gru_whh, je_w, je_b, gru_bhh);
        cvt16_perm_ws<<<(4 * Dd * Dd / 4 + 255) / 256, blk, 0, sSide>>>();
    }
    zero_h<<<(Bb * Dd + 255) / 256, blk, 0, sSide>>>();
    cudaEventRecord(evJoin, sSide);

    // main chain: obs/w1 cvt -> enc1
    cvt16_a<<<(BT * OBSn / 4 + 255) / 256, blk>>>(obs, p_obsH, p_obsL, BT * OBSn / 4);
    cvt16_w<<<(Hh * OBSn / 4 + 255) / 256, blk>>>(enc_w1, p_w1, Hh * OBSn / 4);

    // ---- encoder layer 1 (fp16 2-term) ----
    {
        dim3 grid(Hh / 128, BT / 128);
        mma_gemm16<<<grid, blk, SM16_BYTES>>>(p_obsH, p_obsL, p_w1, enc_b1, p_h1,
                                              BT, Hh, OBSn);
        col_stats<<<Hh / 32, statsBlk>>>(p_h1, BT, Hh, p_m, p_v);
        bn_apply_cvt16<<<(BT * Hh / 4 + 255) / 256, blk>>>(p_h1, nullptr, p_h1H, p_h1L,
                                                           p_m, p_v, enc_g1, enc_bt1,
                                                           BT * Hh / 4, Hh, 1);
    }

    // ================== JOIN ==================================================
    cudaStreamWaitEvent(0, evJoin, 0);

    // ---- encoder layer 2 (fp16 2-term) ----
    {
        dim3 grid(Dd / 128, BT / 128);
        mma_gemm16<<<grid, blk, SM16_BYTES>>>(p_h1H, p_h1L, p_w2, enc_b2, p_x,
                                              BT, Dd, Hh);
        col_stats<<<Dd / 32, statsBlk>>>(p_x, BT, Dd, p_m, p_v);
        bn_apply_cvt16<<<(BT * Dd / 4 + 255) / 256, blk>>>(p_x, p_x, p_xH, p_xL,
                                                           p_m, p_v, enc_g2, enc_bt2,
                                                           BT * Dd / 4, Dd, 0);
    }
    // ---- gi (fp16 2-term) ----
    {
        dim3 grid(3 * Dd / 128, BT / 128);
        mma_gemm16<<<grid, blk, SM16_BYTES>>>(p_xH, p_xL, p_wih, gru_bih, p_gi,
                                              BT, 3 * Dd, Dd);
    }
    // ---- recurrent scan: ONE persistent kernel (fp16 2-term) ----
    {
        dim3 gridS(4 * Dd / 64, Bb / 128);   // (64, 2) = 128 CTAs, all resident
        mma_scan_persist<<<gridS, blk, SSM_BYTES>>>(actions, je_w, je_b);
    }
    // ---- gumbel softmax ----
    gumbel_softmax_k<<<Bb * ZLn, ZDn>>>(out);
    // ---- decoder layer 1 (fp16 2-term) ----
    {
        dim3 grid(Hh / 128, Bb / 128);
        mma_gemm16<<<grid, blk, SM16_BYTES>>>(p_zH, p_zL, p_dw1, dec_b1, p_d1,
                                              Bb, Hh, Dd);
        col_stats<<<Hh / 32, statsBlk>>>(p_d1, Bb, Hh, p_m, p_v);
        bn_apply_cvt16<<<(Bb * Hh / 4 + 255) / 256, blk>>>(p_d1, nullptr, p_d1H, p_d1L,
                                                           p_m, p_v, dec_g1, dec_bt1,
                                                           Bb * Hh / 4, Hh, 1);
    }
    // ---- decoder layer 2 (fp16 2-term) -> x_hat ----
    {
        dim3 grid(OBSn / 128, Bb / 128);
        mma_gemm16<<<grid, blk, SM16_BYTES>>>(p_d1H, p_d1L, p_dw2, dec_b2, p_d2,
                                              Bb, OBSn, Hh);
        col_stats<<<OBSn / 32, statsBlk>>>(p_d2, Bb, OBSn, p_m, p_v);
        int total = Bb * OBSn;
        bn_apply<<<(total + 255) / 256, blk>>>(p_d2, out + 2 * Bb * ZLn * ZDn,
                                               p_m, p_v, dec_g2, dec_bt2, total, OBSn, 0);
    }
}

// round 14
// speedup vs baseline: 2.8592x; 1.2529x over previous
#include <cuda_runtime.h>
#include <cuda_bf16.h>
#include <cuda_fp16.h>
#include <cstdint>

#define Bb   256
#define Tt   64
#define OBSn 4096
#define Dd   1024
#define Aa   8
#define Hh   2048
#define ZLn  4
#define ZDn  256
#define BT   (Bb*Tt)          // 16384
#define EPSf 1e-5f
#define JEW_LD (Dd + Aa)      // 1032

typedef __half f16;

// ---------------- scratch (static device globals; no allocation) -------------
__device__ float g_h1[BT * Hh];
__device__ float g_x [BT * Dd];
__device__ float g_gi[BT * 3 * Dd];
__device__ float g_h [Bb * Dd];
__device__ float g_d1[Bb * Hh];
__device__ float g_d2[Bb * OBSn];
__device__ float g_mean[4096];
__device__ float g_var [4096];
__device__ float g_wscan[4 * Dd * Dd];
__device__ float g_M2[3 * Dd * Aa];
__device__ float g_c [3 * Dd];
__device__ unsigned g_bar_cnt;

// fp16 buffers: FF path single-digit A and B
__device__ f16 g_obsH[BT * OBSn];
__device__ f16 g_w1  [Hh * OBSn];
__device__ f16 g_h1H [BT * Hh];
__device__ f16 g_w2  [Dd * Hh];
__device__ f16 g_xH  [BT * Dd];
__device__ f16 g_wih [3 * Dd * Dd];
__device__ f16 g_zH  [Bb * Dd];
__device__ f16 g_d1H [Bb * Hh];
__device__ f16 g_dw1 [Hh * Dd];
__device__ f16 g_dw2 [OBSn * Hh];
// scan (fp16 2-term): h 2-digit, W_scan permuted 1-digit
__device__ f16 g_wsf [4 * Dd * Dd];               // PERMUTED rows 4d+comp
__device__ f16 g_hH  [Bb * Dd],   g_hL  [Bb * Dd];

// ======================= PTX helpers =========================================
__device__ __forceinline__ uint32_t smem_u32(const void* p) {
    uint32_t a;
    asm("{ .reg .u64 t; cvta.to.shared.u64 t, %1; cvt.u32.u64 %0, t; }"
        : "=r"(a) : "l"(p));
    return a;
}
__device__ __forceinline__ void cp16(uint32_t s, const void* g) {
    asm volatile("cp.async.cg.shared.global [%0], [%1], 16;" :: "r"(s), "l"(g));
}
__device__ __forceinline__ void cp_commit() {
    asm volatile("cp.async.commit_group;" ::: "memory");
}
__device__ __forceinline__ void cp_wait0() {
    asm volatile("cp.async.wait_group 0;" ::: "memory");
}
__device__ __forceinline__ void cp_wait1() {
    asm volatile("cp.async.wait_group 1;" ::: "memory");
}
__device__ __forceinline__ void cp_wait2() {
    asm volatile("cp.async.wait_group 2;" ::: "memory");
}
__device__ __forceinline__ void ldm_x4(uint32_t* r, uint32_t a) {
    asm volatile("ldmatrix.sync.aligned.m8n8.x4.shared.b16 {%0,%1,%2,%3}, [%4];"
                 : "=r"(r[0]), "=r"(r[1]), "=r"(r[2]), "=r"(r[3]) : "r"(a));
}
__device__ __forceinline__ void mma_f16(float* c, const uint32_t* a, const uint32_t* b) {
    asm volatile("mma.sync.aligned.m16n8k16.row.col.f32.f16.f16.f32 "
                 "{%0,%1,%2,%3}, {%4,%5,%6,%7}, {%8,%9}, {%0,%1,%2,%3};"
                 : "+f"(c[0]), "+f"(c[1]), "+f"(c[2]), "+f"(c[3])
                 : "r"(a[0]), "r"(a[1]), "r"(a[2]), "r"(a[3]),
                   "r"(b[0]), "r"(b[1]));
}

// ============ fp16 GEMM: C = A @ B^T (+bias), 3-stage ========================
// A: MxK fp16; B: NxK fp16; C: MxN fp32. M%128==0, N%128==0, K%32==0.
#define LD2   40
#define TILE2 (128 * LD2)
#define STG16 (2 * TILE2)              // A, B
#define SM16_BYTES (3 * STG16 * 2)     // 61440

__global__ void __launch_bounds__(256)
mma_gemm16(const f16* __restrict__ A, const f16* __restrict__ B,
           const float* __restrict__ bias, float* __restrict__ C,
           int M, int N, int K)
{
    extern __shared__ f16 smh[];

    const int tid = threadIdx.x;
    const int wid = tid >> 5, lane = tid & 31;
    const int wm = wid >> 2, wn = wid & 3;
    const int rowBase = blockIdx.y * 128, colBase = blockIdx.x * 128;
    const int NC = K >> 5;

    float acc[4][4][4];
#pragma unroll
    for (int i = 0; i < 4; i++)
#pragma unroll
        for (int j = 0; j < 4; j++)
#pragma unroll
            for (int k = 0; k < 4; k++) acc[i][j][k] = 0.f;

    const f16* srcs[2] = { A, B };
    const int  rbs [2] = { rowBase, colBase };

    auto load = [&](int c, int st) {
        const int koff = c << 5;
        f16* stp = smh + st * STG16;
#pragma unroll
        for (int tI = 0; tI < 2; tI++) {
#pragma unroll
            for (int i = 0; i < 2; i++) {
                int u = tid * 2 + i;
                int row = u >> 2;
                int seg = (u & 3) << 3;
                cp16(smem_u32(stp + tI * TILE2 + row * LD2 + seg),
                     srcs[tI] + (size_t)(rbs[tI] + row) * K + koff + seg);
            }
        }
        cp_commit();
    };

    load(0, 0);
    load(1, 1);
    for (int c = 0; c < NC; c++) {
        const int st = c % 3;
        if (c + 2 < NC) { load(c + 2, (c + 2) % 3); cp_wait2(); }
        else if (c + 1 < NC) cp_wait1();
        else cp_wait0();
        __syncthreads();

        const f16* stp = smh + st * STG16;
#pragma unroll
        for (int kh = 0; kh < 2; kh++) {
            const int kcol = kh << 4;
            uint32_t a[4][4];
            uint32_t b[4][2];
            {
                const f16* base = stp;
#pragma unroll
                for (int mt = 0; mt < 4; mt++) {
                    int r = wm * 64 + mt * 16 + (lane & 15);
                    int cc = kcol + ((lane >> 4) << 3);
                    ldm_x4(a[mt], smem_u32(base + r * LD2 + cc));
                }
            }
            {
                const f16* base = stp + TILE2;
#pragma unroll
                for (int np = 0; np < 2; np++) {
                    int r = wn * 32 + (np * 2 + (lane >> 4)) * 8 + (lane & 7);
                    int cc = kcol + (((lane >> 3) & 1) << 3);
                    uint32_t rr[4];
                    ldm_x4(rr, smem_u32(base + r * LD2 + cc));
                    b[np * 2][0] = rr[0];     b[np * 2][1] = rr[1];
                    b[np * 2 + 1][0] = rr[2]; b[np * 2 + 1][1] = rr[3];
                }
            }
#pragma unroll
            for (int mt = 0; mt < 4; mt++)
#pragma unroll
                for (int nt = 0; nt < 4; nt++)
                    mma_f16(acc[mt][nt], a[mt], b[nt]);
        }
        __syncthreads();
    }

#pragma unroll
    for (int mt = 0; mt < 4; mt++) {
        const int row = rowBase + wm * 64 + mt * 16 + (lane >> 2);
#pragma unroll
        for (int nt = 0; nt < 4; nt++) {
            const int col = colBase + wn * 32 + nt * 8 + (lane & 3) * 2;
            float b0 = bias ? bias[col] : 0.f;
            float b1 = bias ? bias[col + 1] : 0.f;
            *(float2*)(C + (size_t)row * N + col) =
                make_float2(acc[mt][nt][0] + b0, acc[mt][nt][1] + b1);
            *(float2*)(C + (size_t)(row + 8) * N + col) =
                make_float2(acc[mt][nt][2] + b0, acc[mt][nt][3] + b1);
        }
    }
}

// =================== persistent fused scan (fp16 2-term, unchanged) ==========
#define SLD    40
#define SATILE (128 * SLD)
#define SBTILE (64 * SLD)
#define SSTAGE (2 * SATILE + SBTILE)
#define SSM_BYTES (2 * SSTAGE * 2)     // 51200
#define SLDF   68
#define NCTA_SCAN 128

__device__ __forceinline__ float sigmoidf_(float x) { return 1.f / (1.f + expf(-x)); }

__global__ void __launch_bounds__(256)
mma_scan_persist(const float* __restrict__ actions,
                 const float* __restrict__ je_w,
                 const float* __restrict__ je_b)
{
    extern __shared__ f16 ssm[];

    const int tid = threadIdx.x;
    const int wid = tid >> 5, lane = tid & 31;
    const int wm = wid & 3;
    const int wn = wid >> 2;
    const int rowBase = blockIdx.y * 128;
    const int colBase = blockIdx.x * 64;
    const int NC = Dd >> 5;   // 32

    const int dl = tid & 15;
    const int rg = tid >> 4;
    const int dg = (colBase >> 2) + dl;
    const float c0 = g_c[dg], c1 = g_c[Dd + dg], c2 = g_c[2 * Dd + dg];
    const float jb = je_b[dg];
    float m2r[8], m2z[8], m2n[8], jea[8];
#pragma unroll
    for (int j = 0; j < 8; j++) {
        m2r[j] = g_M2[(size_t)dg * 8 + j];
        m2z[j] = g_M2[(size_t)(Dd + dg) * 8 + j];
        m2n[j] = g_M2[(size_t)(2 * Dd + dg) * 8 + j];
        jea[j] = je_w[(size_t)dg * JEW_LD + Dd + j];
    }

    auto load = [&](int c, int st) {
        const int koff = c << 5;
        f16* stp = ssm + st * SSTAGE;
#pragma unroll
        for (int tI = 0; tI < 2; tI++) {
            const f16* src = tI ? g_hL : g_hH;
#pragma unroll
            for (int i = 0; i < 2; i++) {
                int u = tid * 2 + i;
                int row = u >> 2;
                int seg = (u & 3) << 3;
                cp16(smem_u32(stp + tI * SATILE + row * SLD + seg),
                     src + (size_t)(rowBase + row) * Dd + koff + seg);
            }
        }
        {
            int row = tid >> 2;
            int seg = (tid & 3) << 3;
            cp16(smem_u32(stp + 2 * SATILE + row * SLD + seg),
                 g_wsf + (size_t)(colBase + row) * Dd + koff + seg);
        }
        cp_commit();
    };

    for (int t = 0; t < Tt; t++) {
        float acc[2][4][4];
#pragma unroll
        for (int i = 0; i < 2; i++)
#pragma unroll
            for (int j = 0; j < 4; j++)
#pragma unroll
                for (int k = 0; k < 4; k++) acc[i][j][k] = 0.f;

        load(0, 0);
        int st = 0;
        for (int c = 0; c < NC; c++) {
            const bool more = (c + 1) < NC;
            if (more) { load(c + 1, st ^ 1); cp_wait1(); }
            else      { cp_wait0(); }
            __syncthreads();

            const f16* stp = ssm + st * SSTAGE;
#pragma unroll
            for (int kh = 0; kh < 2; kh++) {
                const int kcol = kh << 4;
                uint32_t a[2][2][4];
                uint32_t b[4][2];
#pragma unroll
                for (int tI = 0; tI < 2; tI++) {
                    const f16* base = stp + tI * SATILE;
#pragma unroll
                    for (int mt = 0; mt < 2; mt++) {
                        int r = wm * 32 + mt * 16 + (lane & 15);
                        int cc = kcol + ((lane >> 4) << 3);
                        ldm_x4(a[tI][mt], smem_u32(base + r * SLD + cc));
                    }
                }
                {
                    const f16* base = stp + 2 * SATILE;
#pragma unroll
                    for (int np = 0; np < 2; np++) {
                        int r = wn * 32 + (np * 2 + (lane >> 4)) * 8 + (lane & 7);
                        int cc = kcol + (((lane >> 3) & 1) << 3);
                        uint32_t rr[4];
                        ldm_x4(rr, smem_u32(base + r * SLD + cc));
                        b[np * 2][0] = rr[0];     b[np * 2][1] = rr[1];
                        b[np * 2 + 1][0] = rr[2]; b[np * 2 + 1][1] = rr[3];
                    }
                }
#pragma unroll
                for (int mt = 0; mt < 2; mt++)
#pragma unroll
                    for (int nt = 0; nt < 4; nt++) {
                        mma_f16(acc[mt][nt], a[0][mt], b[nt]);
                        mma_f16(acc[mt][nt], a[1][mt], b[nt]);
                    }
            }
            __syncthreads();
            st ^= 1;
        }

        float* smf = (float*)ssm;
#pragma unroll
        for (int mt = 0; mt < 2; mt++) {
            const int row = wm * 32 + mt * 16 + (lane >> 2);
#pragma unroll
            for (int nt = 0; nt < 4; nt++) {
                const int col = wn * 32 + nt * 8 + (lane & 3) * 2;
                smf[row * SLDF + col]     = acc[mt][nt][0];
                smf[row * SLDF + col + 1] = acc[mt][nt][1];
                smf[(row + 8) * SLDF + col]     = acc[mt][nt][2];
                smf[(row + 8) * SLDF + col + 1] = acc[mt][nt][3];
            }
        }
        __syncthreads();

        const bool lastStep = (t == Tt - 1);
#pragma unroll
        for (int r8 = 0; r8 < 8; r8++) {
            const int row = rg * 8 + r8;
            const int b = rowBase + row;
            const int trow = b * Tt + t;

            float4 G4 = *(float4*)&smf[row * SLDF + 4 * dl];
            float hr = G4.x + c0;
            float hz = G4.y + c1;
            float hn = G4.z + c2;
            float hj = G4.w + jb;

            const float* a = actions + (size_t)trow * Aa;
#pragma unroll
            for (int j = 0; j < 8; j++) {
                float av = a[j];
                hr = fmaf(av, m2r[j], hr);
                hz = fmaf(av, m2z[j], hz);
                hn = fmaf(av, m2n[j], hn);
                hj = fmaf(av, jea[j], hj);
            }

            const float* gi = g_gi + (size_t)trow * (3 * Dd);
            float r = sigmoidf_(gi[dg] + hr);
            float z = sigmoidf_(gi[Dd + dg] + hz);
            float n = tanhf(gi[2 * Dd + dg] + r * hn);
            float xv = g_x[(size_t)trow * Dd + dg];
            float hnew = (1.f - z) * n + z * hj + xv;

            const int oi = b * Dd + dg;
            if (lastStep) g_h[oi] = hnew;
            f16 hh = __float2half_rn(hnew);
            g_hH[oi] = hh;
            g_hL[oi] = __float2half_rn(hnew - __half2float(hh));
        }

        __syncthreads();
        if (tid == 0) {
            __threadfence();
            atomicAdd(&g_bar_cnt, 1u);
            const unsigned target = (unsigned)(t + 1) * NCTA_SCAN;
            while (atomicAdd(&g_bar_cnt, 0u) < target) {}
            __threadfence();
        }
        __syncthreads();
    }
}

// =============== conversions =================================================
__global__ void cvt16_w(const float* __restrict__ X, f16* __restrict__ Xh, int n4)
{
    int i = blockIdx.x * blockDim.x + threadIdx.x;
    if (i >= n4) return;
    float4 v = ((const float4*)X)[i];
    __half2* H = (__half2*)Xh;
    H[2 * i]     = __halves2half2(__float2half_rn(v.x), __float2half_rn(v.y));
    H[2 * i + 1] = __halves2half2(__float2half_rn(v.z), __float2half_rn(v.w));
}
__global__ void cvt16_perm_ws()
{
    int i = blockIdx.x * blockDim.x + threadIdx.x;
    if (i >= 4 * Dd * Dd / 4) return;
    int flat = i * 4;
    int nrow = flat >> 10;
    int k = flat & 1023;
    int d = nrow >> 2, comp = nrow & 3;
    int orow = (comp < 3) ? comp * Dd + d : 3 * Dd + d;
    float4 v = *(const float4*)&g_wscan[(size_t)orow * Dd + k];
    __half2* H = (__half2*)g_wsf;
    H[2*i]   = __halves2half2(__float2half_rn(v.x), __float2half_rn(v.y));
    H[2*i+1] = __halves2half2(__float2half_rn(v.z), __float2half_rn(v.w));
}

// =============== SIMT GEMM (precompute only) ==================================
#define BKd 8
__global__ void __launch_bounds__(256)
sgemm_ab(const float* __restrict__ A, const float* __restrict__ Bm,
         float* __restrict__ C, int M, int N, int K, int lda, int ldb, int ldc)
{
    __shared__ float As[BKd][128];
    __shared__ float Bs[BKd][128];
    const int tid = threadIdx.x;
    const int tx = tid & 15, ty = tid >> 4;
    const int rowBase = blockIdx.y * 128, colBase = blockIdx.x * 128;
    const int lrA = tid >> 1, lcA = (tid & 1) * 4;
    const int kkB = tid >> 5, c4B = (tid & 31) * 4;
    const float* Aptr = A + (size_t)(rowBase + lrA) * lda + lcA;
    const float* Bptr = Bm + (size_t)kkB * ldb + colBase + c4B;
    float acc[8][8];
#pragma unroll
    for (int i = 0; i < 8; i++)
#pragma unroll
        for (int j = 0; j < 8; j++) acc[i][j] = 0.f;
    for (int k0 = 0; k0 < K; k0 += BKd) {
        float4 av = *(const float4*)(Aptr + k0);
        float4 bv = *(const float4*)(Bptr + (size_t)k0 * ldb);
        As[lcA+0][lrA]=av.x; As[lcA+1][lrA]=av.y;
        As[lcA+2][lrA]=av.z; As[lcA+3][lrA]=av.w;
        *(float4*)&Bs[kkB][c4B] = bv;
        __syncthreads();
#pragma unroll
        for (int kk = 0; kk < BKd; kk++) {
            float a[8], b[8];
#pragma unroll
            for (int i = 0; i < 8; i++) a[i] = As[kk][ty*8+i];
#pragma unroll
            for (int j = 0; j < 8; j++) b[j] = Bs[kk][tx*8+j];
#pragma unroll
            for (int i = 0; i < 8; i++)
#pragma unroll
                for (int j = 0; j < 8; j++)
                    acc[i][j] = fmaf(a[i], b[j], acc[i][j]);
        }
        __syncthreads();
    }
#pragma unroll
    for (int i = 0; i < 8; i++) {
        const int r = rowBase + ty * 8 + i;
#pragma unroll
        for (int j = 0; j < 8; j++)
            C[(size_t)r * ldc + colBase + tx * 8 + j] = acc[i][j];
    }
}

__global__ void copy_jew(const float* __restrict__ je_w)
{
    int idx = blockIdx.x * blockDim.x + threadIdx.x;
    if (idx >= Dd * Dd) return;
    int j = idx >> 10, k = idx & 1023;
    g_wscan[(size_t)(3 * Dd + j) * Dd + k] = je_w[(size_t)j * JEW_LD + k];
}

__global__ void __launch_bounds__(128)
m2c_k(const float* __restrict__ whh, const float* __restrict__ je_w,
      const float* __restrict__ je_b, const float* __restrict__ bhh)
{
    const int i = blockIdx.x;
    const int t = threadIdx.x;
    float acc[9];
#pragma unroll
    for (int j = 0; j < 9; j++) acc[j] = 0.f;
    for (int k = t; k < Dd; k += 128) {
        float w = whh[(size_t)i * Dd + k];
        const float* jr = je_w + (size_t)k * JEW_LD + Dd;
#pragma unroll
        for (int j = 0; j < 8; j++) acc[j] = fmaf(w, jr[j], acc[j]);
        acc[8] = fmaf(w, je_b[k], acc[8]);
    }
    __shared__ float sh[9][128];
#pragma unroll
    for (int j = 0; j < 9; j++) sh[j][t] = acc[j];
    __syncthreads();
    for (int s = 64; s > 0; s >>= 1) {
        if (t < s)
#pragma unroll
            for (int j = 0; j < 9; j++) sh[j][t] += sh[j][t + s];
        __syncthreads();
    }
    if (t == 0) {
#pragma unroll
        for (int j = 0; j < 8; j++) g_M2[i * 8 + j] = sh[j][0];
        g_c[i] = sh[8][0] + bhh[i];
    }
}

// ---------------- batch stats + BN ------------------------------------------
__global__ void col_stats(const float* __restrict__ X, int M, int N,
                          float* __restrict__ mean, float* __restrict__ var)
{
    const int c = blockIdx.x * 32 + threadIdx.x;
    const int ry = threadIdx.y;
    float s = 0.f, s2 = 0.f;
    for (int r = ry; r < M; r += 8) {
        float v = X[(size_t)r * N + c];
        s += v; s2 += v * v;
    }
    __shared__ float sh[8][32], sh2[8][32];
    sh[ry][threadIdx.x] = s; sh2[ry][threadIdx.x] = s2;
    __syncthreads();
    if (ry == 0) {
#pragma unroll
        for (int y = 1; y < 8; y++) { s += sh[y][threadIdx.x]; s2 += sh2[y][threadIdx.x]; }
        float m = s / (float)M;
        mean[c] = m;
        var[c]  = s2 / (float)M - m * m;
    }
}

__global__ void bn_apply(const float* __restrict__ X, float* __restrict__ Y,
                         const float* __restrict__ mean, const float* __restrict__ var,
                         const float* __restrict__ g, const float* __restrict__ beta,
                         int total, int N, int relu)
{
    int idx = blockIdx.x * blockDim.x + threadIdx.x;
    if (idx >= total) return;
    int c = idx % N;
    float v = g[c] * (X[idx] - mean[c]) * rsqrtf(var[c] + EPSf) + beta[c];
    if (relu) v = fmaxf(v, 0.f);
    Y[idx] = v;
}

// BN + optional relu + optional fp32 out + fp16 single-digit out
__global__ void bn_apply_cvt16(const float* __restrict__ X, float* __restrict__ Yf,
                               f16* __restrict__ Yh,
                               const float* __restrict__ mean, const float* __restrict__ var,
                               const float* __restrict__ g, const float* __restrict__ beta,
                               int total4, int N, int relu)
{
    int i = blockIdx.x * blockDim.x + threadIdx.x;
    if (i >= total4) return;
    int c0 = (i * 4) % N;
    float4 v = ((const float4*)X)[i];
    float o[4] = { v.x, v.y, v.z, v.w };
#pragma unroll
    for (int j = 0; j < 4; j++) {
        int c = c0 + j;
        float t = g[c] * (o[j] - mean[c]) * rsqrtf(var[c] + EPSf) + beta[c];
        if (relu) t = fmaxf(t, 0.f);
        o[j] = t;
    }
    if (Yf) ((float4*)Yf)[i] = make_float4(o[0], o[1], o[2], o[3]);
    __half2* H = (__half2*)Yh;
    H[2*i]   = __halves2half2(__float2half_rn(o[0]), __float2half_rn(o[1]));
    H[2*i+1] = __halves2half2(__float2half_rn(o[2]), __float2half_rn(o[3]));
}

// ---------------- misc ------------------------------------------------------
__global__ void zero_h() {
    int idx = blockIdx.x * blockDim.x + threadIdx.x;
    if (idx == 0) g_bar_cnt = 0u;
    if (idx < Bb * Dd) {
        g_h[idx] = 0.f;
        g_hH[idx] = __float2half_rn(0.f);
        g_hL[idx] = __float2half_rn(0.f);
    }
}

// ---------------- threefry2x32-20 (JAX partitionable) ------------------------
__device__ __forceinline__ uint32_t rotl32_(uint32_t x, int r) {
    return (x << r) | (x >> (32 - r));
}
__device__ __forceinline__ void threefry2x32_(uint32_t k0, uint32_t k1,
                                              uint32_t& x0, uint32_t& x1)
{
    const uint32_t k2 = k0 ^ k1 ^ 0x1BD11BDAu;
    x0 += k0; x1 += k1;
#define TF_R4(a,b,c,d) \
    x0 += x1; x1 = rotl32_(x1, a); x1 ^= x0; \
    x0 += x1; x1 = rotl32_(x1, b); x1 ^= x0; \
    x0 += x1; x1 = rotl32_(x1, c); x1 ^= x0; \
    x0 += x1; x1 = rotl32_(x1, d); x1 ^= x0;
    TF_R4(13,15,26,6)  x0 += k1; x1 += k2 + 1u;
    TF_R4(17,29,16,24) x0 += k2; x1 += k0 + 2u;
    TF_R4(13,15,26,6)  x0 += k0; x1 += k1 + 3u;
    TF_R4(17,29,16,24) x0 += k1; x1 += k2 + 4u;
    TF_R4(13,15,26,6)  x0 += k2; x1 += k0 + 5u;
#undef TF_R4
}

__global__ void gumbel_softmax_k(float* __restrict__ out)
{
    const int bl = blockIdx.x;
    const int d  = threadIdx.x;
    const int i  = bl * ZDn + d;
    const float logit = g_h[i];

    uint32_t c0 = 0u;
    uint32_t c1 = (uint32_t)i;
    threefry2x32_(0u, 42u, c0, c1);
    const uint32_t bits = c0 ^ c1;
    float f = __uint_as_float((bits >> 9) | 0x3f800000u) - 1.0f;
    const float tiny = 1.1754943508222875e-38f;
    float u = fmaxf(f * (1.0f - tiny) + tiny, tiny);
    float gum = -logf(-logf(u));

    float v = logit + gum;

    __shared__ float red[ZDn];
    red[d] = v; __syncthreads();
    for (int s = ZDn / 2; s > 0; s >>= 1) {
        if (d < s) red[d] = fmaxf(red[d], red[d + s]);
        __syncthreads();
    }
    float mx = red[0];
    __syncthreads();
    float e = expf(v - mx);
    red[d] = e; __syncthreads();
    for (int s = ZDn / 2; s > 0; s >>= 1) {
        if (d < s) red[d] += red[d + s];
        __syncthreads();
    }
    float z = e / red[0];

    out[i] = logit;
    out[Bb * ZLn * ZDn + i] = z;
    g_zH[i] = __float2half_rn(z);
}

// ---------------- launch ------------------------------------------------------
static inline float* symf(const void* s) {
    void* p = nullptr;
    cudaGetSymbolAddress(&p, s);
    return (float*)p;
}
static inline f16* symh(const void* s) {
    void* p = nullptr;
    cudaGetSymbolAddress(&p, s);
    return (f16*)p;
}

extern "C" void kernel_launch(void* const* d_in, const int* in_sizes, int n_in,
                              void* d_out, int out_size)
{
    (void)in_sizes; (void)n_in; (void)out_size;
    const float* obs      = (const float*)d_in[0];
    const float* actions  = (const float*)d_in[1];
    const float* enc_w1   = (const float*)d_in[2];
    const float* enc_b1   = (const float*)d_in[3];
    const float* enc_g1   = (const float*)d_in[4];
    const float* enc_bt1  = (const float*)d_in[5];
    const float* enc_w2   = (const float*)d_in[6];
    const float* enc_b2   = (const float*)d_in[7];
    const float* enc_g2   = (const float*)d_in[8];
    const float* enc_bt2  = (const float*)d_in[9];
    const float* je_w     = (const float*)d_in[10];
    const float* je_b     = (const float*)d_in[11];
    const float* gru_wih  = (const float*)d_in[12];
    const float* gru_bih  = (const float*)d_in[13];
    const float* gru_whh  = (const float*)d_in[14];
    const float* gru_bhh  = (const float*)d_in[15];
    const float* dec_w1   = (const float*)d_in[16];
    const float* dec_b1   = (const float*)d_in[17];
    const float* dec_g1   = (const float*)d_in[18];
    const float* dec_bt1  = (const float*)d_in[19];
    const float* dec_w2   = (const float*)d_in[20];
    const float* dec_b2   = (const float*)d_in[21];
    const float* dec_g2   = (const float*)d_in[22];
    const float* dec_bt2  = (const float*)d_in[23];
    float* out = (float*)d_out;

    float* p_h1 = symf(g_h1);
    float* p_x  = symf(g_x);
    float* p_gi = symf(g_gi);
    float* p_d1 = symf(g_d1);
    float* p_d2 = symf(g_d2);
    float* p_m  = symf(g_mean);
    float* p_v  = symf(g_var);
    float* p_ws = symf(g_wscan);

    f16 *p_obsH = symh(g_obsH);
    f16 *p_w1 = symh(g_w1);
    f16 *p_h1H = symh(g_h1H);
    f16 *p_w2 = symh(g_w2);
    f16 *p_xH = symh(g_xH);
    f16 *p_wih = symh(g_wih);
    f16 *p_zH = symh(g_zH);
    f16 *p_d1H = symh(g_d1H);
    f16 *p_dw1 = symh(g_dw1);
    f16 *p_dw2 = symh(g_dw2);

    static cudaStream_t sSide = nullptr;
    static cudaEvent_t evFork = nullptr, evJoin = nullptr;
    static bool attrDone = false;
    if (!attrDone) {
        cudaFuncSetAttribute(mma_gemm16, cudaFuncAttributeMaxDynamicSharedMemorySize, SM16_BYTES);
        cudaFuncSetAttribute(mma_scan_persist, cudaFuncAttributeMaxDynamicSharedMemorySize, SSM_BYTES);
        cudaStreamCreateWithFlags(&sSide, cudaStreamNonBlocking);
        cudaEventCreateWithFlags(&evFork, cudaEventDisableTiming);
        cudaEventCreateWithFlags(&evJoin, cudaEventDisableTiming);
        attrDone = true;
    }

    dim3 blk(256);
    dim3 statsBlk(32, 8);

    // ================== FORK: side stream does setup work =====================
    cudaEventRecord(evFork, 0);
    cudaStreamWaitEvent(sSide, evFork, 0);

    cvt16_w<<<(Dd * Hh / 4 + 255) / 256, blk, 0, sSide>>>(enc_w2, p_w2, Dd * Hh / 4);
    cvt16_w<<<(3 * Dd * Dd / 4 + 255) / 256, blk, 0, sSide>>>(gru_wih, p_wih, 3 * Dd * Dd / 4);
    cvt16_w<<<(Hh * Dd / 4 + 255) / 256, blk, 0, sSide>>>(dec_w1, p_dw1, Hh * Dd / 4);
    cvt16_w<<<(OBSn * Hh / 4 + 255) / 256, blk, 0, sSide>>>(dec_w2, p_dw2, OBSn * Hh / 4);
    {
        dim3 grid(Dd / 128, 3 * Dd / 128);
        sgemm_ab<<<grid, blk, 0, sSide>>>(gru_whh, je_w, p_ws, 3 * Dd, Dd, Dd, Dd, JEW_LD, Dd);
        copy_jew<<<(Dd * Dd + 255) / 256, blk, 0, sSide>>>(je_w);
        m2c_k<<<3 * Dd, 128, 0, sSide>>>(gru_whh, je_w, je_b, gru_bhh);
        cvt16_perm_ws<<<(4 * Dd * Dd / 4 + 255) / 256, blk, 0, sSide>>>();
    }
    zero_h<<<(Bb * Dd + 255) / 256, blk, 0, sSide>>>();
    cudaEventRecord(evJoin, sSide);

    // main chain: obs/w1 cvt -> enc1
    cvt16_w<<<(BT * OBSn / 4 + 255) / 256, blk>>>(obs, p_obsH, BT * OBSn / 4);
    cvt16_w<<<(Hh * OBSn / 4 + 255) / 256, blk>>>(enc_w1, p_w1, Hh * OBSn / 4);

    // ---- encoder layer 1 (fp16) ----
    {
        dim3 grid(Hh / 128, BT / 128);
        mma_gemm16<<<grid, blk, SM16_BYTES>>>(p_obsH, p_w1, enc_b1, p_h1, BT, Hh, OBSn);
        col_stats<<<Hh / 32, statsBlk>>>(p_h1, BT, Hh, p_m, p_v);
        bn_apply_cvt16<<<(BT * Hh / 4 + 255) / 256, blk>>>(p_h1, nullptr, p_h1H,
                                                           p_m, p_v, enc_g1, enc_bt1,
                                                           BT * Hh / 4, Hh, 1);
    }

    // ================== JOIN ==================================================
    cudaStreamWaitEvent(0, evJoin, 0);

    // ---- encoder layer 2 (fp16) ----
    {
        dim3 grid(Dd / 128, BT / 128);
        mma_gemm16<<<grid, blk, SM16_BYTES>>>(p_h1H, p_w2, enc_b2, p_x, BT, Dd, Hh);
        col_stats<<<Dd / 32, statsBlk>>>(p_x, BT, Dd, p_m, p_v);
        bn_apply_cvt16<<<(BT * Dd / 4 + 255) / 256, blk>>>(p_x, p_x, p_xH,
                                                           p_m, p_v, enc_g2, enc_bt2,
                                                           BT * Dd / 4, Dd, 0);
    }
    // ---- gi (fp16) ----
    {
        dim3 grid(3 * Dd / 128, BT / 128);
        mma_gemm16<<<grid, blk, SM16_BYTES>>>(p_xH, p_wih, gru_bih, p_gi, BT, 3 * Dd, Dd);
    }
    // ---- recurrent scan: ONE persistent kernel (fp16 2-term) ----
    {
        dim3 gridS(4 * Dd / 64, Bb / 128);   // (64, 2) = 128 CTAs, all resident
        mma_scan_persist<<<gridS, blk, SSM_BYTES>>>(actions, je_w, je_b);
    }
    // ---- gumbel softmax ----
    gumbel_softmax_k<<<Bb * ZLn, ZDn>>>(out);
    // ---- decoder layer 1 (fp16) ----
    {
        dim3 grid(Hh / 128, Bb / 128);
        mma_gemm16<<<grid, blk, SM16_BYTES>>>(p_zH, p_dw1, dec_b1, p_d1, Bb, Hh, Dd);
        col_stats<<<Hh / 32, statsBlk>>>(p_d1, Bb, Hh, p_m, p_v);
        bn_apply_cvt16<<<(Bb * Hh / 4 + 255) / 256, blk>>>(p_d1, nullptr, p_d1H,
                                                           p_m, p_v, dec_g1, dec_bt1,
                                                           Bb * Hh / 4, Hh, 1);
    }
    // ---- decoder layer 2 (fp16) -> x_hat ----
    {
        dim3 grid(OBSn / 128, Bb / 128);
        mma_gemm16<<<grid, blk, SM16_BYTES>>>(p_d1H, p_dw2, dec_b2, p_d2, Bb, OBSn, Hh);
        col_stats<<<OBSn / 32, statsBlk>>>(p_d2, Bb, OBSn, p_m, p_v);
        int total = Bb * OBSn;
        bn_apply<<<(total + 255) / 256, blk>>>(p_d2, out + 2 * Bb * ZLn * ZDn,
                                               p_m, p_v, dec_g2, dec_bt2, total, OBSn, 0);
    }
}

// round 16
// speedup vs baseline: 3.2739x; 1.1450x over previous
#include <cuda_runtime.h>
#include <cuda_bf16.h>
#include <cuda_fp16.h>
#include <cstdint>

#define Bb   256
#define Tt   64
#define OBSn 4096
#define Dd   1024
#define Aa   8
#define Hh   2048
#define ZLn  4
#define ZDn  256
#define BT   (Bb*Tt)          // 16384
#define EPSf 1e-5f
#define JEW_LD (Dd + Aa)      // 1032

typedef __half f16;

// ---------------- scratch (static device globals; no allocation) -------------
__device__ float g_h1[BT * Hh];
__device__ float g_x [BT * Dd];
__device__ float g_gi[BT * 3 * Dd];
__device__ float g_h [Bb * Dd];
__device__ float g_d1[Bb * Hh];
__device__ float g_d2[Bb * OBSn];
__device__ float g_mean[4096];
__device__ float g_var [4096];
__device__ float g_wscan[4 * Dd * Dd];
__device__ float g_M2[3 * Dd * Aa];
__device__ float g_c [3 * Dd];
__device__ unsigned g_bar_cnt;

// fp16 buffers (single-digit throughout)
__device__ f16 g_obsH[BT * OBSn];
__device__ f16 g_w1  [Hh * OBSn];
__device__ f16 g_h1H [BT * Hh];
__device__ f16 g_w2  [Dd * Hh];
__device__ f16 g_xH  [BT * Dd];
__device__ f16 g_wih [3 * Dd * Dd];
__device__ f16 g_zH  [Bb * Dd];
__device__ f16 g_d1H [Bb * Hh];
__device__ f16 g_dw1 [Hh * Dd];
__device__ f16 g_dw2 [OBSn * Hh];
__device__ f16 g_wsf [4 * Dd * Dd];               // PERMUTED rows 4d+comp
__device__ f16 g_hH  [Bb * Dd];

// ======================= PTX helpers =========================================
__device__ __forceinline__ uint32_t smem_u32(const void* p) {
    uint32_t a;
    asm("{ .reg .u64 t; cvta.to.shared.u64 t, %1; cvt.u32.u64 %0, t; }"
        : "=r"(a) : "l"(p));
    return a;
}
__device__ __forceinline__ void cp16(uint32_t s, const void* g) {
    asm volatile("cp.async.cg.shared.global [%0], [%1], 16;" :: "r"(s), "l"(g));
}
__device__ __forceinline__ void cp_commit() {
    asm volatile("cp.async.commit_group;" ::: "memory");
}
__device__ __forceinline__ void cp_wait0() {
    asm volatile("cp.async.wait_group 0;" ::: "memory");
}
__device__ __forceinline__ void cp_wait1() {
    asm volatile("cp.async.wait_group 1;" ::: "memory");
}
__device__ __forceinline__ void cp_wait2() {
    asm volatile("cp.async.wait_group 2;" ::: "memory");
}
__device__ __forceinline__ void ldm_x4(uint32_t* r, uint32_t a) {
    asm volatile("ldmatrix.sync.aligned.m8n8.x4.shared.b16 {%0,%1,%2,%3}, [%4];"
                 : "=r"(r[0]), "=r"(r[1]), "=r"(r[2]), "=r"(r[3]) : "r"(a));
}
__device__ __forceinline__ void mma_f16(float* c, const uint32_t* a, const uint32_t* b) {
    asm volatile("mma.sync.aligned.m16n8k16.row.col.f32.f16.f16.f32 "
                 "{%0,%1,%2,%3}, {%4,%5,%6,%7}, {%8,%9}, {%0,%1,%2,%3};"
                 : "+f"(c[0]), "+f"(c[1]), "+f"(c[2]), "+f"(c[3])
                 : "r"(a[0]), "r"(a[1]), "r"(a[2]), "r"(a[3]),
                   "r"(b[0]), "r"(b[1]));
}

// ============ fp16 GEMM: C = A @ B^T (+bias), 3-stage ========================
#define LD2   40
#define TILE2 (128 * LD2)
#define STG16 (2 * TILE2)              // A, B
#define SM16_BYTES (3 * STG16 * 2)     // 61440

__global__ void __launch_bounds__(256)
mma_gemm16(const f16* __restrict__ A, const f16* __restrict__ B,
           const float* __restrict__ bias, float* __restrict__ C,
           int M, int N, int K)
{
    extern __shared__ f16 smh[];

    const int tid = threadIdx.x;
    const int wid = tid >> 5, lane = tid & 31;
    const int wm = wid >> 2, wn = wid & 3;
    const int rowBase = blockIdx.y * 128, colBase = blockIdx.x * 128;
    const int NC = K >> 5;

    float acc[4][4][4];
#pragma unroll
    for (int i = 0; i < 4; i++)
#pragma unroll
        for (int j = 0; j < 4; j++)
#pragma unroll
            for (int k = 0; k < 4; k++) acc[i][j][k] = 0.f;

    const f16* srcs[2] = { A, B };
    const int  rbs [2] = { rowBase, colBase };

    auto load = [&](int c, int st) {
        const int koff = c << 5;
        f16* stp = smh + st * STG16;
#pragma unroll
        for (int tI = 0; tI < 2; tI++) {
#pragma unroll
            for (int i = 0; i < 2; i++) {
                int u = tid * 2 + i;
                int row = u >> 2;
                int seg = (u & 3) << 3;
                cp16(smem_u32(stp + tI * TILE2 + row * LD2 + seg),
                     srcs[tI] + (size_t)(rbs[tI] + row) * K + koff + seg);
            }
        }
        cp_commit();
    };

    load(0, 0);
    load(1, 1);
    for (int c = 0; c < NC; c++) {
        const int st = c % 3;
        if (c + 2 < NC) { load(c + 2, (c + 2) % 3); cp_wait2(); }
        else if (c + 1 < NC) cp_wait1();
        else cp_wait0();
        __syncthreads();

        const f16* stp = smh + st * STG16;
#pragma unroll
        for (int kh = 0; kh < 2; kh++) {
            const int kcol = kh << 4;
            uint32_t a[4][4];
            uint32_t b[4][2];
            {
                const f16* base = stp;
#pragma unroll
                for (int mt = 0; mt < 4; mt++) {
                    int r = wm * 64 + mt * 16 + (lane & 15);
                    int cc = kcol + ((lane >> 4) << 3);
                    ldm_x4(a[mt], smem_u32(base + r * LD2 + cc));
                }
            }
            {
                const f16* base = stp + TILE2;
#pragma unroll
                for (int np = 0; np < 2; np++) {
                    int r = wn * 32 + (np * 2 + (lane >> 4)) * 8 + (lane & 7);
                    int cc = kcol + (((lane >> 3) & 1) << 3);
                    uint32_t rr[4];
                    ldm_x4(rr, smem_u32(base + r * LD2 + cc));
                    b[np * 2][0] = rr[0];     b[np * 2][1] = rr[1];
                    b[np * 2 + 1][0] = rr[2]; b[np * 2 + 1][1] = rr[3];
                }
            }
#pragma unroll
            for (int mt = 0; mt < 4; mt++)
#pragma unroll
                for (int nt = 0; nt < 4; nt++)
                    mma_f16(acc[mt][nt], a[mt], b[nt]);
        }
        __syncthreads();
    }

#pragma unroll
    for (int mt = 0; mt < 4; mt++) {
        const int row = rowBase + wm * 64 + mt * 16 + (lane >> 2);
#pragma unroll
        for (int nt = 0; nt < 4; nt++) {
            const int col = colBase + wn * 32 + nt * 8 + (lane & 3) * 2;
            float b0 = bias ? bias[col] : 0.f;
            float b1 = bias ? bias[col + 1] : 0.f;
            *(float2*)(C + (size_t)row * N + col) =
                make_float2(acc[mt][nt][0] + b0, acc[mt][nt][1] + b1);
            *(float2*)(C + (size_t)(row + 8) * N + col) =
                make_float2(acc[mt][nt][2] + b0, acc[mt][nt][3] + b1);
        }
    }
}

// =================== persistent fused scan (fp16 single-digit h) =============
#define SLD    40
#define SATILE (128 * SLD)
#define SBTILE (64 * SLD)
#define SSTAGE (SATILE + SBTILE)
// smem must cover BOTH: pipeline (2*SSTAGE halves = 30720 B) AND the fp32
// epilogue staging tile (128 * SLDF * 4 = 34816 B). Take the max, padded.
#define SLDF   68
#define SSM_BYTES 35840
#define NCTA_SCAN 128

__device__ __forceinline__ float sigmoidf_(float x) { return 1.f / (1.f + expf(-x)); }

__global__ void __launch_bounds__(256)
mma_scan_persist(const float* __restrict__ actions,
                 const float* __restrict__ je_w,
                 const float* __restrict__ je_b)
{
    extern __shared__ f16 ssm[];

    const int tid = threadIdx.x;
    const int wid = tid >> 5, lane = tid & 31;
    const int wm = wid & 3;
    const int wn = wid >> 2;
    const int rowBase = blockIdx.y * 128;
    const int colBase = blockIdx.x * 64;
    const int NC = Dd >> 5;   // 32

    const int dl = tid & 15;
    const int rg = tid >> 4;
    const int dg = (colBase >> 2) + dl;
    const float c0 = g_c[dg], c1 = g_c[Dd + dg], c2 = g_c[2 * Dd + dg];
    const float jb = je_b[dg];
    float m2r[8], m2z[8], m2n[8], jea[8];
#pragma unroll
    for (int j = 0; j < 8; j++) {
        m2r[j] = g_M2[(size_t)dg * 8 + j];
        m2z[j] = g_M2[(size_t)(Dd + dg) * 8 + j];
        m2n[j] = g_M2[(size_t)(2 * Dd + dg) * 8 + j];
        jea[j] = je_w[(size_t)dg * JEW_LD + Dd + j];
    }

    auto load = [&](int c, int st) {
        const int koff = c << 5;
        f16* stp = ssm + st * SSTAGE;
        {
#pragma unroll
            for (int i = 0; i < 2; i++) {
                int u = tid * 2 + i;
                int row = u >> 2;
                int seg = (u & 3) << 3;
                cp16(smem_u32(stp + row * SLD + seg),
                     g_hH + (size_t)(rowBase + row) * Dd + koff + seg);
            }
        }
        {
            int row = tid >> 2;
            int seg = (tid & 3) << 3;
            cp16(smem_u32(stp + SATILE + row * SLD + seg),
                 g_wsf + (size_t)(colBase + row) * Dd + koff + seg);
        }
        cp_commit();
    };

    for (int t = 0; t < Tt; t++) {
        float acc[2][4][4];
#pragma unroll
        for (int i = 0; i < 2; i++)
#pragma unroll
            for (int j = 0; j < 4; j++)
#pragma unroll
                for (int k = 0; k < 4; k++) acc[i][j][k] = 0.f;

        load(0, 0);
        int st = 0;
        for (int c = 0; c < NC; c++) {
            const bool more = (c + 1) < NC;
            if (more) { load(c + 1, st ^ 1); cp_wait1(); }
            else      { cp_wait0(); }
            __syncthreads();

            const f16* stp = ssm + st * SSTAGE;
#pragma unroll
            for (int kh = 0; kh < 2; kh++) {
                const int kcol = kh << 4;
                uint32_t a[2][4];
                uint32_t b[4][2];
                {
#pragma unroll
                    for (int mt = 0; mt < 2; mt++) {
                        int r = wm * 32 + mt * 16 + (lane & 15);
                        int cc = kcol + ((lane >> 4) << 3);
                        ldm_x4(a[mt], smem_u32(stp + r * SLD + cc));
                    }
                }
                {
                    const f16* base = stp + SATILE;
#pragma unroll
                    for (int np = 0; np < 2; np++) {
                        int r = wn * 32 + (np * 2 + (lane >> 4)) * 8 + (lane & 7);
                        int cc = kcol + (((lane >> 3) & 1) << 3);
                        uint32_t rr[4];
                        ldm_x4(rr, smem_u32(base + r * SLD + cc));
                        b[np * 2][0] = rr[0];     b[np * 2][1] = rr[1];
                        b[np * 2 + 1][0] = rr[2]; b[np * 2 + 1][1] = rr[3];
                    }
                }
#pragma unroll
                for (int mt = 0; mt < 2; mt++)
#pragma unroll
                    for (int nt = 0; nt < 4; nt++)
                        mma_f16(acc[mt][nt], a[mt], b[nt]);
            }
            __syncthreads();
            st ^= 1;
        }

        float* smf = (float*)ssm;
#pragma unroll
        for (int mt = 0; mt < 2; mt++) {
            const int row = wm * 32 + mt * 16 + (lane >> 2);
#pragma unroll
            for (int nt = 0; nt < 4; nt++) {
                const int col = wn * 32 + nt * 8 + (lane & 3) * 2;
                smf[row * SLDF + col]     = acc[mt][nt][0];
                smf[row * SLDF + col + 1] = acc[mt][nt][1];
                smf[(row + 8) * SLDF + col]     = acc[mt][nt][2];
                smf[(row + 8) * SLDF + col + 1] = acc[mt][nt][3];
            }
        }
        __syncthreads();

        const bool lastStep = (t == Tt - 1);
#pragma unroll
        for (int r8 = 0; r8 < 8; r8++) {
            const int row = rg * 8 + r8;
            const int b = rowBase + row;
            const int trow = b * Tt + t;

            float4 G4 = *(float4*)&smf[row * SLDF + 4 * dl];
            float hr = G4.x + c0;
            float hz = G4.y + c1;
            float hn = G4.z + c2;
            float hj = G4.w + jb;

            const float* a = actions + (size_t)trow * Aa;
#pragma unroll
            for (int j = 0; j < 8; j++) {
                float av = a[j];
                hr = fmaf(av, m2r[j], hr);
                hz = fmaf(av, m2z[j], hz);
                hn = fmaf(av, m2n[j], hn);
                hj = fmaf(av, jea[j], hj);
            }

            const float* gi = g_gi + (size_t)trow * (3 * Dd);
            float r = sigmoidf_(gi[dg] + hr);
            float z = sigmoidf_(gi[Dd + dg] + hz);
            float n = tanhf(gi[2 * Dd + dg] + r * hn);
            float xv = g_x[(size_t)trow * Dd + dg];
            float hnew = (1.f - z) * n + z * hj + xv;

            const int oi = b * Dd + dg;
            if (lastStep) g_h[oi] = hnew;
            g_hH[oi] = __float2half_rn(hnew);
        }

        __syncthreads();
        if (tid == 0) {
            __threadfence();
            atomicAdd(&g_bar_cnt, 1u);
            const unsigned target = (unsigned)(t + 1) * NCTA_SCAN;
            while (atomicAdd(&g_bar_cnt, 0u) < target) {}
            __threadfence();
        }
        __syncthreads();
    }
}

// =============== conversions =================================================
__global__ void cvt16_w(const float* __restrict__ X, f16* __restrict__ Xh, int n4)
{
    int i = blockIdx.x * blockDim.x + threadIdx.x;
    if (i >= n4) return;
    float4 v = ((const float4*)X)[i];
    __half2* H = (__half2*)Xh;
    H[2 * i]     = __halves2half2(__float2half_rn(v.x), __float2half_rn(v.y));
    H[2 * i + 1] = __halves2half2(__float2half_rn(v.z), __float2half_rn(v.w));
}
__global__ void cvt16_perm_ws()
{
    int i = blockIdx.x * blockDim.x + threadIdx.x;
    if (i >= 4 * Dd * Dd / 4) return;
    int flat = i * 4;
    int nrow = flat >> 10;
    int k = flat & 1023;
    int d = nrow >> 2, comp = nrow & 3;
    int orow = (comp < 3) ? comp * Dd + d : 3 * Dd + d;
    float4 v = *(const float4*)&g_wscan[(size_t)orow * Dd + k];
    __half2* H = (__half2*)g_wsf;
    H[2*i]   = __halves2half2(__float2half_rn(v.x), __float2half_rn(v.y));
    H[2*i+1] = __halves2half2(__float2half_rn(v.z), __float2half_rn(v.w));
}

// =============== SIMT GEMM (precompute only) ==================================
#define BKd 8
__global__ void __launch_bounds__(256)
sgemm_ab(const float* __restrict__ A, const float* __restrict__ Bm,
         float* __restrict__ C, int M, int N, int K, int lda, int ldb, int ldc)
{
    __shared__ float As[BKd][128];
    __shared__ float Bs[BKd][128];
    const int tid = threadIdx.x;
    const int tx = tid & 15, ty = tid >> 4;
    const int rowBase = blockIdx.y * 128, colBase = blockIdx.x * 128;
    const int lrA = tid >> 1, lcA = (tid & 1) * 4;
    const int kkB = tid >> 5, c4B = (tid & 31) * 4;
    const float* Aptr = A + (size_t)(rowBase + lrA) * lda + lcA;
    const float* Bptr = Bm + (size_t)kkB * ldb + colBase + c4B;
    float acc[8][8];
#pragma unroll
    for (int i = 0; i < 8; i++)
#pragma unroll
        for (int j = 0; j < 8; j++) acc[i][j] = 0.f;
    for (int k0 = 0; k0 < K; k0 += BKd) {
        float4 av = *(const float4*)(Aptr + k0);
        float4 bv = *(const float4*)(Bptr + (size_t)k0 * ldb);
        As[lcA+0][lrA]=av.x; As[lcA+1][lrA]=av.y;
        As[lcA+2][lrA]=av.z; As[lcA+3][lrA]=av.w;
        *(float4*)&Bs[kkB][c4B] = bv;
        __syncthreads();
#pragma unroll
        for (int kk = 0; kk < BKd; kk++) {
            float a[8], b[8];
#pragma unroll
            for (int i = 0; i < 8; i++) a[i] = As[kk][ty*8+i];
#pragma unroll
            for (int j = 0; j < 8; j++) b[j] = Bs[kk][tx*8+j];
#pragma unroll
            for (int i = 0; i < 8; i++)
#pragma unroll
                for (int j = 0; j < 8; j++)
                    acc[i][j] = fmaf(a[i], b[j], acc[i][j]);
        }
        __syncthreads();
    }
#pragma unroll
    for (int i = 0; i < 8; i++) {
        const int r = rowBase + ty * 8 + i;
#pragma unroll
        for (int j = 0; j < 8; j++)
            C[(size_t)r * ldc + colBase + tx * 8 + j] = acc[i][j];
    }
}

__global__ void copy_jew(const float* __restrict__ je_w)
{
    int idx = blockIdx.x * blockDim.x + threadIdx.x;
    if (idx >= Dd * Dd) return;
    int j = idx >> 10, k = idx & 1023;
    g_wscan[(size_t)(3 * Dd + j) * Dd + k] = je_w[(size_t)j * JEW_LD + k];
}

__global__ void __launch_bounds__(128)
m2c_k(const float* __restrict__ whh, const float* __restrict__ je_w,
      const float* __restrict__ je_b, const float* __restrict__ bhh)
{
    const int i = blockIdx.x;
    const int t = threadIdx.x;
    float acc[9];
#pragma unroll
    for (int j = 0; j < 9; j++) acc[j] = 0.f;
    for (int k = t; k < Dd; k += 128) {
        float w = whh[(size_t)i * Dd + k];
        const float* jr = je_w + (size_t)k * JEW_LD + Dd;
#pragma unroll
        for (int j = 0; j < 8; j++) acc[j] = fmaf(w, jr[j], acc[j]);
        acc[8] = fmaf(w, je_b[k], acc[8]);
    }
    __shared__ float sh[9][128];
#pragma unroll
    for (int j = 0; j < 9; j++) sh[j][t] = acc[j];
    __syncthreads();
    for (int s = 64; s > 0; s >>= 1) {
        if (t < s)
#pragma unroll
            for (int j = 0; j < 9; j++) sh[j][t] += sh[j][t + s];
        __syncthreads();
    }
    if (t == 0) {
#pragma unroll
        for (int j = 0; j < 8; j++) g_M2[i * 8 + j] = sh[j][0];
        g_c[i] = sh[8][0] + bhh[i];
    }
}

// ---------------- batch stats + BN ------------------------------------------
__global__ void col_stats(const float* __restrict__ X, int M, int N,
                          float* __restrict__ mean, float* __restrict__ var)
{
    const int c = blockIdx.x * 32 + threadIdx.x;
    const int ry = threadIdx.y;
    float s = 0.f, s2 = 0.f;
    for (int r = ry; r < M; r += 8) {
        float v = X[(size_t)r * N + c];
        s += v; s2 += v * v;
    }
    __shared__ float sh[8][32], sh2[8][32];
    sh[ry][threadIdx.x] = s; sh2[ry][threadIdx.x] = s2;
    __syncthreads();
    if (ry == 0) {
#pragma unroll
        for (int y = 1; y < 8; y++) { s += sh[y][threadIdx.x]; s2 += sh2[y][threadIdx.x]; }
        float m = s / (float)M;
        mean[c] = m;
        var[c]  = s2 / (float)M - m * m;
    }
}

__global__ void bn_apply(const float* __restrict__ X, float* __restrict__ Y,
                         const float* __restrict__ mean, const float* __restrict__ var,
                         const float* __restrict__ g, const float* __restrict__ beta,
                         int total, int N, int relu)
{
    int idx = blockIdx.x * blockDim.x + threadIdx.x;
    if (idx >= total) return;
    int c = idx % N;
    float v = g[c] * (X[idx] - mean[c]) * rsqrtf(var[c] + EPSf) + beta[c];
    if (relu) v = fmaxf(v, 0.f);
    Y[idx] = v;
}

__global__ void bn_apply_cvt16(const float* __restrict__ X, float* __restrict__ Yf,
                               f16* __restrict__ Yh,
                               const float* __restrict__ mean, const float* __restrict__ var,
                               const float* __restrict__ g, const float* __restrict__ beta,
                               int total4, int N, int relu)
{
    int i = blockIdx.x * blockDim.x + threadIdx.x;
    if (i >= total4) return;
    int c0 = (i * 4) % N;
    float4 v = ((const float4*)X)[i];
    float o[4] = { v.x, v.y, v.z, v.w };
#pragma unroll
    for (int j = 0; j < 4; j++) {
        int c = c0 + j;
        float t = g[c] * (o[j] - mean[c]) * rsqrtf(var[c] + EPSf) + beta[c];
        if (relu) t = fmaxf(t, 0.f);
        o[j] = t;
    }
    if (Yf) ((float4*)Yf)[i] = make_float4(o[0], o[1], o[2], o[3]);
    __half2* H = (__half2*)Yh;
    H[2*i]   = __halves2half2(__float2half_rn(o[0]), __float2half_rn(o[1]));
    H[2*i+1] = __halves2half2(__float2half_rn(o[2]), __float2half_rn(o[3]));
}

// ---------------- misc ------------------------------------------------------
__global__ void zero_h() {
    int idx = blockIdx.x * blockDim.x + threadIdx.x;
    if (idx == 0) g_bar_cnt = 0u;
    if (idx < Bb * Dd) {
        g_h[idx] = 0.f;
        g_hH[idx] = __float2half_rn(0.f);
    }
}

// ---------------- threefry2x32-20 (JAX partitionable) ------------------------
__device__ __forceinline__ uint32_t rotl32_(uint32_t x, int r) {
    return (x << r) | (x >> (32 - r));
}
__device__ __forceinline__ void threefry2x32_(uint32_t k0, uint32_t k1,
                                              uint32_t& x0, uint32_t& x1)
{
    const uint32_t k2 = k0 ^ k1 ^ 0x1BD11BDAu;
    x0 += k0; x1 += k1;
#define TF_R4(a,b,c,d) \
    x0 += x1; x1 = rotl32_(x1, a); x1 ^= x0; \
    x0 += x1; x1 = rotl32_(x1, b); x1 ^= x0; \
    x0 += x1; x1 = rotl32_(x1, c); x1 ^= x0; \
    x0 += x1; x1 = rotl32_(x1, d); x1 ^= x0;
    TF_R4(13,15,26,6)  x0 += k1; x1 += k2 + 1u;
    TF_R4(17,29,16,24) x0 += k2; x1 += k0 + 2u;
    TF_R4(13,15,26,6)  x0 += k0; x1 += k1 + 3u;
    TF_R4(17,29,16,24) x0 += k1; x1 += k2 + 4u;
    TF_R4(13,15,26,6)  x0 += k2; x1 += k0 + 5u;
#undef TF_R4
}

__global__ void gumbel_softmax_k(float* __restrict__ out)
{
    const int bl = blockIdx.x;
    const int d  = threadIdx.x;
    const int i  = bl * ZDn + d;
    const float logit = g_h[i];

    uint32_t c0 = 0u;
    uint32_t c1 = (uint32_t)i;
    threefry2x32_(0u, 42u, c0, c1);
    const uint32_t bits = c0 ^ c1;
    float f = __uint_as_float((bits >> 9) | 0x3f800000u) - 1.0f;
    const float tiny = 1.1754943508222875e-38f;
    float u = fmaxf(f * (1.0f - tiny) + tiny, tiny);
    float gum = -logf(-logf(u));

    float v = logit + gum;

    __shared__ float red[ZDn];
    red[d] = v; __syncthreads();
    for (int s = ZDn / 2; s > 0; s >>= 1) {
        if (d < s) red[d] = fmaxf(red[d], red[d + s]);
        __syncthreads();
    }
    float mx = red[0];
    __syncthreads();
    float e = expf(v - mx);
    red[d] = e; __syncthreads();
    for (int s = ZDn / 2; s > 0; s >>= 1) {
        if (d < s) red[d] += red[d + s];
        __syncthreads();
    }
    float z = e / red[0];

    out[i] = logit;
    out[Bb * ZLn * ZDn + i] = z;
    g_zH[i] = __float2half_rn(z);
}

// ---------------- launch ------------------------------------------------------
static inline float* symf(const void* s) {
    void* p = nullptr;
    cudaGetSymbolAddress(&p, s);
    return (float*)p;
}
static inline f16* symh(const void* s) {
    void* p = nullptr;
    cudaGetSymbolAddress(&p, s);
    return (f16*)p;
}

extern "C" void kernel_launch(void* const* d_in, const int* in_sizes, int n_in,
                              void* d_out, int out_size)
{
    (void)in_sizes; (void)n_in; (void)out_size;
    const float* obs      = (const float*)d_in[0];
    const float* actions  = (const float*)d_in[1];
    const float* enc_w1   = (const float*)d_in[2];
    const float* enc_b1   = (const float*)d_in[3];
    const float* enc_g1   = (const float*)d_in[4];
    const float* enc_bt1  = (const float*)d_in[5];
    const float* enc_w2   = (const float*)d_in[6];
    const float* enc_b2   = (const float*)d_in[7];
    const float* enc_g2   = (const float*)d_in[8];
    const float* enc_bt2  = (const float*)d_in[9];
    const float* je_w     = (const float*)d_in[10];
    const float* je_b     = (const float*)d_in[11];
    const float* gru_wih  = (const float*)d_in[12];
    const float* gru_bih  = (const float*)d_in[13];
    const float* gru_whh  = (const float*)d_in[14];
    const float* gru_bhh  = (const float*)d_in[15];
    const float* dec_w1   = (const float*)d_in[16];
    const float* dec_b1   = (const float*)d_in[17];
    const float* dec_g1   = (const float*)d_in[18];
    const float* dec_bt1  = (const float*)d_in[19];
    const float* dec_w2   = (const float*)d_in[20];
    const float* dec_b2   = (const float*)d_in[21];
    const float* dec_g2   = (const float*)d_in[22];
    const float* dec_bt2  = (const float*)d_in[23];
    float* out = (float*)d_out;

    float* p_h1 = symf(g_h1);
    float* p_x  = symf(g_x);
    float* p_gi = symf(g_gi);
    float* p_d1 = symf(g_d1);
    float* p_d2 = symf(g_d2);
    float* p_m  = symf(g_mean);
    float* p_v  = symf(g_var);
    float* p_ws = symf(g_wscan);

    f16 *p_obsH = symh(g_obsH);
    f16 *p_w1 = symh(g_w1);
    f16 *p_h1H = symh(g_h1H);
    f16 *p_w2 = symh(g_w2);
    f16 *p_xH = symh(g_xH);
    f16 *p_wih = symh(g_wih);
    f16 *p_zH = symh(g_zH);
    f16 *p_d1H = symh(g_d1H);
    f16 *p_dw1 = symh(g_dw1);
    f16 *p_dw2 = symh(g_dw2);

    static cudaStream_t sSide = nullptr;
    static cudaEvent_t evFork = nullptr, evJoin = nullptr;
    static bool attrDone = false;
    if (!attrDone) {
        cudaFuncSetAttribute(mma_gemm16, cudaFuncAttributeMaxDynamicSharedMemorySize, SM16_BYTES);
        cudaFuncSetAttribute(mma_scan_persist, cudaFuncAttributeMaxDynamicSharedMemorySize, SSM_BYTES);
        cudaStreamCreateWithFlags(&sSide, cudaStreamNonBlocking);
        cudaEventCreateWithFlags(&evFork, cudaEventDisableTiming);
        cudaEventCreateWithFlags(&evJoin, cudaEventDisableTiming);
        attrDone = true;
    }

    dim3 blk(256);
    dim3 statsBlk(32, 8);

    // ================== FORK: side stream does setup work =====================
    cudaEventRecord(evFork, 0);
    cudaStreamWaitEvent(sSide, evFork, 0);

    cvt16_w<<<(Dd * Hh / 4 + 255) / 256, blk, 0, sSide>>>(enc_w2, p_w2, Dd * Hh / 4);
    cvt16_w<<<(3 * Dd * Dd / 4 + 255) / 256, blk, 0, sSide>>>(gru_wih, p_wih, 3 * Dd * Dd / 4);
    cvt16_w<<<(Hh * Dd / 4 + 255) / 256, blk, 0, sSide>>>(dec_w1, p_dw1, Hh * Dd / 4);
    cvt16_w<<<(OBSn * Hh / 4 + 255) / 256, blk, 0, sSide>>>(dec_w2, p_dw2, OBSn * Hh / 4);
    {
        dim3 grid(Dd / 128, 3 * Dd / 128);
        sgemm_ab<<<grid, blk, 0, sSide>>>(gru_whh, je_w, p_ws, 3 * Dd, Dd, Dd, Dd, JEW_LD, Dd);
        copy_jew<<<(Dd * Dd + 255) / 256, blk, 0, sSide>>>(je_w);
        m2c_k<<<3 * Dd, 128, 0, sSide>>>(gru_whh, je_w, je_b, gru_bhh);
        cvt16_perm_ws<<<(4 * Dd * Dd / 4 + 255) / 256, blk, 0, sSide>>>();
    }
    zero_h<<<(Bb * Dd + 255) / 256, blk, 0, sSide>>>();
    cudaEventRecord(evJoin, sSide);

    // main chain: obs/w1 cvt -> enc1
    cvt16_w<<<(BT * OBSn / 4 + 255) / 256, blk>>>(obs, p_obsH, BT * OBSn / 4);
    cvt16_w<<<(Hh * OBSn / 4 + 255) / 256, blk>>>(enc_w1, p_w1, Hh * OBSn / 4);

    // ---- encoder layer 1 (fp16) ----
    {
        dim3 grid(Hh / 128, BT / 128);
        mma_gemm16<<<grid, blk, SM16_BYTES>>>(p_obsH, p_w1, enc_b1, p_h1, BT, Hh, OBSn);
        col_stats<<<Hh / 32, statsBlk>>>(p_h1, BT, Hh, p_m, p_v);
        bn_apply_cvt16<<<(BT * Hh / 4 + 255) / 256, blk>>>(p_h1, nullptr, p_h1H,
                                                           p_m, p_v, enc_g1, enc_bt1,
                                                           BT * Hh / 4, Hh, 1);
    }

    // ================== JOIN ==================================================
    cudaStreamWaitEvent(0, evJoin, 0);

    // ---- encoder layer 2 (fp16) ----
    {
        dim3 grid(Dd / 128, BT / 128);
        mma_gemm16<<<grid, blk, SM16_BYTES>>>(p_h1H, p_w2, enc_b2, p_x, BT, Dd, Hh);
        col_stats<<<Dd / 32, statsBlk>>>(p_x, BT, Dd, p_m, p_v);
        bn_apply_cvt16<<<(BT * Dd / 4 + 255) / 256, blk>>>(p_x, p_x, p_xH,
                                                           p_m, p_v, enc_g2, enc_bt2,
                                                           BT * Dd / 4, Dd, 0);
    }
    // ---- gi (fp16) ----
    {
        dim3 grid(3 * Dd / 128, BT / 128);
        mma_gemm16<<<grid, blk, SM16_BYTES>>>(p_xH, p_wih, gru_bih, p_gi, BT, 3 * Dd, Dd);
    }
    // ---- recurrent scan: ONE persistent kernel (fp16 single-digit) ----
    {
        dim3 gridS(4 * Dd / 64, Bb / 128);   // (64, 2) = 128 CTAs, all resident
        mma_scan_persist<<<gridS, blk, SSM_BYTES>>>(actions, je_w, je_b);
    }
    // ---- gumbel softmax ----
    gumbel_softmax_k<<<Bb * ZLn, ZDn>>>(out);
    // ---- decoder layer 1 (fp16) ----
    {
        dim3 grid(Hh / 128, Bb / 128);
        mma_gemm16<<<grid, blk, SM16_BYTES>>>(p_zH, p_dw1, dec_b1, p_d1, Bb, Hh, Dd);
        col_stats<<<Hh / 32, statsBlk>>>(p_d1, Bb, Hh, p_m, p_v);
        bn_apply_cvt16<<<(Bb * Hh / 4 + 255) / 256, blk>>>(p_d1, nullptr, p_d1H,
                                                           p_m, p_v, dec_g1, dec_bt1,
                                                           Bb * Hh / 4, Hh, 1);
    }
    // ---- decoder layer 2 (fp16) -> x_hat ----
    {
        dim3 grid(OBSn / 128, Bb / 128);
        mma_gemm16<<<grid, blk, SM16_BYTES>>>(p_d1H, p_dw2, dec_b2, p_d2, Bb, OBSn, Hh);
        col_stats<<<OBSn / 32, statsBlk>>>(p_d2, Bb, OBSn, p_m, p_v);
        int total = Bb * OBSn;
        bn_apply<<<(total + 255) / 256, blk>>>(p_d2, out + 2 * Bb * ZLn * ZDn,
                                               p_m, p_v, dec_g2, dec_bt2, total, OBSn, 0);
    }
}